// round 1
// baseline (speedup 1.0000x reference)
#include <cuda_runtime.h>
#include <cuda_bf16.h>

// Problem constants
#define Bv     4
#define Nv     2048
#define INF_   256
#define OUTF_  256
#define Hh     8
#define NHv    32
#define SLOPE  0.2f
#define NEGINF (-9e15f)

// Scratch (device globals — no allocation allowed)
__device__ float g_Wh [Bv * Nv * OUTF_];   // 8 MB: Wh = h @ W, flat [B, N, 256] == raw [B,H,N,32]
__device__ float g_Wh1[Bv * Hh * Nv];      // [B,H,N]
__device__ float g_Wh2[Bv * Hh * Nv];      // [B,H,N]

__device__ __forceinline__ float warpMax(float v) {
#pragma unroll
    for (int o = 16; o > 0; o >>= 1) v = fmaxf(v, __shfl_xor_sync(0xFFFFFFFFu, v, o));
    return v;
}
__device__ __forceinline__ float warpSum(float v) {
#pragma unroll
    for (int o = 16; o > 0; o >>= 1) v += __shfl_xor_sync(0xFFFFFFFFu, v, o);
    return v;
}

// ---------------------------------------------------------------------------
// Kernel 1: Wh = h @ W.   A: [8192, 256], W: [256, 256], C: [8192, 256]
// 64x64 block tile, 4x4 per-thread micro tile, BK=16.
// ---------------------------------------------------------------------------
#define BM 64
#define BN 64
#define BK 16
__global__ __launch_bounds__(256) void gemm_kernel(const float* __restrict__ A,
                                                   const float* __restrict__ Wm) {
    __shared__ float sA[BK][BM + 1];
    __shared__ float sB[BK][BN];

    const int tid = threadIdx.x;
    const int tx  = tid & 15;          // 0..15  -> col group
    const int ty  = tid >> 4;          // 0..15  -> row group
    const int mBase = blockIdx.x * BM;
    const int nBase = blockIdx.y * BN;

    float acc[4][4];
#pragma unroll
    for (int i = 0; i < 4; i++)
#pragma unroll
        for (int j = 0; j < 4; j++) acc[i][j] = 0.f;

    for (int k0 = 0; k0 < INF_; k0 += BK) {
        // Load A tile 64x16 (k fastest in global)
#pragma unroll
        for (int r = 0; r < 4; r++) {
            int idx = tid + r * 256;
            int m = idx >> 4, kk = idx & 15;
            sA[kk][m] = A[(size_t)(mBase + m) * INF_ + k0 + kk];
        }
        // Load B tile 16x64 (n fastest)
#pragma unroll
        for (int r = 0; r < 4; r++) {
            int idx = tid + r * 256;
            int kk = idx >> 6, n = idx & 63;
            sB[kk][n] = Wm[(size_t)(k0 + kk) * OUTF_ + nBase + n];
        }
        __syncthreads();

#pragma unroll
        for (int kk = 0; kk < BK; kk++) {
            float af[4], bf[4];
#pragma unroll
            for (int i = 0; i < 4; i++) af[i] = sA[kk][ty * 4 + i];
#pragma unroll
            for (int j = 0; j < 4; j++) bf[j] = sB[kk][tx * 4 + j];
#pragma unroll
            for (int i = 0; i < 4; i++)
#pragma unroll
                for (int j = 0; j < 4; j++) acc[i][j] = fmaf(af[i], bf[j], acc[i][j]);
        }
        __syncthreads();
    }

#pragma unroll
    for (int i = 0; i < 4; i++) {
        float4 v = make_float4(acc[i][0], acc[i][1], acc[i][2], acc[i][3]);
        size_t off = (size_t)(mBase + ty * 4 + i) * OUTF_ + nBase + tx * 4;
        *reinterpret_cast<float4*>(&g_Wh[off]) = v;
    }
}

// ---------------------------------------------------------------------------
// Kernel 2: Wh1[bhn] = dot(Whr[bhn,:], a[0:32]); Wh2 = dot(., a[32:64])
// One warp per (b,h,n). Flat index gw == (b*H+h)*N + n; Whr row = g_Wh[gw*32 + d].
// ---------------------------------------------------------------------------
__global__ __launch_bounds__(256) void wh12_kernel(const float* __restrict__ a) {
    int gw   = blockIdx.x * 8 + (threadIdx.x >> 5);
    int lane = threadIdx.x & 31;
    float v  = g_Wh[(size_t)gw * 32 + lane];
    float s1 = warpSum(v * a[lane]);
    float s2 = warpSum(v * a[32 + lane]);
    if (lane == 0) { g_Wh1[gw] = s1; g_Wh2[gw] = s2; }
}

// ---------------------------------------------------------------------------
// Kernel 3: fused online-softmax attention + PV + ELU.
// grid = (N/64, H, B); block = 256 threads (8 warps).
// Warp w owns 8 i-rows; lane = output feature d (0..31).
// ---------------------------------------------------------------------------
#define TI 64
#define TJ 64
__global__ __launch_bounds__(256) void attn_kernel(const int* __restrict__ adj,
                                                   float* __restrict__ out) {
    __shared__ float sV[TJ][NHv];        // 8 KB   value tile (contiguous chunk of g_Wh)
    __shared__ float sP[TI][TJ];         // 16 KB  probability tile
    __shared__ float sWh2[TJ];

    const int tid  = threadIdx.x;
    const int w    = tid >> 5;
    const int lane = tid & 31;
    const int iT   = blockIdx.x;         // i tile
    const int h    = blockIdx.y;
    const int b    = blockIdx.z;
    const int bh   = b * Hh + h;
    const int iBase = iT * TI;
    const int w8    = w * 8;

    const size_t whBase  = (size_t)bh * Nv * NHv;   // base of Whr[b,h,:,:] in g_Wh
    const size_t adjBase = (size_t)b * Nv * Nv;

    float wh1r[8];
#pragma unroll
    for (int ii = 0; ii < 8; ii++)
        wh1r[ii] = g_Wh1[bh * Nv + iBase + w8 + ii];

    float m[8], l[8], acc[8];
#pragma unroll
    for (int ii = 0; ii < 8; ii++) { m[ii] = -INFINITY; l[ii] = 0.f; acc[ii] = 0.f; }

    for (int jt = 0; jt < Nv / TJ; jt++) {
        __syncthreads();
        // V tile: 2048 contiguous floats of g_Wh -> 512 float4, 2 per thread
        {
            const float4* src = reinterpret_cast<const float4*>(&g_Wh[whBase + (size_t)jt * TJ * NHv]);
            float4* dst = reinterpret_cast<float4*>(&sV[0][0]);
            dst[tid]        = src[tid];
            dst[tid + 256]  = src[tid + 256];
        }
        if (tid < TJ) sWh2[tid] = g_Wh2[bh * Nv + jt * TJ + tid];
        __syncthreads();

        // ---- score phase: online softmax stats + P tile ----
        const int j0 = jt * TJ + lane;
#pragma unroll
        for (int ii = 0; ii < 8; ii++) {
            const int i = iBase + w8 + ii;
            const size_t arow = adjBase + (size_t)i * Nv;

            float s0 = wh1r[ii] + sWh2[lane];
            float s1 = wh1r[ii] + sWh2[lane + 32];
            s0 = (s0 >= 0.f) ? s0 : SLOPE * s0;
            s1 = (s1 >= 0.f) ? s1 : SLOPE * s1;
            if (adj[arow + j0]      <= 0) s0 = NEGINF;
            if (adj[arow + j0 + 32] <= 0) s1 = NEGINF;

            float mt   = warpMax(fmaxf(s0, s1));
            float mnew = fmaxf(m[ii], mt);
            float alpha = __expf(m[ii] - mnew);   // exp(-inf)=0 on first tile
            float p0 = __expf(s0 - mnew);
            float p1 = __expf(s1 - mnew);
            float rs = warpSum(p0 + p1);

            l[ii]   = l[ii] * alpha + rs;
            acc[ii] = acc[ii] * alpha;
            m[ii]   = mnew;
            sP[w8 + ii][lane]      = p0;
            sP[w8 + ii][lane + 32] = p1;
        }
        __syncwarp();   // sP rows are warp-private

        // ---- PV phase: acc[ii] += sum_j P[ii][j] * V[j][lane] ----
#pragma unroll
        for (int j4 = 0; j4 < TJ / 4; j4++) {
            const int jb = j4 * 4;
            float v0 = sV[jb + 0][lane];
            float v1 = sV[jb + 1][lane];
            float v2 = sV[jb + 2][lane];
            float v3 = sV[jb + 3][lane];
#pragma unroll
            for (int ii = 0; ii < 8; ii++) {
                float4 p = *reinterpret_cast<const float4*>(&sP[w8 + ii][jb]);
                acc[ii] = fmaf(p.x, v0,
                          fmaf(p.y, v1,
                          fmaf(p.z, v2,
                          fmaf(p.w, v3, acc[ii]))));
            }
        }
    }

    // ---- epilogue: normalize + ELU, raw-reshape write ----
#pragma unroll
    for (int ii = 0; ii < 8; ii++) {
        const int i = iBase + w8 + ii;
        float o = acc[ii] / l[ii];
        o = (o > 0.f) ? o : expm1f(o);
        out[((size_t)bh * Nv + i) * NHv + lane] = o;
    }
}

// ---------------------------------------------------------------------------
extern "C" void kernel_launch(void* const* d_in, const int* in_sizes, int n_in,
                              void* d_out, int out_size) {
    const float* h   = (const float*)d_in[0];   // [4,2048,256]
    const int*   adj = (const int*)  d_in[1];   // [4,2048,2048]
    const float* W   = (const float*)d_in[2];   // [256,256]
    const float* a   = (const float*)d_in[3];   // [64,1]
    float* out = (float*)d_out;                 // [4,2048,256]

    gemm_kernel<<<dim3((Bv * Nv) / BM, OUTF_ / BN), 256>>>(h, W);
    wh12_kernel<<<(Bv * Hh * Nv) / 8, 256>>>(a);
    attn_kernel<<<dim3(Nv / TI, Hh, Bv), 256>>>(adj, out);
}

// round 3
// speedup vs baseline: 2.8464x; 2.8464x over previous
#include <cuda_runtime.h>
#include <cuda_fp16.h>
#include <cstdint>

// Problem constants
#define Bv     4
#define Nv     2048
#define INF_   256
#define OUTF_  256
#define Hh     8
#define NHv    32
#define SLOPE  0.2f
#define LOG2E  1.4426950408889634f

// ---------------------------------------------------------------------------
// Device scratch (no allocations allowed)
// ---------------------------------------------------------------------------
__device__ float    g_Wh   [Bv * Nv * OUTF_];          // 8 MB  Wh (flat == raw view [B,H,N,32])
__device__ float    g_wh1s [Bv * Hh * Nv];             // wh1 * log2e
__device__ float    g_wh2s [Bv * Hh * Nv];             // wh2 * log2e
__device__ float    g_m    [Bv * Hh * Nv];             // exact row max (log2 domain, lrelu'd)
__device__ unsigned g_adjbits[Bv * Nv * (Nv / 32)];    // 2 MB  adj bitmask
__device__ __align__(16) __half g_Vh16[32 * 16 * 4096]; // 4 MB  V tiles f16, [bh][jt][d 32][j 128]

// ---------------------------------------------------------------------------
// helpers
// ---------------------------------------------------------------------------
__device__ __forceinline__ float ex2f(float x) {
    float y; asm("ex2.approx.ftz.f32 %0, %1;" : "=f"(y) : "f"(x)); return y;
}
__device__ __forceinline__ float warpMax(float v) {
#pragma unroll
    for (int o = 16; o > 0; o >>= 1) v = fmaxf(v, __shfl_xor_sync(0xFFFFFFFFu, v, o));
    return v;
}
__device__ __forceinline__ float warpSum(float v) {
#pragma unroll
    for (int o = 16; o > 0; o >>= 1) v += __shfl_xor_sync(0xFFFFFFFFu, v, o);
    return v;
}
__device__ __forceinline__ void mma16816(float* d, uint32_t a0, uint32_t a1, uint32_t a2,
                                         uint32_t a3, uint32_t b0, uint32_t b1) {
    asm volatile(
        "mma.sync.aligned.m16n8k16.row.col.f32.f16.f16.f32 "
        "{%0,%1,%2,%3}, {%4,%5,%6,%7}, {%8,%9}, {%0,%1,%2,%3};"
        : "+f"(d[0]), "+f"(d[1]), "+f"(d[2]), "+f"(d[3])
        : "r"(a0), "r"(a1), "r"(a2), "r"(a3), "r"(b0), "r"(b1));
}
__device__ __forceinline__ uint32_t packh2(float a, float b) {
    __half2 h = __floats2half2_rn(a, b);
    return *reinterpret_cast<uint32_t*>(&h);
}
__device__ __forceinline__ float pcalc(float c, float m, float w2, unsigned bit) {
    float e = c + w2;
    e = fmaxf(e, SLOPE * e);
    float p = ex2f(e - m);
    return bit ? p : 0.f;
}

// ---------------------------------------------------------------------------
// K1: Wh = h @ W  (fp32, 128x128 tile, 8x8 micro, BK=16)
// ---------------------------------------------------------------------------
#define GM 128
#define GN 128
#define GK 16
__global__ __launch_bounds__(256) void gemm_kernel(const float* __restrict__ A,
                                                   const float* __restrict__ Wm) {
    __shared__ float sA[GK][GM + 4];
    __shared__ float sB[GK][GN];
    const int tid = threadIdx.x;
    const int tx = tid & 15, ty = tid >> 4;
    const int mBase = blockIdx.x * GM, nBase = blockIdx.y * GN;

    float acc[8][8];
#pragma unroll
    for (int i = 0; i < 8; i++)
#pragma unroll
        for (int j = 0; j < 8; j++) acc[i][j] = 0.f;

    for (int k0 = 0; k0 < INF_; k0 += GK) {
#pragma unroll
        for (int r = 0; r < 2; r++) {
            int s = tid + r * 256;
            int m = s >> 2, k4 = (s & 3) * 4;
            float4 v = *reinterpret_cast<const float4*>(&A[(size_t)(mBase + m) * INF_ + k0 + k4]);
            sA[k4 + 0][m] = v.x; sA[k4 + 1][m] = v.y;
            sA[k4 + 2][m] = v.z; sA[k4 + 3][m] = v.w;
        }
#pragma unroll
        for (int r = 0; r < 2; r++) {
            int s = tid + r * 256;
            int kk = s >> 5, n4 = (s & 31) * 4;
            *reinterpret_cast<float4*>(&sB[kk][n4]) =
                *reinterpret_cast<const float4*>(&Wm[(size_t)(k0 + kk) * OUTF_ + nBase + n4]);
        }
        __syncthreads();
#pragma unroll
        for (int kk = 0; kk < GK; kk++) {
            float af[8], bf[8];
            *reinterpret_cast<float4*>(&af[0]) = *reinterpret_cast<const float4*>(&sA[kk][ty * 8]);
            *reinterpret_cast<float4*>(&af[4]) = *reinterpret_cast<const float4*>(&sA[kk][ty * 8 + 4]);
            *reinterpret_cast<float4*>(&bf[0]) = *reinterpret_cast<const float4*>(&sB[kk][tx * 8]);
            *reinterpret_cast<float4*>(&bf[4]) = *reinterpret_cast<const float4*>(&sB[kk][tx * 8 + 4]);
#pragma unroll
            for (int i = 0; i < 8; i++)
#pragma unroll
                for (int j = 0; j < 8; j++) acc[i][j] = fmaf(af[i], bf[j], acc[i][j]);
        }
        __syncthreads();
    }
#pragma unroll
    for (int i = 0; i < 8; i++) {
        size_t row = (size_t)(mBase + ty * 8 + i) * OUTF_ + nBase + tx * 8;
        *reinterpret_cast<float4*>(&g_Wh[row])     = make_float4(acc[i][0], acc[i][1], acc[i][2], acc[i][3]);
        *reinterpret_cast<float4*>(&g_Wh[row + 4]) = make_float4(acc[i][4], acc[i][5], acc[i][6], acc[i][7]);
    }
}

// ---------------------------------------------------------------------------
// K2: wh1/wh2 per (b,h,n), pre-scaled by log2(e). One warp per row.
// ---------------------------------------------------------------------------
__global__ __launch_bounds__(256) void wh12_kernel(const float* __restrict__ a) {
    int gw = blockIdx.x * 8 + (threadIdx.x >> 5);
    int lane = threadIdx.x & 31;
    float v = g_Wh[(size_t)gw * 32 + lane];
    float s1 = warpSum(v * a[lane]);
    float s2 = warpSum(v * a[32 + lane]);
    if (lane == 0) { g_wh1s[gw] = s1 * LOG2E; g_wh2s[gw] = s2 * LOG2E; }
}

// ---------------------------------------------------------------------------
// K3a: compress adj to bitmask via ballot
// ---------------------------------------------------------------------------
__global__ __launch_bounds__(256) void adjbits_kernel(const int* __restrict__ adj) {
    unsigned idx = blockIdx.x * 256u + threadIdx.x;
    unsigned mask = __ballot_sync(0xFFFFFFFFu, adj[idx] > 0);
    if ((threadIdx.x & 31) == 0) g_adjbits[idx >> 5] = mask;
}

// ---------------------------------------------------------------------------
// K2b: V tiles -> f16, transposed to [d 32][j 128] per (bh, jt). grid (16, 32)
// ---------------------------------------------------------------------------
__global__ __launch_bounds__(256) void vconv_kernel() {
    __shared__ float sVf[128 * 33];
    const int jt = blockIdx.x, bh = blockIdx.y, tid = threadIdx.x;
    const float* src = &g_Wh[(size_t)bh * 65536 + (size_t)jt * 4096];
#pragma unroll
    for (int k = 0; k < 16; k++) {
        int idx = tid + k * 256;
        sVf[(idx >> 5) * 33 + (idx & 31)] = src[idx];
    }
    __syncthreads();
    __half2* dst = reinterpret_cast<__half2*>(g_Vh16 + ((size_t)bh * 16 + jt) * 4096);
#pragma unroll
    for (int it = 0; it < 8; it++) {
        int q = tid + it * 256;        // half2 slot; layout [d][j] => linear
        int d = q >> 6, jp = (q & 63) * 2;
        dst[q] = __floats2half2_rn(sVf[jp * 33 + d], sVf[(jp + 1) * 33 + d]);
    }
}

// ---------------------------------------------------------------------------
// K3b: exact row max m[bhn] = lrelu(wh1 + max_{j in adj} wh2_j). One warp/row.
// ---------------------------------------------------------------------------
__global__ __launch_bounds__(256) void rowmax_kernel() {
    int gw = blockIdx.x * 8 + (threadIdx.x >> 5);
    int lane = threadIdx.x & 31;
    int bh = gw >> 11, i = gw & 2047, b = bh >> 3;
    const unsigned* bits = g_adjbits + (size_t)(b * 2048 + i) * 64;
    const float4* w2v = reinterpret_cast<const float4*>(g_wh2s + (size_t)bh * 2048);

    float mx = -INFINITY;
#pragma unroll
    for (int s = 0; s < 16; s++) {
        float4 w2 = w2v[s * 32 + lane];
        unsigned w = bits[s * 4 + (lane >> 3)];
        unsigned sh = (lane & 7) * 4;
        if ((w >> (sh + 0)) & 1u) mx = fmaxf(mx, w2.x);
        if ((w >> (sh + 1)) & 1u) mx = fmaxf(mx, w2.y);
        if ((w >> (sh + 2)) & 1u) mx = fmaxf(mx, w2.z);
        if ((w >> (sh + 3)) & 1u) mx = fmaxf(mx, w2.w);
    }
    mx = warpMax(mx);
    if (lane == 0) {
        float e = g_wh1s[gw] + mx;
        g_m[gw] = fmaxf(e, SLOPE * e);
    }
}

// ---------------------------------------------------------------------------
// K4: fused scores + HMMA PV + ELU. grid (16 itiles, 8 h, 4 b), 256 threads.
// Warp w owns 16 i-rows. P computed directly in mma A-fragment registers.
// ---------------------------------------------------------------------------
__global__ __launch_bounds__(256) void attn_kernel(float* __restrict__ out) {
    __shared__ float2 sRow[128];                 // (wh1*log2e, m) per i-row
    __shared__ float  sW2[128];
    __shared__ uint4  sBits[128];
    __shared__ __align__(16) uint32_t sVt[32 * 68];  // V^T f16 [d][j], row stride 68 u32 (pad)

    const int tid  = threadIdx.x;
    const int w    = tid >> 5, lane = tid & 31;
    const int tig  = lane & 3, grp = lane >> 2;
    const int iT = blockIdx.x, hh = blockIdx.y, b = blockIdx.z;
    const int bh = b * Hh + hh;
    const int iBase = iT * 128;
    const int il0 = w * 16 + grp, il1 = il0 + 8;

    if (tid < 128) {
        int gi = bh * Nv + iBase + tid;
        sRow[tid] = make_float2(g_wh1s[gi], g_m[gi]);
    }
    __syncthreads();
    const float2 cm0 = sRow[il0];
    const float2 cm1 = sRow[il1];

    float dacc[4][4];
#pragma unroll
    for (int nb = 0; nb < 4; nb++)
#pragma unroll
        for (int q = 0; q < 4; q++) dacc[nb][q] = 0.f;
    float lsum0 = 0.f, lsum1 = 0.f;

    const unsigned* bitsBase = g_adjbits + (size_t)(b * 2048 + iBase) * 64;
    const float* wh2Base = g_wh2s + (size_t)bh * 2048;
    const uint4* vBase = reinterpret_cast<const uint4*>(g_Vh16 + (size_t)bh * 16 * 4096);

    for (int jt = 0; jt < 16; jt++) {
        __syncthreads();
        {   // V tile: 512 uint4 -> padded smem rows (17 uint4 per d-row)
            uint4* dst = reinterpret_cast<uint4*>(sVt);
            int q0 = tid, q1 = tid + 256;
            dst[(q0 >> 4) * 17 + (q0 & 15)] = vBase[jt * 512 + q0];
            dst[(q1 >> 4) * 17 + (q1 & 15)] = vBase[jt * 512 + q1];
        }
        if (tid < 128) {
            sW2[tid] = wh2Base[jt * 128 + tid];
            sBits[tid] = *reinterpret_cast<const uint4*>(bitsBase + (size_t)tid * 64 + jt * 4);
        }
        __syncthreads();

        const uint4 bw0 = sBits[il0];
        const uint4 bw1 = sBits[il1];
        const unsigned* bw0w = reinterpret_cast<const unsigned*>(&bw0);
        const unsigned* bw1w = reinterpret_cast<const unsigned*>(&bw1);

#pragma unroll
        for (int ks = 0; ks < 8; ks++) {
            const int jb = ks * 16 + tig * 2;
            const float2 w2a = *reinterpret_cast<const float2*>(&sW2[jb]);
            const float2 w2b = *reinterpret_cast<const float2*>(&sW2[jb + 8]);
            const unsigned wd0 = bw0w[ks >> 1];
            const unsigned wd1 = bw1w[ks >> 1];
            const int sh = (ks & 1) * 16 + tig * 2;

            float p00 = pcalc(cm0.x, cm0.y, w2a.x, (wd0 >> sh) & 1u);
            float p01 = pcalc(cm0.x, cm0.y, w2a.y, (wd0 >> (sh + 1)) & 1u);
            float p02 = pcalc(cm0.x, cm0.y, w2b.x, (wd0 >> (sh + 8)) & 1u);
            float p03 = pcalc(cm0.x, cm0.y, w2b.y, (wd0 >> (sh + 9)) & 1u);
            float p10 = pcalc(cm1.x, cm1.y, w2a.x, (wd1 >> sh) & 1u);
            float p11 = pcalc(cm1.x, cm1.y, w2a.y, (wd1 >> (sh + 1)) & 1u);
            float p12 = pcalc(cm1.x, cm1.y, w2b.x, (wd1 >> (sh + 8)) & 1u);
            float p13 = pcalc(cm1.x, cm1.y, w2b.y, (wd1 >> (sh + 9)) & 1u);

            lsum0 += (p00 + p01) + (p02 + p03);
            lsum1 += (p10 + p11) + (p12 + p13);

            uint32_t A0 = packh2(p00, p01);
            uint32_t A1 = packh2(p10, p11);
            uint32_t A2 = packh2(p02, p03);
            uint32_t A3 = packh2(p12, p13);

            const uint32_t* vcol = sVt + (jb >> 1);
#pragma unroll
            for (int nb = 0; nb < 4; nb++) {
                int drow = nb * 8 + grp;
                uint32_t B0 = vcol[drow * 68];
                uint32_t B1 = vcol[drow * 68 + 4];
                mma16816(dacc[nb], A0, A1, A2, A3, B0, B1);
            }
        }
    }

    // reduce l over the 4 lanes sharing each row
    lsum0 += __shfl_xor_sync(0xFFFFFFFFu, lsum0, 1);
    lsum0 += __shfl_xor_sync(0xFFFFFFFFu, lsum0, 2);
    lsum1 += __shfl_xor_sync(0xFFFFFFFFu, lsum1, 1);
    lsum1 += __shfl_xor_sync(0xFFFFFFFFu, lsum1, 2);
    const float rl0 = 1.f / lsum0, rl1 = 1.f / lsum1;

    const size_t o0 = ((size_t)bh * Nv + iBase + il0) * NHv + tig * 2;
    const size_t o1 = ((size_t)bh * Nv + iBase + il1) * NHv + tig * 2;
#pragma unroll
    for (int nb = 0; nb < 4; nb++) {
        float x0 = dacc[nb][0] * rl0, x1 = dacc[nb][1] * rl0;
        float y0 = dacc[nb][2] * rl1, y1 = dacc[nb][3] * rl1;
        x0 = (x0 > 0.f) ? x0 : expm1f(x0);
        x1 = (x1 > 0.f) ? x1 : expm1f(x1);
        y0 = (y0 > 0.f) ? y0 : expm1f(y0);
        y1 = (y1 > 0.f) ? y1 : expm1f(y1);
        *reinterpret_cast<float2*>(&out[o0 + nb * 8]) = make_float2(x0, x1);
        *reinterpret_cast<float2*>(&out[o1 + nb * 8]) = make_float2(y0, y1);
    }
}

// ---------------------------------------------------------------------------
extern "C" void kernel_launch(void* const* d_in, const int* in_sizes, int n_in,
                              void* d_out, int out_size) {
    const float* h   = (const float*)d_in[0];   // [4,2048,256]
    const int*   adj = (const int*)  d_in[1];   // [4,2048,2048]
    const float* W   = (const float*)d_in[2];   // [256,256]
    const float* a   = (const float*)d_in[3];   // [64,1]
    float* out = (float*)d_out;                 // [4,2048,256]

    gemm_kernel<<<dim3(64, 2), 256>>>(h, W);
    adjbits_kernel<<<65536, 256>>>(adj);
    wh12_kernel<<<8192, 256>>>(a);
    vconv_kernel<<<dim3(16, 32), 256>>>();
    rowmax_kernel<<<8192, 256>>>();
    attn_kernel<<<dim3(16, 8, 4), 256>>>(out);
}

// round 4
// speedup vs baseline: 3.6339x; 1.2767x over previous
#include <cuda_runtime.h>
#include <cuda_fp16.h>
#include <cstdint>

// Problem constants
#define Bv     4
#define Nv     2048
#define INF_   256
#define OUTF_  256
#define Hh     8
#define NHv    32
#define SLOPE  0.2f
#define LOG2E  1.4426950408889634f

// ---------------------------------------------------------------------------
// Device scratch (no allocations allowed)
// ---------------------------------------------------------------------------
__device__ float    g_Wh   [Bv * Nv * OUTF_];          // 8 MB  Wh (flat == raw view [B,H,N,32])
__device__ float    g_wh1s [Bv * Hh * Nv];             // wh1 * log2e
__device__ float    g_wh2s [Bv * Hh * Nv];             // wh2 * log2e
__device__ float    g_w2max[Bv * Hh];                  // per-(b,h) max of g_wh2s
__device__ unsigned g_adjbits[Bv * Nv * (Nv / 32)];    // 2 MB  adj bitmask
__device__ __align__(16) __half g_Vh16[32 * 16 * 4096]; // 4 MB  V tiles f16, [bh][jt][d 32][j 128]

// ---------------------------------------------------------------------------
// helpers
// ---------------------------------------------------------------------------
__device__ __forceinline__ float ex2f(float x) {
    float y; asm("ex2.approx.ftz.f32 %0, %1;" : "=f"(y) : "f"(x)); return y;
}
__device__ __forceinline__ float warpMax(float v) {
#pragma unroll
    for (int o = 16; o > 0; o >>= 1) v = fmaxf(v, __shfl_xor_sync(0xFFFFFFFFu, v, o));
    return v;
}
__device__ __forceinline__ float warpSum(float v) {
#pragma unroll
    for (int o = 16; o > 0; o >>= 1) v += __shfl_xor_sync(0xFFFFFFFFu, v, o);
    return v;
}
__device__ __forceinline__ void mma16816(float* d, uint32_t a0, uint32_t a1, uint32_t a2,
                                         uint32_t a3, uint32_t b0, uint32_t b1) {
    asm volatile(
        "mma.sync.aligned.m16n8k16.row.col.f32.f16.f16.f32 "
        "{%0,%1,%2,%3}, {%4,%5,%6,%7}, {%8,%9}, {%0,%1,%2,%3};"
        : "+f"(d[0]), "+f"(d[1]), "+f"(d[2]), "+f"(d[3])
        : "r"(a0), "r"(a1), "r"(a2), "r"(a3), "r"(b0), "r"(b1));
}
__device__ __forceinline__ uint32_t packh2(float a, float b) {
    __half2 h = __floats2half2_rn(a, b);
    return *reinterpret_cast<uint32_t*>(&h);
}
__device__ __forceinline__ uint64_t packf2(float lo, float hi) {
    uint64_t r;
    asm("mov.b64 %0, {%1, %2};" : "=l"(r) : "f"(lo), "f"(hi));
    return r;
}
__device__ __forceinline__ void ffma2(uint64_t& d, uint64_t a, uint64_t b) {
    asm("fma.rn.f32x2 %0, %1, %2, %0;" : "+l"(d) : "l"(a), "l"(b));
}

// ---------------------------------------------------------------------------
// K1: Wh = h @ W  (fp32 via packed f32x2 FMA, 64x64 tile, 4x4 micro, BK=16)
// ---------------------------------------------------------------------------
#define BM 64
#define BN 64
#define BK 16
__global__ __launch_bounds__(256) void gemm_kernel(const float* __restrict__ A,
                                                   const float* __restrict__ Wm) {
    __shared__ float sA[BK][BM + 4];
    __shared__ float sB[BK][BN];
    const int tid = threadIdx.x;
    const int tx = tid & 15, ty = tid >> 4;
    const int mBase = blockIdx.x * BM, nBase = blockIdx.y * BN;

    uint64_t acc2[4][2];
#pragma unroll
    for (int i = 0; i < 4; i++) { acc2[i][0] = 0ull; acc2[i][1] = 0ull; }

    for (int k0 = 0; k0 < INF_; k0 += BK) {
#pragma unroll
        for (int r = 0; r < 4; r++) {
            int idx = tid + r * 256;
            int m = idx >> 4, kk = idx & 15;
            sA[kk][m] = A[(size_t)(mBase + m) * INF_ + k0 + kk];
        }
#pragma unroll
        for (int r = 0; r < 4; r++) {
            int idx = tid + r * 256;
            int kk = idx >> 6, n = idx & 63;
            sB[kk][n] = Wm[(size_t)(k0 + kk) * OUTF_ + nBase + n];
        }
        __syncthreads();
#pragma unroll
        for (int kk = 0; kk < BK; kk++) {
            float4 a4 = *reinterpret_cast<const float4*>(&sA[kk][ty * 4]);
            float4 b4 = *reinterpret_cast<const float4*>(&sB[kk][tx * 4]);
            uint64_t bv0 = packf2(b4.x, b4.y);
            uint64_t bv1 = packf2(b4.z, b4.w);
            uint64_t av0 = packf2(a4.x, a4.x);
            uint64_t av1 = packf2(a4.y, a4.y);
            uint64_t av2 = packf2(a4.z, a4.z);
            uint64_t av3 = packf2(a4.w, a4.w);
            ffma2(acc2[0][0], av0, bv0); ffma2(acc2[0][1], av0, bv1);
            ffma2(acc2[1][0], av1, bv0); ffma2(acc2[1][1], av1, bv1);
            ffma2(acc2[2][0], av2, bv0); ffma2(acc2[2][1], av2, bv1);
            ffma2(acc2[3][0], av3, bv0); ffma2(acc2[3][1], av3, bv1);
        }
        __syncthreads();
    }
#pragma unroll
    for (int i = 0; i < 4; i++) {
        size_t off = (size_t)(mBase + ty * 4 + i) * OUTF_ + nBase + tx * 4;
        uint64_t v2[2] = {acc2[i][0], acc2[i][1]};
        *reinterpret_cast<float4*>(&g_Wh[off]) = *reinterpret_cast<const float4*>(v2);
    }
}

// ---------------------------------------------------------------------------
// K2: wh1/wh2 per (b,h,n), pre-scaled by log2(e). One warp per row.
// ---------------------------------------------------------------------------
__global__ __launch_bounds__(256) void wh12_kernel(const float* __restrict__ a) {
    int gw = blockIdx.x * 8 + (threadIdx.x >> 5);
    int lane = threadIdx.x & 31;
    float v = g_Wh[(size_t)gw * 32 + lane];
    float s1 = warpSum(v * a[lane]);
    float s2 = warpSum(v * a[32 + lane]);
    if (lane == 0) { g_wh1s[gw] = s1 * LOG2E; g_wh2s[gw] = s2 * LOG2E; }
}

// ---------------------------------------------------------------------------
// K2c: per-(b,h) max of wh2 (log2-scaled). One block per bh.
// ---------------------------------------------------------------------------
__global__ __launch_bounds__(256) void w2max_kernel() {
    __shared__ float red[8];
    const int bh = blockIdx.x, tid = threadIdx.x;
    float mx = -INFINITY;
#pragma unroll
    for (int k = 0; k < 8; k++)
        mx = fmaxf(mx, g_wh2s[bh * Nv + tid + k * 256]);
    mx = warpMax(mx);
    if ((tid & 31) == 0) red[tid >> 5] = mx;
    __syncthreads();
    if (tid == 0) {
        float m = red[0];
#pragma unroll
        for (int w = 1; w < 8; w++) m = fmaxf(m, red[w]);
        g_w2max[bh] = m;
    }
}

// ---------------------------------------------------------------------------
// K3a: compress adj to bitmask via ballot
// ---------------------------------------------------------------------------
__global__ __launch_bounds__(256) void adjbits_kernel(const int* __restrict__ adj) {
    unsigned idx = blockIdx.x * 256u + threadIdx.x;
    unsigned mask = __ballot_sync(0xFFFFFFFFu, adj[idx] > 0);
    if ((threadIdx.x & 31) == 0) g_adjbits[idx >> 5] = mask;
}

// ---------------------------------------------------------------------------
// K2b: V tiles -> f16, transposed to [d 32][j 128] per (bh, jt). grid (16, 32)
// ---------------------------------------------------------------------------
__global__ __launch_bounds__(256) void vconv_kernel() {
    __shared__ float sVf[128 * 33];
    const int jt = blockIdx.x, bh = blockIdx.y, tid = threadIdx.x;
    const float* src = &g_Wh[(size_t)bh * 65536 + (size_t)jt * 4096];
#pragma unroll
    for (int k = 0; k < 16; k++) {
        int idx = tid + k * 256;
        sVf[(idx >> 5) * 33 + (idx & 31)] = src[idx];
    }
    __syncthreads();
    __half2* dst = reinterpret_cast<__half2*>(g_Vh16 + ((size_t)bh * 16 + jt) * 4096);
#pragma unroll
    for (int it = 0; it < 8; it++) {
        int q = tid + it * 256;
        int d = q >> 6, jp = (q & 63) * 2;
        dst[q] = __floats2half2_rn(sVf[jp * 33 + d], sVf[(jp + 1) * 33 + d]);
    }
}

// ---------------------------------------------------------------------------
// K4: fused scores (factorized, MUFU-free) + HMMA PV + ones-MMA l + ELU.
// grid (16 itiles, 8 h, 4 b), 256 threads. Warp w owns 16 i-rows.
// ---------------------------------------------------------------------------
#define ONESH2 0x3C003C00u

__global__ __launch_bounds__(256) void attn_kernel(float* __restrict__ out) {
    __shared__ float2 sRowE[128];                // (E1, E2) per i-row
    __shared__ float  sF1[128];                  // 2^(W2_j)
    __shared__ float  sF2[128];                  // 2^(0.2*W2_j)
    __shared__ uint4  sBits[128];
    __shared__ __align__(16) uint32_t sVt[32 * 68];  // V^T f16 [d][j], row stride 68 u32

    const int tid  = threadIdx.x;
    const int w    = tid >> 5, lane = tid & 31;
    const int tig  = lane & 3, grp = lane >> 2;
    const int iT = blockIdx.x, hh = blockIdx.y, b = blockIdx.z;
    const int bh = b * Hh + hh;
    const int iBase = iT * 128;
    const int il0 = w * 16 + grp, il1 = il0 + 8;

    if (tid < 128) {
        int gi = bh * Nv + iBase + tid;
        float C = g_wh1s[gi];
        float s = C + g_w2max[bh];
        float M = fmaxf(s, SLOPE * s);
        sRowE[tid] = make_float2(ex2f(C - M), ex2f(SLOPE * C - M));
    }
    __syncthreads();
    const float2 E0 = sRowE[il0];
    const float2 E1 = sRowE[il1];

    float dacc[4][4];
#pragma unroll
    for (int nb = 0; nb < 4; nb++)
#pragma unroll
        for (int q = 0; q < 4; q++) dacc[nb][q] = 0.f;
    float lacc[4] = {0.f, 0.f, 0.f, 0.f};

    const unsigned* bitsBase = g_adjbits + (size_t)(b * 2048 + iBase) * 64;
    const float* wh2Base = g_wh2s + (size_t)bh * 2048;
    const uint4* vBase = reinterpret_cast<const uint4*>(g_Vh16 + (size_t)bh * 16 * 4096);
    const int s0 = tig * 2;

    for (int jt = 0; jt < 16; jt++) {
        __syncthreads();
        {   // V tile: 512 uint4 -> padded smem rows (17 uint4 per d-row)
            uint4* dst = reinterpret_cast<uint4*>(sVt);
            int q0 = tid, q1 = tid + 256;
            dst[(q0 >> 4) * 17 + (q0 & 15)] = vBase[jt * 512 + q0];
            dst[(q1 >> 4) * 17 + (q1 & 15)] = vBase[jt * 512 + q1];
        }
        if (tid < 128) {
            float w2 = wh2Base[jt * 128 + tid];
            sF1[tid] = ex2f(w2);
            sF2[tid] = ex2f(SLOPE * w2);
            sBits[tid] = *reinterpret_cast<const uint4*>(bitsBase + (size_t)tid * 64 + jt * 4);
        }
        __syncthreads();

        const uint4 bq0 = sBits[il0];
        const uint4 bq1 = sBits[il1];
        const unsigned* bw0w = reinterpret_cast<const unsigned*>(&bq0);
        const unsigned* bw1w = reinterpret_cast<const unsigned*>(&bq1);

#pragma unroll
        for (int k2 = 0; k2 < 4; k2++) {
            const unsigned u0 = bw0w[k2] >> s0;   // row il0 bits, tig-aligned
            const unsigned u1 = bw1w[k2] >> s0;   // row il1 bits
#pragma unroll
            for (int kh = 0; kh < 2; kh++) {
                const int ks = k2 * 2 + kh;
                const int jb = ks * 16 + tig * 2;
                const float2 F1a = *reinterpret_cast<const float2*>(&sF1[jb]);
                const float2 F1b = *reinterpret_cast<const float2*>(&sF1[jb + 8]);
                const float2 F2a = *reinterpret_cast<const float2*>(&sF2[jb]);
                const float2 F2b = *reinterpret_cast<const float2*>(&sF2[jb + 8]);
                const unsigned m0 = kh ? 0x10000u : 0x1u;
                const unsigned m1 = kh ? 0x20000u : 0x2u;
                const unsigned m8 = kh ? 0x1000000u : 0x100u;
                const unsigned m9 = kh ? 0x2000000u : 0x200u;

                float p00 = fmaxf(E0.x * F1a.x, E0.y * F2a.x); p00 = (u0 & m0) ? p00 : 0.f;
                float p01 = fmaxf(E0.x * F1a.y, E0.y * F2a.y); p01 = (u0 & m1) ? p01 : 0.f;
                float p02 = fmaxf(E0.x * F1b.x, E0.y * F2b.x); p02 = (u0 & m8) ? p02 : 0.f;
                float p03 = fmaxf(E0.x * F1b.y, E0.y * F2b.y); p03 = (u0 & m9) ? p03 : 0.f;
                float p10 = fmaxf(E1.x * F1a.x, E1.y * F2a.x); p10 = (u1 & m0) ? p10 : 0.f;
                float p11 = fmaxf(E1.x * F1a.y, E1.y * F2a.y); p11 = (u1 & m1) ? p11 : 0.f;
                float p12 = fmaxf(E1.x * F1b.x, E1.y * F2b.x); p12 = (u1 & m8) ? p12 : 0.f;
                float p13 = fmaxf(E1.x * F1b.y, E1.y * F2b.y); p13 = (u1 & m9) ? p13 : 0.f;

                uint32_t A0 = packh2(p00, p01);
                uint32_t A1 = packh2(p10, p11);
                uint32_t A2 = packh2(p02, p03);
                uint32_t A3 = packh2(p12, p13);

                const uint32_t* vcol = sVt + (jb >> 1);
#pragma unroll
                for (int nb = 0; nb < 4; nb++) {
                    int drow = nb * 8 + grp;
                    uint32_t B0 = vcol[drow * 68];
                    uint32_t B1 = vcol[drow * 68 + 4];
                    mma16816(dacc[nb], A0, A1, A2, A3, B0, B1);
                }
                mma16816(lacc, A0, A1, A2, A3, ONESH2, ONESH2);
            }
        }
    }

    const float rl0 = 1.f / lacc[0];
    const float rl1 = 1.f / lacc[2];

    const size_t o0 = ((size_t)bh * Nv + iBase + il0) * NHv + tig * 2;
    const size_t o1 = ((size_t)bh * Nv + iBase + il1) * NHv + tig * 2;
#pragma unroll
    for (int nb = 0; nb < 4; nb++) {
        float x0 = dacc[nb][0] * rl0, x1 = dacc[nb][1] * rl0;
        float y0 = dacc[nb][2] * rl1, y1 = dacc[nb][3] * rl1;
        x0 = (x0 > 0.f) ? x0 : expm1f(x0);
        x1 = (x1 > 0.f) ? x1 : expm1f(x1);
        y0 = (y0 > 0.f) ? y0 : expm1f(y0);
        y1 = (y1 > 0.f) ? y1 : expm1f(y1);
        *reinterpret_cast<float2*>(&out[o0 + nb * 8]) = make_float2(x0, x1);
        *reinterpret_cast<float2*>(&out[o1 + nb * 8]) = make_float2(y0, y1);
    }
}

// ---------------------------------------------------------------------------
extern "C" void kernel_launch(void* const* d_in, const int* in_sizes, int n_in,
                              void* d_out, int out_size) {
    const float* h   = (const float*)d_in[0];   // [4,2048,256]
    const int*   adj = (const int*)  d_in[1];   // [4,2048,2048]
    const float* W   = (const float*)d_in[2];   // [256,256]
    const float* a   = (const float*)d_in[3];   // [64,1]
    float* out = (float*)d_out;                 // [4,2048,256]

    gemm_kernel<<<dim3(128, 4), 256>>>(h, W);
    adjbits_kernel<<<65536, 256>>>(adj);
    wh12_kernel<<<8192, 256>>>(a);
    w2max_kernel<<<32, 256>>>();
    vconv_kernel<<<dim3(16, 32), 256>>>();
    attn_kernel<<<dim3(16, 8, 4), 256>>>(out);
}

// round 6
// speedup vs baseline: 4.1826x; 1.1510x over previous
#include <cuda_runtime.h>
#include <cuda_fp16.h>
#include <cstdint>

// Problem constants
#define Bv     4
#define Nv     2048
#define INF_   256
#define OUTF_  256
#define Hh     8
#define NHv    32
#define SLOPE  0.2f
#define LOG2E  1.4426950408889634f

// ---------------------------------------------------------------------------
// Device scratch (no allocations; zero-initialized at load)
// ---------------------------------------------------------------------------
__device__ float    g_wh1s [Bv * Hh * Nv];              // wh1 * log2e   [bh][n]
__device__ float    g_wh2s [Bv * Hh * Nv];              // wh2 * log2e   [bh][n]
__device__ unsigned g_w2maxU[Bv * Hh];                  // ordered-uint max of wh2s (atomicMax)
__device__ unsigned g_adjbits[Bv * Nv * (Nv / 32)];     // 2 MB adj bitmask
__device__ __align__(16) __half g_Vh16[32 * 16 * 4096]; // 4 MB V tiles f16, [bh][jt][d 32][j 128]

// ---------------------------------------------------------------------------
// helpers
// ---------------------------------------------------------------------------
__device__ __forceinline__ float ex2f(float x) {
    float y; asm("ex2.approx.ftz.f32 %0, %1;" : "=f"(y) : "f"(x)); return y;
}
__device__ __forceinline__ uint32_t packh2(float a, float b) {
    __half2 h = __floats2half2_rn(a, b);
    return *reinterpret_cast<uint32_t*>(&h);
}
__device__ __forceinline__ uint32_t hmul2u(uint32_t a, uint32_t b) {
    uint32_t d; asm("mul.f16x2 %0, %1, %2;" : "=r"(d) : "r"(a), "r"(b)); return d;
}
__device__ __forceinline__ uint32_t hmax2u(uint32_t a, uint32_t b) {
    uint32_t d; asm("max.f16x2 %0, %1, %2;" : "=r"(d) : "r"(a), "r"(b)); return d;
}
__device__ __forceinline__ uint32_t prmtu(uint32_t a, uint32_t b, uint32_t c) {
    uint32_t d; asm("prmt.b32 %0, %1, %2, %3;" : "=r"(d) : "r"(a), "r"(b), "r"(c)); return d;
}
__device__ __forceinline__ uint32_t fkey(float f) {      // monotone float->uint
    uint32_t u = __float_as_uint(f);
    return u ^ (uint32_t)(((int)u >> 31) | 0x80000000);
}
__device__ __forceinline__ float fkeyinv(uint32_t k) {
    return __uint_as_float(k ^ (((int)k >> 31) ? 0x80000000u : 0xFFFFFFFFu));
}
__device__ __forceinline__ uint64_t packf2(float lo, float hi) {
    uint64_t r;
    asm("mov.b64 %0, {%1, %2};" : "=l"(r) : "f"(lo), "f"(hi));
    return r;
}
__device__ __forceinline__ void unpackf2(uint64_t v, float& lo, float& hi) {
    asm("mov.b64 {%0, %1}, %2;" : "=f"(lo), "=f"(hi) : "l"(v));
}
__device__ __forceinline__ void ffma2(uint64_t& d, uint64_t a, uint64_t b) {
    asm("fma.rn.f32x2 %0, %1, %2, %0;" : "+l"(d) : "l"(a), "l"(b));
}
__device__ __forceinline__ void mma16816(float* d, uint32_t a0, uint32_t a1, uint32_t a2,
                                         uint32_t a3, uint32_t b0, uint32_t b1) {
    asm volatile(
        "mma.sync.aligned.m16n8k16.row.col.f32.f16.f16.f32 "
        "{%0,%1,%2,%3}, {%4,%5,%6,%7}, {%8,%9}, {%0,%1,%2,%3};"
        : "+f"(d[0]), "+f"(d[1]), "+f"(d[2]), "+f"(d[3])
        : "r"(a0), "r"(a1), "r"(a2), "r"(a3), "r"(b0), "r"(b1));
}

// ---------------------------------------------------------------------------
// K1: f32x2 GEMM Wh = h @ W with fused epilogue honoring the raw .view:
//     head  h  = row >> 8 (within batch)
//     node  n' = (row & 255) * 8 + (col >> 5)
//     feat  d  = col & 31
// Emits: g_wh1s/g_wh2s (log2e-scaled, exact f32), per-head wh2 max (atomicMax),
//        V tiles f16 in [bh][jt][d][j] layout.
// grid (64, 4), 256 threads; tile 128x64, BK=16, micro 8x4.
// ---------------------------------------------------------------------------
__global__ __launch_bounds__(256) void gemm_fused_kernel(const float* __restrict__ A,
                                                         const float* __restrict__ Wm,
                                                         const float* __restrict__ a_vec) {
    __shared__ float sA[16][132];
    __shared__ float sB[16][64];
    __shared__ float sa[64];
    const int tid = threadIdx.x;
    const int tx = tid & 15, ty = tid >> 4;
    const int mBase = blockIdx.x * 128, nBase = blockIdx.y * 64;
    if (tid < 64) sa[tid] = a_vec[tid];

    uint64_t acc2[8][2];
#pragma unroll
    for (int i = 0; i < 8; i++) { acc2[i][0] = 0ull; acc2[i][1] = 0ull; }

    for (int k0 = 0; k0 < INF_; k0 += 16) {
        __syncthreads();
        {   // A tile 128x16, transposed store (conflict-free: lanes span 32 rows)
            int r = tid & 127, kb = (tid >> 7) * 8;
            const float4* src = reinterpret_cast<const float4*>(&A[(size_t)(mBase + r) * INF_ + k0 + kb]);
            float4 v0 = src[0], v1 = src[1];
            sA[kb + 0][r] = v0.x; sA[kb + 1][r] = v0.y; sA[kb + 2][r] = v0.z; sA[kb + 3][r] = v0.w;
            sA[kb + 4][r] = v1.x; sA[kb + 5][r] = v1.y; sA[kb + 6][r] = v1.z; sA[kb + 7][r] = v1.w;
        }
        {   // B tile 16x64
            int kk = tid >> 4, n4 = (tid & 15) * 4;
            *reinterpret_cast<float4*>(&sB[kk][n4]) =
                *reinterpret_cast<const float4*>(&Wm[(size_t)(k0 + kk) * OUTF_ + nBase + n4]);
        }
        __syncthreads();
#pragma unroll
        for (int kk = 0; kk < 16; kk++) {
            float af[8], bf[4];
            *reinterpret_cast<float4*>(&af[0]) = *reinterpret_cast<const float4*>(&sA[kk][ty * 8]);
            *reinterpret_cast<float4*>(&af[4]) = *reinterpret_cast<const float4*>(&sA[kk][ty * 8 + 4]);
            *reinterpret_cast<float4*>(&bf[0]) = *reinterpret_cast<const float4*>(&sB[kk][tx * 4]);
            uint64_t b01 = packf2(bf[0], bf[1]);
            uint64_t b23 = packf2(bf[2], bf[3]);
#pragma unroll
            for (int i = 0; i < 8; i++) {
                uint64_t av = packf2(af[i], af[i]);
                ffma2(acc2[i][0], av, b01);
                ffma2(acc2[i][1], av, b23);
            }
        }
    }

    // unpack accumulators: c[rr][q] = Wh[mBase + ty*8 + rr][nBase + tx*4 + q]
    float c[8][4];
#pragma unroll
    for (int i = 0; i < 8; i++) {
        unpackf2(acc2[i][0], c[i][0], c[i][1]);
        unpackf2(acc2[i][1], c[i][2], c[i][3]);
    }

    // ---- fused epilogue with raw-view mapping ----
    const int b    = mBase >> 11;
    const int hloc = (mBase & 2047) >> 8;
    const int bh   = b * Hh + hloc;
    const int r255 = mBase & 255;                 // 0 or 128
    const int cblk = (nBase >> 5) + (tx >> 3);    // node sub-index 0..7
    const int dbase = (tx & 7) * 4;               // feature d base

    // wh1/wh2 partial dots over this thread's 4 features, reduced across the
    // 8 lanes (tx&7) that share (rows, node-column).
    float w1p[8], w2p[8];
#pragma unroll
    for (int rr = 0; rr < 8; rr++) {
        float s1 = c[rr][0] * sa[dbase]      + c[rr][1] * sa[dbase + 1]
                 + c[rr][2] * sa[dbase + 2]  + c[rr][3] * sa[dbase + 3];
        float s2 = c[rr][0] * sa[32 + dbase]     + c[rr][1] * sa[32 + dbase + 1]
                 + c[rr][2] * sa[32 + dbase + 2] + c[rr][3] * sa[32 + dbase + 3];
#pragma unroll
        for (int o = 1; o < 8; o <<= 1) {
            s1 += __shfl_xor_sync(0xFFFFFFFFu, s1, o);
            s2 += __shfl_xor_sync(0xFFFFFFFFu, s2, o);
        }
        w1p[rr] = s1 * LOG2E;
        w2p[rr] = s2 * LOG2E;
    }

    // V f16 stores: V[bh][jt = n'>>7][d][j = n'&127]
#pragma unroll
    for (int rr = 0; rr < 8; rr++) {
        const int n = (r255 + ty * 8 + rr) * 8 + cblk;
        __half* vt = &g_Vh16[((size_t)(bh * 16 + (n >> 7))) * 4096 + (n & 127)];
        vt[(size_t)(dbase + 0) * 128] = __float2half(c[rr][0]);
        vt[(size_t)(dbase + 1) * 128] = __float2half(c[rr][1]);
        vt[(size_t)(dbase + 2) * 128] = __float2half(c[rr][2]);
        vt[(size_t)(dbase + 3) * 128] = __float2half(c[rr][3]);
    }

    // wh1/wh2 writes: lane k of each 8-group writes row rr=k
    {
        const int rr = tx & 7;
        const int n = (r255 + ty * 8 + rr) * 8 + cblk;
        g_wh1s[bh * Nv + n] = w1p[rr];
        g_wh2s[bh * Nv + n] = w2p[rr];
    }

    // per-head max of wh2 (block covers one head only)
    {
        float mx = w2p[0];
#pragma unroll
        for (int rr = 1; rr < 8; rr++) mx = fmaxf(mx, w2p[rr]);
#pragma unroll
        for (int o = 16; o > 0; o >>= 1) mx = fmaxf(mx, __shfl_xor_sync(0xFFFFFFFFu, mx, o));
        if ((tid & 31) == 0) atomicMax(&g_w2maxU[bh], fkey(mx));
    }
}

// ---------------------------------------------------------------------------
// K2: compress adj to bitmask via ballot
// ---------------------------------------------------------------------------
__global__ __launch_bounds__(256) void adjbits_kernel(const int* __restrict__ adj) {
    unsigned idx = blockIdx.x * 256u + threadIdx.x;
    unsigned mask = __ballot_sync(0xFFFFFFFFu, adj[idx] > 0);
    if ((threadIdx.x & 31) == 0) g_adjbits[idx >> 5] = mask;
}

// ---------------------------------------------------------------------------
// K3: fused scores (h2 packed, MUFU-free) + HMMA PV + ones-MMA l + ELU.
// grid (16 itiles, 8 h, 4 b), 256 threads. Warp w owns 16 i-rows.
// ---------------------------------------------------------------------------
#define ONESH2 0x3C003C00u

__global__ __launch_bounds__(256) void attn_kernel(float* __restrict__ out) {
    __shared__ uint32_t sRowE[128];              // h2 {E1, E2} per i-row
    __shared__ __half sF1[128];                  // 2^(W2-wmax)
    __shared__ __half sF2[128];                  // 2^(0.2*(W2-wmax))
    __shared__ uint4  sBits[128];
    __shared__ __align__(16) uint32_t sVt[32 * 68];  // V^T f16 [d][j], row stride 68 u32

    const int tid  = threadIdx.x;
    const int w    = tid >> 5, lane = tid & 31;
    const int tig  = lane & 3, grp = lane >> 2;
    const int iT = blockIdx.x, hh = blockIdx.y, b = blockIdx.z;
    const int bh = b * Hh + hh;
    const int iBase = iT * 128;
    const int il0 = w * 16 + grp, il1 = il0 + 8;

    const float wmax = fkeyinv(g_w2maxU[bh]);
    if (tid < 128) {
        float C = g_wh1s[bh * Nv + iBase + tid];
        float s = C + wmax;
        float M = fmaxf(s, SLOPE * s);
        sRowE[tid] = packh2(ex2f(s - M), ex2f(SLOPE * s - M));
    }
    __syncthreads();
    const uint32_t e0 = sRowE[il0], e1 = sRowE[il1];
    const uint32_t E0lo = prmtu(e0, e0, 0x1010u), E0hi = prmtu(e0, e0, 0x3232u);
    const uint32_t E1lo = prmtu(e1, e1, 0x1010u), E1hi = prmtu(e1, e1, 0x3232u);

    float dacc[4][4];
#pragma unroll
    for (int nb = 0; nb < 4; nb++)
#pragma unroll
        for (int q = 0; q < 4; q++) dacc[nb][q] = 0.f;
    float lacc[4] = {0.f, 0.f, 0.f, 0.f};

    const unsigned* bitsBase = g_adjbits + (size_t)(b * 2048 + iBase) * 64;
    const float* wh2Base = g_wh2s + (size_t)bh * 2048;
    const uint4* vBase = reinterpret_cast<const uint4*>(g_Vh16 + (size_t)bh * 16 * 4096);
    const int s0 = tig * 2;
    const int tig2 = tig * 2;

    for (int jt = 0; jt < 16; jt++) {
        __syncthreads();
        {   // V tile: 512 uint4 -> padded smem rows (17 uint4 per d-row)
            uint4* dst = reinterpret_cast<uint4*>(sVt);
            int q0 = tid, q1 = tid + 256;
            dst[(q0 >> 4) * 17 + (q0 & 15)] = vBase[jt * 512 + q0];
            dst[(q1 >> 4) * 17 + (q1 & 15)] = vBase[jt * 512 + q1];
        }
        if (tid < 128) {
            float w2 = wh2Base[jt * 128 + tid] - wmax;
            sF1[tid] = __float2half(ex2f(w2));
            sF2[tid] = __float2half(ex2f(SLOPE * w2));
            sBits[tid] = *reinterpret_cast<const uint4*>(bitsBase + (size_t)tid * 64 + jt * 4);
        }
        __syncthreads();

        const uint4 bq0 = sBits[il0];
        const uint4 bq1 = sBits[il1];
        const unsigned* bw0w = reinterpret_cast<const unsigned*>(&bq0);
        const unsigned* bw1w = reinterpret_cast<const unsigned*>(&bq1);

#pragma unroll
        for (int k2 = 0; k2 < 4; k2++) {
            const unsigned u0 = bw0w[k2] >> s0;
            const unsigned u1 = bw1w[k2] >> s0;
            // bits {0,1},{8,9},{16,17},{24,25} land on byte MSBs after <<7 / <<6
            const unsigned v07 = u0 << 7, v06 = u0 << 6;
            const unsigned v17 = u1 << 7, v16 = u1 << 6;
#pragma unroll
            for (int kh = 0; kh < 2; kh++) {
                const int jb = (k2 * 2 + kh) * 16 + tig2;
                const uint32_t F1a = *reinterpret_cast<const uint32_t*>(sF1 + jb);
                const uint32_t F1b = *reinterpret_cast<const uint32_t*>(sF1 + jb + 8);
                const uint32_t F2a = *reinterpret_cast<const uint32_t*>(sF2 + jb);
                const uint32_t F2b = *reinterpret_cast<const uint32_t*>(sF2 + jb + 8);
                const uint32_t cA = kh ? 0xEEAAu : 0xCC88u;   // PRMT sign-replicate masks
                const uint32_t cB = kh ? 0xFFBBu : 0xDD99u;

                uint32_t A0 = hmax2u(hmul2u(E0lo, F1a), hmul2u(E0hi, F2a)) & prmtu(v07, v06, cA);
                uint32_t A2 = hmax2u(hmul2u(E0lo, F1b), hmul2u(E0hi, F2b)) & prmtu(v07, v06, cB);
                uint32_t A1 = hmax2u(hmul2u(E1lo, F1a), hmul2u(E1hi, F2a)) & prmtu(v17, v16, cA);
                uint32_t A3 = hmax2u(hmul2u(E1lo, F1b), hmul2u(E1hi, F2b)) & prmtu(v17, v16, cB);

                const uint32_t* vcol = sVt + (jb >> 1);
#pragma unroll
                for (int nb = 0; nb < 4; nb++) {
                    int drow = nb * 8 + grp;
                    uint32_t B0 = vcol[drow * 68];
                    uint32_t B1 = vcol[drow * 68 + 4];
                    mma16816(dacc[nb], A0, A1, A2, A3, B0, B1);
                }
                mma16816(lacc, A0, A1, A2, A3, ONESH2, ONESH2);
            }
        }
    }

    const float rl0 = 1.f / lacc[0];
    const float rl1 = 1.f / lacc[2];

    const size_t o0 = ((size_t)bh * Nv + iBase + il0) * NHv + tig * 2;
    const size_t o1 = ((size_t)bh * Nv + iBase + il1) * NHv + tig * 2;
#pragma unroll
    for (int nb = 0; nb < 4; nb++) {
        float x0 = dacc[nb][0] * rl0, x1 = dacc[nb][1] * rl0;
        float y0 = dacc[nb][2] * rl1, y1 = dacc[nb][3] * rl1;
        x0 = (x0 > 0.f) ? x0 : expm1f(x0);
        x1 = (x1 > 0.f) ? x1 : expm1f(x1);
        y0 = (y0 > 0.f) ? y0 : expm1f(y0);
        y1 = (y1 > 0.f) ? y1 : expm1f(y1);
        *reinterpret_cast<float2*>(&out[o0 + nb * 8]) = make_float2(x0, x1);
        *reinterpret_cast<float2*>(&out[o1 + nb * 8]) = make_float2(y0, y1);
    }
}

// ---------------------------------------------------------------------------
extern "C" void kernel_launch(void* const* d_in, const int* in_sizes, int n_in,
                              void* d_out, int out_size) {
    const float* h   = (const float*)d_in[0];   // [4,2048,256]
    const int*   adj = (const int*)  d_in[1];   // [4,2048,2048]
    const float* W   = (const float*)d_in[2];   // [256,256]
    const float* a   = (const float*)d_in[3];   // [64,1]
    float* out = (float*)d_out;                 // [4,2048,256]

    gemm_fused_kernel<<<dim3(64, 4), 256>>>(h, W, a);
    adjbits_kernel<<<65536, 256>>>(adj);
    attn_kernel<<<dim3(16, 8, 4), 256>>>(out);
}

// round 7
// speedup vs baseline: 4.7572x; 1.1374x over previous
#include <cuda_runtime.h>
#include <cuda_fp16.h>
#include <cstdint>

// Problem constants
#define Bv     4
#define Nv     2048
#define INF_   256
#define OUTF_  256
#define Hh     8
#define NHv    32
#define SLOPE  0.2f
#define LOG2E  1.4426950408889634f

// ---------------------------------------------------------------------------
// Device scratch (no allocations; zero-initialized at load)
// ---------------------------------------------------------------------------
__device__ float    g_wh1s [Bv * Hh * Nv];              // wh1 * log2e   [bh][n]
__device__ float    g_wh2s [Bv * Hh * Nv];              // wh2 * log2e   [bh][n]
__device__ unsigned g_w2maxU[Bv * Hh];                  // ordered-uint max of wh2s (atomicMax)
__device__ unsigned g_adjbits[Bv * Nv * (Nv / 32)];     // 2 MB adj bitmask
__device__ __align__(16) __half g_Vh16[32 * 16 * 4096]; // 4 MB V tiles f16, [bh][jt][d 32][j 128]

// ---------------------------------------------------------------------------
// helpers
// ---------------------------------------------------------------------------
__device__ __forceinline__ float ex2f(float x) {
    float y; asm("ex2.approx.ftz.f32 %0, %1;" : "=f"(y) : "f"(x)); return y;
}
__device__ __forceinline__ uint32_t packh2(float a, float b) {
    __half2 h = __floats2half2_rn(a, b);
    return *reinterpret_cast<uint32_t*>(&h);
}
__device__ __forceinline__ uint32_t hmul2u(uint32_t a, uint32_t b) {
    uint32_t d; asm("mul.f16x2 %0, %1, %2;" : "=r"(d) : "r"(a), "r"(b)); return d;
}
__device__ __forceinline__ uint32_t hmax2u(uint32_t a, uint32_t b) {
    uint32_t d; asm("max.f16x2 %0, %1, %2;" : "=r"(d) : "r"(a), "r"(b)); return d;
}
__device__ __forceinline__ uint32_t prmtu(uint32_t a, uint32_t b, uint32_t c) {
    uint32_t d; asm("prmt.b32 %0, %1, %2, %3;" : "=r"(d) : "r"(a), "r"(b), "r"(c)); return d;
}
__device__ __forceinline__ uint32_t fkey(float f) {      // monotone float->uint
    uint32_t u = __float_as_uint(f);
    return u ^ (uint32_t)(((int)u >> 31) | 0x80000000);
}
__device__ __forceinline__ float fkeyinv(uint32_t k) {
    return __uint_as_float(k ^ (((int)k >> 31) ? 0x80000000u : 0xFFFFFFFFu));
}
__device__ __forceinline__ uint32_t f2tf32(float f) {
    uint32_t r; asm("cvt.rna.tf32.f32 %0, %1;" : "=r"(r) : "f"(f)); return r;
}
__device__ __forceinline__ void mma16816(float* d, uint32_t a0, uint32_t a1, uint32_t a2,
                                         uint32_t a3, uint32_t b0, uint32_t b1) {
    asm volatile(
        "mma.sync.aligned.m16n8k16.row.col.f32.f16.f16.f32 "
        "{%0,%1,%2,%3}, {%4,%5,%6,%7}, {%8,%9}, {%0,%1,%2,%3};"
        : "+f"(d[0]), "+f"(d[1]), "+f"(d[2]), "+f"(d[3])
        : "r"(a0), "r"(a1), "r"(a2), "r"(a3), "r"(b0), "r"(b1));
}
__device__ __forceinline__ void mma_tf32(float* d, uint32_t a0, uint32_t a1, uint32_t a2,
                                         uint32_t a3, uint32_t b0, uint32_t b1) {
    asm volatile(
        "mma.sync.aligned.m16n8k8.row.col.f32.tf32.tf32.f32 "
        "{%0,%1,%2,%3}, {%4,%5,%6,%7}, {%8,%9}, {%0,%1,%2,%3};"
        : "+f"(d[0]), "+f"(d[1]), "+f"(d[2]), "+f"(d[3])
        : "r"(a0), "r"(a1), "r"(a2), "r"(a3), "r"(b0), "r"(b1));
}

// ---------------------------------------------------------------------------
// K1: 3x-tf32 tensor GEMM Wh = h @ W with fused epilogue (raw .view mapping:
//     head = row>>8 (in batch), node n' = (row&255)*8 + (col>>5), d = col&31).
// Split: X = hi + lo (hi = tf32 rna); Wh = Ah*Bh + Al*Bh + Ah*Bl (~f32 acc).
// grid (64 m, 4 n), 256 threads; tile 128x64, BK=16.
// Emits g_wh1s/g_wh2s (log2e-scaled), per-head wh2 max, V f16 [bh][jt][d][j].
// ---------------------------------------------------------------------------
__global__ __launch_bounds__(256) void gemm3x_kernel(const float* __restrict__ A,
                                                     const float* __restrict__ Wm,
                                                     const float* __restrict__ a_vec) {
    __shared__ uint32_t sAh[128][20], sAl[128][20];   // [m][k], stride 20: conflict-free
    __shared__ uint32_t sBh[16][72],  sBl[16][72];    // [k][n], stride 72: conflict-free
    __shared__ float sa[64];

    const int tid = threadIdx.x;
    const int w = tid >> 5, lane = tid & 31;
    const int g = lane >> 2, tig = lane & 3;
    const int mBase = blockIdx.x * 128, nBase = blockIdx.y * 64;
    if (tid < 64) sa[tid] = a_vec[tid];

    float c[8][4];
#pragma unroll
    for (int nb = 0; nb < 8; nb++)
#pragma unroll
        for (int q = 0; q < 4; q++) c[nb][q] = 0.f;

    const int rA = tid >> 1, kbA = (tid & 1) * 8;
    const int kkB = tid >> 4, n4B = (tid & 15) * 4;
    const int rw = w * 16;

    for (int k0 = 0; k0 < INF_; k0 += 16) {
        __syncthreads();
        {   // A tile 128x16 -> hi/lo tf32
            const float4* src = reinterpret_cast<const float4*>(&A[(size_t)(mBase + rA) * INF_ + k0 + kbA]);
            float4 v0 = src[0], v1 = src[1];
            float vf[8] = {v0.x, v0.y, v0.z, v0.w, v1.x, v1.y, v1.z, v1.w};
            uint32_t hu[8], lu[8];
#pragma unroll
            for (int i = 0; i < 8; i++) {
                hu[i] = f2tf32(vf[i]);
                lu[i] = f2tf32(vf[i] - __uint_as_float(hu[i]));
            }
            *reinterpret_cast<uint4*>(&sAh[rA][kbA])     = *reinterpret_cast<uint4*>(&hu[0]);
            *reinterpret_cast<uint4*>(&sAh[rA][kbA + 4]) = *reinterpret_cast<uint4*>(&hu[4]);
            *reinterpret_cast<uint4*>(&sAl[rA][kbA])     = *reinterpret_cast<uint4*>(&lu[0]);
            *reinterpret_cast<uint4*>(&sAl[rA][kbA + 4]) = *reinterpret_cast<uint4*>(&lu[4]);
        }
        {   // B tile 16x64 -> hi/lo tf32
            float4 v = *reinterpret_cast<const float4*>(&Wm[(size_t)(k0 + kkB) * OUTF_ + nBase + n4B]);
            float vf[4] = {v.x, v.y, v.z, v.w};
            uint32_t hu[4], lu[4];
#pragma unroll
            for (int i = 0; i < 4; i++) {
                hu[i] = f2tf32(vf[i]);
                lu[i] = f2tf32(vf[i] - __uint_as_float(hu[i]));
            }
            *reinterpret_cast<uint4*>(&sBh[kkB][n4B]) = *reinterpret_cast<uint4*>(&hu[0]);
            *reinterpret_cast<uint4*>(&sBl[kkB][n4B]) = *reinterpret_cast<uint4*>(&lu[0]);
        }
        __syncthreads();

#pragma unroll
        for (int kc = 0; kc < 2; kc++) {
            const int k8 = kc * 8;
            uint32_t ah0 = sAh[rw + g][k8 + tig],     ah1 = sAh[rw + g + 8][k8 + tig];
            uint32_t ah2 = sAh[rw + g][k8 + tig + 4], ah3 = sAh[rw + g + 8][k8 + tig + 4];
            uint32_t al0 = sAl[rw + g][k8 + tig],     al1 = sAl[rw + g + 8][k8 + tig];
            uint32_t al2 = sAl[rw + g][k8 + tig + 4], al3 = sAl[rw + g + 8][k8 + tig + 4];
#pragma unroll
            for (int nb = 0; nb < 8; nb++) {
                uint32_t bh0 = sBh[k8 + tig][nb * 8 + g];
                uint32_t bh1 = sBh[k8 + tig + 4][nb * 8 + g];
                uint32_t bl0 = sBl[k8 + tig][nb * 8 + g];
                uint32_t bl1 = sBl[k8 + tig + 4][nb * 8 + g];
                mma_tf32(c[nb], al0, al1, al2, al3, bh0, bh1);
                mma_tf32(c[nb], ah0, ah1, ah2, ah3, bl0, bl1);
                mma_tf32(c[nb], ah0, ah1, ah2, ah3, bh0, bh1);
            }
        }
    }

    // ---- fused epilogue (raw .view mapping) ----
    const int b    = mBase >> 11;
    const int hloc = (mBase & 2047) >> 8;
    const int bh   = b * Hh + hloc;
    const int r255 = mBase & 255;                 // 0 or 128
    const int cb0  = nBase >> 5;                  // even node sub-base {0,2,4,6}
    const int m0   = r255 + w * 16 + g;           // (m & 255) for row0; row1 = +8

    // V f16 stores: pack node-pair (nb, nb+4) -> half2 at consecutive j
#pragma unroll
    for (int nb = 0; nb < 4; nb++) {
#pragma unroll
        for (int q = 0; q < 4; q++) {
            const int d = nb * 8 + tig * 2 + (q & 1);
            const int j = (m0 + (q >> 1) * 8) * 8 + cb0;
            __half2 hv = __floats2half2_rn(c[nb][q], c[nb + 4][q]);
            *reinterpret_cast<__half2*>(
                &g_Vh16[((size_t)(bh * 16 + (j >> 7))) * 4096 + (size_t)d * 128 + (j & 127)]) = hv;
        }
    }

    // wh1/wh2 partial dots (per row rq, per node group gb), quad-reduced
    float s1v[2][2], s2v[2][2];
#pragma unroll
    for (int rq = 0; rq < 2; rq++) {
#pragma unroll
        for (int gb = 0; gb < 2; gb++) {
            float t1 = 0.f, t2 = 0.f;
#pragma unroll
            for (int k = 0; k < 4; k++) {
                const int d = k * 8 + tig * 2;
                float cx = c[gb * 4 + k][rq * 2], cy = c[gb * 4 + k][rq * 2 + 1];
                t1 += cx * sa[d]      + cy * sa[d + 1];
                t2 += cx * sa[32 + d] + cy * sa[32 + d + 1];
            }
            t1 += __shfl_xor_sync(0xFFFFFFFFu, t1, 1);
            t1 += __shfl_xor_sync(0xFFFFFFFFu, t1, 2);
            t2 += __shfl_xor_sync(0xFFFFFFFFu, t2, 1);
            t2 += __shfl_xor_sync(0xFFFFFFFFu, t2, 2);
            s1v[rq][gb] = t1 * LOG2E;
            s2v[rq][gb] = t2 * LOG2E;
        }
    }
    if (tig == 0) {
#pragma unroll
        for (int rq = 0; rq < 2; rq++)
#pragma unroll
            for (int gb = 0; gb < 2; gb++) {
                const int n = (m0 + rq * 8) * 8 + cb0 + gb;
                g_wh1s[bh * Nv + n] = s1v[rq][gb];
                g_wh2s[bh * Nv + n] = s2v[rq][gb];
            }
    }
    {   // per-head wh2 max
        float mx = fmaxf(fmaxf(s2v[0][0], s2v[0][1]), fmaxf(s2v[1][0], s2v[1][1]));
#pragma unroll
        for (int o = 16; o > 0; o >>= 1) mx = fmaxf(mx, __shfl_xor_sync(0xFFFFFFFFu, mx, o));
        if (lane == 0) atomicMax(&g_w2maxU[bh], fkey(mx));
    }
}

// ---------------------------------------------------------------------------
// K2: compress adj to bitmask via ballot
// ---------------------------------------------------------------------------
__global__ __launch_bounds__(256) void adjbits_kernel(const int* __restrict__ adj) {
    unsigned idx = blockIdx.x * 256u + threadIdx.x;
    unsigned mask = __ballot_sync(0xFFFFFFFFu, adj[idx] > 0);
    if ((threadIdx.x & 31) == 0) g_adjbits[idx >> 5] = mask;
}

// ---------------------------------------------------------------------------
// K3: fused scores (h2 packed, MUFU-free) + HMMA PV + ones-MMA l + ELU.
// Double-buffered smem (1 sync per j-tile, LDG overlapped with compute).
// grid (16 itiles, 8 h, 4 b), 256 threads. Warp w owns 16 i-rows.
// ---------------------------------------------------------------------------
#define ONESH2 0x3C003C00u

__global__ __launch_bounds__(256) void attn_kernel(float* __restrict__ out) {
    __shared__ uint32_t sRowE[128];                         // h2 {E1, E2} per i-row
    __shared__ __align__(4) __half sF1[2][128];             // 2^(W2-wmax)
    __shared__ __align__(4) __half sF2[2][128];             // 2^(0.2*(W2-wmax))
    __shared__ uint4  sBits[2][128];
    __shared__ __align__(16) uint32_t sVt[2][32 * 68];      // V^T f16 [d][j], stride 68 u32

    const int tid  = threadIdx.x;
    const int w    = tid >> 5, lane = tid & 31;
    const int tig  = lane & 3, grp = lane >> 2;
    const int iT = blockIdx.x, hh = blockIdx.y, b = blockIdx.z;
    const int bh = b * Hh + hh;
    const int iBase = iT * 128;
    const int il0 = w * 16 + grp, il1 = il0 + 8;

    const float wmax = fkeyinv(g_w2maxU[bh]);
    if (tid < 128) {
        float C = g_wh1s[bh * Nv + iBase + tid];
        float s = C + wmax;
        float M = fmaxf(s, SLOPE * s);
        sRowE[tid] = packh2(ex2f(s - M), ex2f(SLOPE * s - M));
    }

    const unsigned* bitsBase = g_adjbits + (size_t)(b * 2048 + iBase) * 64;
    const float* wh2Base = g_wh2s + (size_t)bh * 2048;
    const uint4* vBase = reinterpret_cast<const uint4*>(g_Vh16 + (size_t)bh * 16 * 4096);
    const int s0 = tig * 2, tig2 = tig * 2;
    const int vi0 = (tid >> 4) * 17 + (tid & 15);
    const int vi1 = ((tid + 256) >> 4) * 17 + (tid & 15);

    // prefetch tile 0 into buffer 0
    {
        uint4 va = vBase[tid], vb = vBase[256 + tid];
        uint4* dst = reinterpret_cast<uint4*>(sVt[0]);
        dst[vi0] = va; dst[vi1] = vb;
        if (tid < 128) {
            float w2 = wh2Base[tid] - wmax;
            sF1[0][tid] = __float2half(ex2f(w2));
            sF2[0][tid] = __float2half(ex2f(SLOPE * w2));
            sBits[0][tid] = *reinterpret_cast<const uint4*>(bitsBase + (size_t)tid * 64);
        }
    }
    __syncthreads();

    const uint32_t e0 = sRowE[il0], e1 = sRowE[il1];
    const uint32_t E0lo = prmtu(e0, e0, 0x1010u), E0hi = prmtu(e0, e0, 0x3232u);
    const uint32_t E1lo = prmtu(e1, e1, 0x1010u), E1hi = prmtu(e1, e1, 0x3232u);

    float dacc[4][4];
#pragma unroll
    for (int nb = 0; nb < 4; nb++)
#pragma unroll
        for (int q = 0; q < 4; q++) dacc[nb][q] = 0.f;
    float lacc[4] = {0.f, 0.f, 0.f, 0.f};

    int buf = 0;
    for (int jt = 0; jt < 16; jt++) {
        // issue next tile's global loads (overlap with compute below)
        const int nj = (jt + 1) & 15;
        uint4 va = vBase[nj * 512 + tid];
        uint4 vb = vBase[nj * 512 + 256 + tid];
        float w2n = 0.f; uint4 bqn = make_uint4(0, 0, 0, 0);
        if (tid < 128) {
            w2n = wh2Base[nj * 128 + tid] - wmax;
            bqn = *reinterpret_cast<const uint4*>(bitsBase + (size_t)tid * 64 + nj * 4);
        }

        // ---- compute on current buffer ----
        const uint4 bq0 = sBits[buf][il0];
        const uint4 bq1 = sBits[buf][il1];
        const unsigned* bw0w = reinterpret_cast<const unsigned*>(&bq0);
        const unsigned* bw1w = reinterpret_cast<const unsigned*>(&bq1);
        const __half* F1p = sF1[buf];
        const __half* F2p = sF2[buf];
        const uint32_t* vtp = sVt[buf];

#pragma unroll
        for (int k2 = 0; k2 < 4; k2++) {
            const unsigned u0 = bw0w[k2] >> s0;
            const unsigned u1 = bw1w[k2] >> s0;
            const unsigned v07 = u0 << 7, v06 = u0 << 6;
            const unsigned v17 = u1 << 7, v16 = u1 << 6;
#pragma unroll
            for (int kh = 0; kh < 2; kh++) {
                const int jb = (k2 * 2 + kh) * 16 + tig2;
                const uint32_t F1a = *reinterpret_cast<const uint32_t*>(F1p + jb);
                const uint32_t F1b = *reinterpret_cast<const uint32_t*>(F1p + jb + 8);
                const uint32_t F2a = *reinterpret_cast<const uint32_t*>(F2p + jb);
                const uint32_t F2b = *reinterpret_cast<const uint32_t*>(F2p + jb + 8);
                const uint32_t cA = kh ? 0xEEAAu : 0xCC88u;
                const uint32_t cB = kh ? 0xFFBBu : 0xDD99u;

                uint32_t A0 = hmax2u(hmul2u(E0lo, F1a), hmul2u(E0hi, F2a)) & prmtu(v07, v06, cA);
                uint32_t A2 = hmax2u(hmul2u(E0lo, F1b), hmul2u(E0hi, F2b)) & prmtu(v07, v06, cB);
                uint32_t A1 = hmax2u(hmul2u(E1lo, F1a), hmul2u(E1hi, F2a)) & prmtu(v17, v16, cA);
                uint32_t A3 = hmax2u(hmul2u(E1lo, F1b), hmul2u(E1hi, F2b)) & prmtu(v17, v16, cB);

                const uint32_t* vcol = vtp + (jb >> 1);
#pragma unroll
                for (int nb = 0; nb < 4; nb++) {
                    int drow = nb * 8 + grp;
                    uint32_t B0 = vcol[drow * 68];
                    uint32_t B1 = vcol[drow * 68 + 4];
                    mma16816(dacc[nb], A0, A1, A2, A3, B0, B1);
                }
                mma16816(lacc, A0, A1, A2, A3, ONESH2, ONESH2);
            }
        }

        // ---- stage next tile into the other buffer ----
        {
            uint4* dst = reinterpret_cast<uint4*>(sVt[buf ^ 1]);
            dst[vi0] = va; dst[vi1] = vb;
            if (tid < 128) {
                sF1[buf ^ 1][tid] = __float2half(ex2f(w2n));
                sF2[buf ^ 1][tid] = __float2half(ex2f(SLOPE * w2n));
                sBits[buf ^ 1][tid] = bqn;
            }
        }
        __syncthreads();
        buf ^= 1;
    }

    const float rl0 = 1.f / lacc[0];
    const float rl1 = 1.f / lacc[2];

    const size_t o0 = ((size_t)bh * Nv + iBase + il0) * NHv + tig * 2;
    const size_t o1 = ((size_t)bh * Nv + iBase + il1) * NHv + tig * 2;
#pragma unroll
    for (int nb = 0; nb < 4; nb++) {
        float x0 = dacc[nb][0] * rl0, x1 = dacc[nb][1] * rl0;
        float y0 = dacc[nb][2] * rl1, y1 = dacc[nb][3] * rl1;
        x0 = (x0 > 0.f) ? x0 : expm1f(x0);
        x1 = (x1 > 0.f) ? x1 : expm1f(x1);
        y0 = (y0 > 0.f) ? y0 : expm1f(y0);
        y1 = (y1 > 0.f) ? y1 : expm1f(y1);
        *reinterpret_cast<float2*>(&out[o0 + nb * 8]) = make_float2(x0, x1);
        *reinterpret_cast<float2*>(&out[o1 + nb * 8]) = make_float2(y0, y1);
    }
}

// ---------------------------------------------------------------------------
extern "C" void kernel_launch(void* const* d_in, const int* in_sizes, int n_in,
                              void* d_out, int out_size) {
    const float* h   = (const float*)d_in[0];   // [4,2048,256]
    const int*   adj = (const int*)  d_in[1];   // [4,2048,2048]
    const float* W   = (const float*)d_in[2];   // [256,256]
    const float* a   = (const float*)d_in[3];   // [64,1]
    float* out = (float*)d_out;                 // [4,2048,256]

    gemm3x_kernel<<<dim3(64, 4), 256>>>(h, W, a);
    adjbits_kernel<<<65536, 256>>>(adj);
    attn_kernel<<<dim3(16, 8, 4), 256>>>(out);
}

// round 8
// speedup vs baseline: 4.9250x; 1.0353x over previous
#include <cuda_runtime.h>
#include <cuda_fp16.h>
#include <cstdint>

// Problem constants
#define Bv     4
#define Nv     2048
#define INF_   256
#define OUTF_  256
#define Hh     8
#define NHv    32
#define SLOPE  0.2f
#define LOG2E  1.4426950408889634f

// ---------------------------------------------------------------------------
// Device scratch (no allocations; zero-initialized at load)
// ---------------------------------------------------------------------------
__device__ float    g_wh1s [Bv * Hh * Nv];              // wh1 * log2e   [bh][n]
__device__ float    g_wh2s [Bv * Hh * Nv];              // wh2 * log2e   [bh][n]
__device__ unsigned g_w2maxU[Bv * Hh];                  // ordered-uint max of wh2s (atomicMax)
__device__ unsigned g_adjbits[Bv * Nv * (Nv / 32)];     // 2 MB adj bitmask
__device__ __align__(16) __half g_Vh16[32 * 16 * 4096]; // 4 MB V tiles f16, [bh][jt][d 32][j 128]
__device__ __align__(16) uint32_t g_Ah[Bv * Nv * INF_]; // 8 MB A hi (tf32 bits)
__device__ __align__(16) uint32_t g_Al[Bv * Nv * INF_]; // 8 MB A lo (tf32 bits)
__device__ __align__(16) uint32_t g_Wth[INF_ * OUTF_];  // W hi
__device__ __align__(16) uint32_t g_Wtl[INF_ * OUTF_];  // W lo

// ---------------------------------------------------------------------------
// helpers
// ---------------------------------------------------------------------------
__device__ __forceinline__ float ex2f(float x) {
    float y; asm("ex2.approx.ftz.f32 %0, %1;" : "=f"(y) : "f"(x)); return y;
}
__device__ __forceinline__ uint32_t packh2(float a, float b) {
    __half2 h = __floats2half2_rn(a, b);
    return *reinterpret_cast<uint32_t*>(&h);
}
__device__ __forceinline__ uint32_t hmul2u(uint32_t a, uint32_t b) {
    uint32_t d; asm("mul.f16x2 %0, %1, %2;" : "=r"(d) : "r"(a), "r"(b)); return d;
}
__device__ __forceinline__ uint32_t hmax2u(uint32_t a, uint32_t b) {
    uint32_t d; asm("max.f16x2 %0, %1, %2;" : "=r"(d) : "r"(a), "r"(b)); return d;
}
__device__ __forceinline__ uint32_t hadd2u(uint32_t a, uint32_t b) {
    uint32_t d; asm("add.f16x2 %0, %1, %2;" : "=r"(d) : "r"(a), "r"(b)); return d;
}
__device__ __forceinline__ uint32_t prmtu(uint32_t a, uint32_t b, uint32_t c) {
    uint32_t d; asm("prmt.b32 %0, %1, %2, %3;" : "=r"(d) : "r"(a), "r"(b), "r"(c)); return d;
}
__device__ __forceinline__ uint32_t fkey(float f) {      // monotone float->uint
    uint32_t u = __float_as_uint(f);
    return u ^ (uint32_t)(((int)u >> 31) | 0x80000000);
}
__device__ __forceinline__ float fkeyinv(uint32_t k) {
    return __uint_as_float(k ^ (((int)k >> 31) ? 0x80000000u : 0xFFFFFFFFu));
}
__device__ __forceinline__ uint32_t f2tf32(float f) {
    uint32_t r; asm("cvt.rna.tf32.f32 %0, %1;" : "=r"(r) : "f"(f)); return r;
}
__device__ __forceinline__ void mma16816(float* d, uint32_t a0, uint32_t a1, uint32_t a2,
                                         uint32_t a3, uint32_t b0, uint32_t b1) {
    asm volatile(
        "mma.sync.aligned.m16n8k16.row.col.f32.f16.f16.f32 "
        "{%0,%1,%2,%3}, {%4,%5,%6,%7}, {%8,%9}, {%0,%1,%2,%3};"
        : "+f"(d[0]), "+f"(d[1]), "+f"(d[2]), "+f"(d[3])
        : "r"(a0), "r"(a1), "r"(a2), "r"(a3), "r"(b0), "r"(b1));
}
__device__ __forceinline__ void mma_tf32(float* d, uint32_t a0, uint32_t a1, uint32_t a2,
                                         uint32_t a3, uint32_t b0, uint32_t b1) {
    asm volatile(
        "mma.sync.aligned.m16n8k8.row.col.f32.tf32.tf32.f32 "
        "{%0,%1,%2,%3}, {%4,%5,%6,%7}, {%8,%9}, {%0,%1,%2,%3};"
        : "+f"(d[0]), "+f"(d[1]), "+f"(d[2]), "+f"(d[3])
        : "r"(a0), "r"(a1), "r"(a2), "r"(a3), "r"(b0), "r"(b1));
}

// ---------------------------------------------------------------------------
// K0: pre-split A and W into tf32 hi/lo (hi = rna(x), lo = rna(x - hi))
// grid 2112 x 256: first 524288 float4 = A, next 16384 float4 = W
// ---------------------------------------------------------------------------
__global__ __launch_bounds__(256) void presplit_kernel(const float4* __restrict__ A4,
                                                       const float4* __restrict__ W4) {
    int idx = blockIdx.x * 256 + threadIdx.x;
    float4 v;
    uint4* dh;
    uint4* dl;
    if (idx < 524288) {
        v = A4[idx];
        dh = reinterpret_cast<uint4*>(g_Ah) + idx;
        dl = reinterpret_cast<uint4*>(g_Al) + idx;
    } else {
        int j = idx - 524288;
        if (j >= 16384) return;
        v = W4[j];
        dh = reinterpret_cast<uint4*>(g_Wth) + j;
        dl = reinterpret_cast<uint4*>(g_Wtl) + j;
    }
    uint4 hi, lo;
    hi.x = f2tf32(v.x); lo.x = f2tf32(v.x - __uint_as_float(hi.x));
    hi.y = f2tf32(v.y); lo.y = f2tf32(v.y - __uint_as_float(hi.y));
    hi.z = f2tf32(v.z); lo.z = f2tf32(v.z - __uint_as_float(hi.z));
    hi.w = f2tf32(v.w); lo.w = f2tf32(v.w - __uint_as_float(hi.w));
    *dh = hi; *dl = lo;
}

// ---------------------------------------------------------------------------
// K1: 3x-tf32 GEMM (64x64 tile, grid (128,4)=512 blocks) + adj->bits prologue
// + fused epilogue honoring the raw .view (head = row>>8 in batch,
//   node n' = (row&255)*8 + col>>5, d = col&31).
// ---------------------------------------------------------------------------
__global__ __launch_bounds__(256) void gemm3x_kernel(const int* __restrict__ adj,
                                                     const float* __restrict__ a_vec) {
    __shared__ uint32_t sAh[64][20], sAl[64][20];   // [m][k] stride 20: conflict-free
    __shared__ uint32_t sBh[16][72], sBl[16][72];   // [k][n] stride 72: conflict-free
    __shared__ float sa[64];

    const int tid = threadIdx.x;
    const int w = tid >> 5, lane = tid & 31;
    const int g = lane >> 2, tig = lane & 3;
    const int wr = w & 3, wc = w >> 2;
    const int mBase = blockIdx.x * 64, nBase = blockIdx.y * 64;
    if (tid < 64) sa[tid] = a_vec[tid];

    // ---- adj -> bitmask prologue (DRAM time overlaps other blocks' MMA) ----
    {
        const int bid = blockIdx.y * 128 + blockIdx.x;   // 0..511
        const size_t ibase = (size_t)bid * 32768;
#pragma unroll 4
        for (int r = 0; r < 128; r++) {
            size_t gi = ibase + (size_t)r * 256 + tid;
            unsigned m = __ballot_sync(0xFFFFFFFFu, adj[gi] > 0);
            if (lane == 0) g_adjbits[gi >> 5] = m;
        }
    }

    float c[4][4];
#pragma unroll
    for (int nb = 0; nb < 4; nb++)
#pragma unroll
        for (int q = 0; q < 4; q++) c[nb][q] = 0.f;

    const int rA = tid >> 2, kqA = (tid & 3) * 4;     // A tile: 64x16 u32 -> 256 uint4
    const int kkB = tid >> 4, n4B = (tid & 15) * 4;   // B tile: 16x64 u32 -> 256 uint4
    const int rw = wr * 16, cw = wc * 32;

    for (int k0 = 0; k0 < INF_; k0 += 16) {
        __syncthreads();
        *reinterpret_cast<uint4*>(&sAh[rA][kqA]) =
            *reinterpret_cast<const uint4*>(&g_Ah[(size_t)(mBase + rA) * INF_ + k0 + kqA]);
        *reinterpret_cast<uint4*>(&sAl[rA][kqA]) =
            *reinterpret_cast<const uint4*>(&g_Al[(size_t)(mBase + rA) * INF_ + k0 + kqA]);
        *reinterpret_cast<uint4*>(&sBh[kkB][n4B]) =
            *reinterpret_cast<const uint4*>(&g_Wth[(size_t)(k0 + kkB) * OUTF_ + nBase + n4B]);
        *reinterpret_cast<uint4*>(&sBl[kkB][n4B]) =
            *reinterpret_cast<const uint4*>(&g_Wtl[(size_t)(k0 + kkB) * OUTF_ + nBase + n4B]);
        __syncthreads();

#pragma unroll
        for (int kc = 0; kc < 2; kc++) {
            const int k8 = kc * 8;
            uint32_t ah0 = sAh[rw + g][k8 + tig],     ah1 = sAh[rw + g + 8][k8 + tig];
            uint32_t ah2 = sAh[rw + g][k8 + tig + 4], ah3 = sAh[rw + g + 8][k8 + tig + 4];
            uint32_t al0 = sAl[rw + g][k8 + tig],     al1 = sAl[rw + g + 8][k8 + tig];
            uint32_t al2 = sAl[rw + g][k8 + tig + 4], al3 = sAl[rw + g + 8][k8 + tig + 4];
#pragma unroll
            for (int nb = 0; nb < 4; nb++) {
                const int cn = cw + nb * 8 + g;
                uint32_t bh0 = sBh[k8 + tig][cn];
                uint32_t bh1 = sBh[k8 + tig + 4][cn];
                uint32_t bl0 = sBl[k8 + tig][cn];
                uint32_t bl1 = sBl[k8 + tig + 4][cn];
                mma_tf32(c[nb], al0, al1, al2, al3, bh0, bh1);
                mma_tf32(c[nb], ah0, ah1, ah2, ah3, bl0, bl1);
                mma_tf32(c[nb], ah0, ah1, ah2, ah3, bh0, bh1);
            }
        }
    }

    // ---- fused epilogue (raw .view mapping) ----
    const int b    = mBase >> 11;
    const int hloc = (mBase & 2047) >> 8;
    const int bh   = b * Hh + hloc;
    const int r255 = mBase & 255;
    const int cb   = (nBase >> 5) + wc;          // node sub-index 0..7
    const int m0   = r255 + wr * 16 + g;

    float mx = -1e30f;
#pragma unroll
    for (int rq = 0; rq < 2; rq++) {
        const int jn = (m0 + rq * 8) * 8 + cb;
        __half* vt = &g_Vh16[((size_t)(bh * 16 + (jn >> 7))) * 4096 + (jn & 127)];
        float t1 = 0.f, t2 = 0.f;
#pragma unroll
        for (int nb = 0; nb < 4; nb++) {
            const int d0 = nb * 8 + tig * 2;
            float cx = c[nb][rq * 2], cy = c[nb][rq * 2 + 1];
            vt[(size_t)d0 * 128]       = __float2half(cx);
            vt[(size_t)(d0 + 1) * 128] = __float2half(cy);
            t1 += cx * sa[d0]      + cy * sa[d0 + 1];
            t2 += cx * sa[32 + d0] + cy * sa[32 + d0 + 1];
        }
        t1 += __shfl_xor_sync(0xFFFFFFFFu, t1, 1);
        t1 += __shfl_xor_sync(0xFFFFFFFFu, t1, 2);
        t2 += __shfl_xor_sync(0xFFFFFFFFu, t2, 1);
        t2 += __shfl_xor_sync(0xFFFFFFFFu, t2, 2);
        t1 *= LOG2E; t2 *= LOG2E;
        if (tig == 0) {
            g_wh1s[bh * Nv + jn] = t1;
            g_wh2s[bh * Nv + jn] = t2;
        }
        mx = fmaxf(mx, t2);
    }
#pragma unroll
    for (int o = 16; o > 0; o >>= 1) mx = fmaxf(mx, __shfl_xor_sync(0xFFFFFFFFu, mx, o));
    if (lane == 0) atomicMax(&g_w2maxU[bh], fkey(mx));
}

// ---------------------------------------------------------------------------
// K2: fused scores (h2, MUFU-free) + HMMA PV + grouped ones-MMA l + ELU.
// grid (32 itiles, 8 h, 4 b), 128 threads (4 warps). Warp w owns 16 i-rows.
// Double-buffered smem, 1 sync/tile.
// ---------------------------------------------------------------------------
#define ONESH2 0x3C003C00u

__global__ __launch_bounds__(128) void attn_kernel(float* __restrict__ out) {
    __shared__ uint32_t sRowE[64];                          // h2 {E1, E2} per i-row
    __shared__ __align__(4) __half sF1[2][128];             // 2^(W2-wmax)
    __shared__ __align__(4) __half sF2[2][128];             // 2^(0.2*(W2-wmax))
    __shared__ uint4  sBits[2][64];
    __shared__ __align__(16) uint32_t sVt[2][32 * 68];      // V^T f16 [d][j], stride 68 u32

    const int tid  = threadIdx.x;
    const int w    = tid >> 5, lane = tid & 31;
    const int tig  = lane & 3, grp = lane >> 2;
    const int iT = blockIdx.x, hh = blockIdx.y, b = blockIdx.z;
    const int bh = b * Hh + hh;
    const int iBase = iT * 64;
    const int il0 = w * 16 + grp, il1 = il0 + 8;

    const float wmax = fkeyinv(g_w2maxU[bh]);
    if (tid < 64) {
        float C = g_wh1s[bh * Nv + iBase + tid];
        float s = C + wmax;
        float M = fmaxf(s, SLOPE * s);
        sRowE[tid] = packh2(ex2f(s - M), ex2f(SLOPE * s - M));
    }

    const unsigned* bitsBase = g_adjbits + (size_t)(b * 2048 + iBase) * 64;
    const float* wh2Base = g_wh2s + (size_t)bh * 2048;
    const uint4* vBase = reinterpret_cast<const uint4*>(g_Vh16 + (size_t)bh * 16 * 4096);
    const int s0 = tig * 2, tig2 = tig * 2;
    int vi[4];
#pragma unroll
    for (int k = 0; k < 4; k++) {
        int q = tid + k * 128;
        vi[k] = (q >> 4) * 17 + (q & 15);
    }

    // prefetch tile 0 into buffer 0
    {
        uint4* dst = reinterpret_cast<uint4*>(sVt[0]);
#pragma unroll
        for (int k = 0; k < 4; k++) dst[vi[k]] = vBase[tid + k * 128];
        float w2 = wh2Base[tid] - wmax;
        sF1[0][tid] = __float2half(ex2f(w2));
        sF2[0][tid] = __float2half(ex2f(SLOPE * w2));
        if (tid < 64)
            sBits[0][tid] = *reinterpret_cast<const uint4*>(bitsBase + (size_t)tid * 64);
    }
    __syncthreads();

    const uint32_t e0 = sRowE[il0], e1 = sRowE[il1];
    const uint32_t E0lo = prmtu(e0, e0, 0x1010u), E0hi = prmtu(e0, e0, 0x3232u);
    const uint32_t E1lo = prmtu(e1, e1, 0x1010u), E1hi = prmtu(e1, e1, 0x3232u);

    float dacc[4][4];
#pragma unroll
    for (int nb = 0; nb < 4; nb++)
#pragma unroll
        for (int q = 0; q < 4; q++) dacc[nb][q] = 0.f;
    float lacc[4] = {0.f, 0.f, 0.f, 0.f};

    int buf = 0;
    for (int jt = 0; jt < 16; jt++) {
        // issue next tile's global loads (overlap with compute below)
        const int nj = (jt + 1) & 15;
        uint4 va[4];
#pragma unroll
        for (int k = 0; k < 4; k++) va[k] = vBase[nj * 512 + tid + k * 128];
        float w2n = wh2Base[nj * 128 + tid] - wmax;
        uint4 bqn = make_uint4(0, 0, 0, 0);
        if (tid < 64)
            bqn = *reinterpret_cast<const uint4*>(bitsBase + (size_t)tid * 64 + nj * 4);

        // ---- compute on current buffer ----
        const uint4 bq0 = sBits[buf][il0];
        const uint4 bq1 = sBits[buf][il1];
        const unsigned* bw0w = reinterpret_cast<const unsigned*>(&bq0);
        const unsigned* bw1w = reinterpret_cast<const unsigned*>(&bq1);
        const __half* F1p = sF1[buf];
        const __half* F2p = sF2[buf];
        const uint32_t* vtp = sVt[buf];
        uint32_t S0 = 0, S1 = 0, S2 = 0, S3 = 0;

#pragma unroll
        for (int k2 = 0; k2 < 4; k2++) {
            const unsigned u0 = bw0w[k2] >> s0;
            const unsigned u1 = bw1w[k2] >> s0;
            const unsigned v07 = u0 << 7, v06 = u0 << 6;
            const unsigned v17 = u1 << 7, v16 = u1 << 6;
#pragma unroll
            for (int kh = 0; kh < 2; kh++) {
                const int ks = k2 * 2 + kh;
                const int jb = ks * 16 + tig2;
                const uint32_t F1a = *reinterpret_cast<const uint32_t*>(F1p + jb);
                const uint32_t F1b = *reinterpret_cast<const uint32_t*>(F1p + jb + 8);
                const uint32_t F2a = *reinterpret_cast<const uint32_t*>(F2p + jb);
                const uint32_t F2b = *reinterpret_cast<const uint32_t*>(F2p + jb + 8);
                const uint32_t cA = kh ? 0xEEAAu : 0xCC88u;
                const uint32_t cB = kh ? 0xFFBBu : 0xDD99u;

                uint32_t A0 = hmax2u(hmul2u(E0lo, F1a), hmul2u(E0hi, F2a)) & prmtu(v07, v06, cA);
                uint32_t A2 = hmax2u(hmul2u(E0lo, F1b), hmul2u(E0hi, F2b)) & prmtu(v07, v06, cB);
                uint32_t A1 = hmax2u(hmul2u(E1lo, F1a), hmul2u(E1hi, F2a)) & prmtu(v17, v16, cA);
                uint32_t A3 = hmax2u(hmul2u(E1lo, F1b), hmul2u(E1hi, F2b)) & prmtu(v17, v16, cB);

                // grouped l accumulation: f16 pre-sums over 4 k-steps, 1 ones-MMA per group
                if ((ks & 3) == 0) { S0 = A0; S1 = A1; S2 = A2; S3 = A3; }
                else {
                    S0 = hadd2u(S0, A0); S1 = hadd2u(S1, A1);
                    S2 = hadd2u(S2, A2); S3 = hadd2u(S3, A3);
                }

                const uint32_t* vcol = vtp + (jb >> 1);
#pragma unroll
                for (int nb = 0; nb < 4; nb++) {
                    int drow = nb * 8 + grp;
                    uint32_t B0 = vcol[drow * 68];
                    uint32_t B1 = vcol[drow * 68 + 4];
                    mma16816(dacc[nb], A0, A1, A2, A3, B0, B1);
                }
                if ((ks & 3) == 3) mma16816(lacc, S0, S1, S2, S3, ONESH2, ONESH2);
            }
        }

        // ---- stage next tile into the other buffer ----
        {
            uint4* dst = reinterpret_cast<uint4*>(sVt[buf ^ 1]);
#pragma unroll
            for (int k = 0; k < 4; k++) dst[vi[k]] = va[k];
            sF1[buf ^ 1][tid] = __float2half(ex2f(w2n));
            sF2[buf ^ 1][tid] = __float2half(ex2f(SLOPE * w2n));
            if (tid < 64) sBits[buf ^ 1][tid] = bqn;
        }
        __syncthreads();
        buf ^= 1;
    }

    const float rl0 = 1.f / lacc[0];
    const float rl1 = 1.f / lacc[2];

    const size_t o0 = ((size_t)bh * Nv + iBase + il0) * NHv + tig * 2;
    const size_t o1 = ((size_t)bh * Nv + iBase + il1) * NHv + tig * 2;
#pragma unroll
    for (int nb = 0; nb < 4; nb++) {
        float x0 = dacc[nb][0] * rl0, x1 = dacc[nb][1] * rl0;
        float y0 = dacc[nb][2] * rl1, y1 = dacc[nb][3] * rl1;
        x0 = (x0 > 0.f) ? x0 : expm1f(x0);
        x1 = (x1 > 0.f) ? x1 : expm1f(x1);
        y0 = (y0 > 0.f) ? y0 : expm1f(y0);
        y1 = (y1 > 0.f) ? y1 : expm1f(y1);
        *reinterpret_cast<float2*>(&out[o0 + nb * 8]) = make_float2(x0, x1);
        *reinterpret_cast<float2*>(&out[o1 + nb * 8]) = make_float2(y0, y1);
    }
}

// ---------------------------------------------------------------------------
extern "C" void kernel_launch(void* const* d_in, const int* in_sizes, int n_in,
                              void* d_out, int out_size) {
    const float* h   = (const float*)d_in[0];   // [4,2048,256]
    const int*   adj = (const int*)  d_in[1];   // [4,2048,2048]
    const float* W   = (const float*)d_in[2];   // [256,256]
    const float* a   = (const float*)d_in[3];   // [64,1]
    float* out = (float*)d_out;                 // [4,2048,256]

    presplit_kernel<<<2112, 256>>>((const float4*)h, (const float4*)W);
    gemm3x_kernel<<<dim3(128, 4), 256>>>(adj, a);
    attn_kernel<<<dim3(32, 8, 4), 128>>>(out);
}

// round 9
// speedup vs baseline: 4.9831x; 1.0118x over previous
#include <cuda_runtime.h>
#include <cuda_fp16.h>
#include <cstdint>

// Problem constants
#define Bv     4
#define Nv     2048
#define INF_   256
#define OUTF_  256
#define Hh     8
#define NHv    32
#define SLOPE  0.2f
#define LOG2E  1.4426950408889634f

// ---------------------------------------------------------------------------
// Device scratch (no allocations; zero-initialized at load)
// ---------------------------------------------------------------------------
__device__ float    g_wh1s [Bv * Hh * Nv];              // wh1 * log2e   [bh][n]
__device__ float    g_wh2s [Bv * Hh * Nv];              // wh2 * log2e   [bh][n]
__device__ unsigned g_w2maxU[Bv * Hh];                  // ordered-uint max of wh2s (atomicMax)
__device__ unsigned g_adjbits[Bv * Nv * (Nv / 32)];     // 2 MB adj bitmask
__device__ __align__(16) __half g_Vh16[32 * 16 * 4096]; // 4 MB V tiles f16, [bh][jt][d 32][j 128]
__device__ __align__(16) uint32_t g_Ah[Bv * Nv * INF_]; // 8 MB A hi (tf32 bits)
__device__ __align__(16) uint32_t g_Al[Bv * Nv * INF_]; // 8 MB A lo (tf32 bits)
__device__ __align__(16) uint32_t g_Wth[INF_ * OUTF_];  // W hi
__device__ __align__(16) uint32_t g_Wtl[INF_ * OUTF_];  // W lo

// ---------------------------------------------------------------------------
// helpers
// ---------------------------------------------------------------------------
__device__ __forceinline__ float ex2f(float x) {
    float y; asm("ex2.approx.ftz.f32 %0, %1;" : "=f"(y) : "f"(x)); return y;
}
__device__ __forceinline__ uint32_t packh2(float a, float b) {
    __half2 h = __floats2half2_rn(a, b);
    return *reinterpret_cast<uint32_t*>(&h);
}
__device__ __forceinline__ uint32_t hmul2u(uint32_t a, uint32_t b) {
    uint32_t d; asm("mul.f16x2 %0, %1, %2;" : "=r"(d) : "r"(a), "r"(b)); return d;
}
__device__ __forceinline__ uint32_t hmax2u(uint32_t a, uint32_t b) {
    uint32_t d; asm("max.f16x2 %0, %1, %2;" : "=r"(d) : "r"(a), "r"(b)); return d;
}
__device__ __forceinline__ uint32_t hadd2u(uint32_t a, uint32_t b) {
    uint32_t d; asm("add.f16x2 %0, %1, %2;" : "=r"(d) : "r"(a), "r"(b)); return d;
}
__device__ __forceinline__ uint32_t prmtu(uint32_t a, uint32_t b, uint32_t c) {
    uint32_t d; asm("prmt.b32 %0, %1, %2, %3;" : "=r"(d) : "r"(a), "r"(b), "r"(c)); return d;
}
__device__ __forceinline__ uint32_t fkey(float f) {      // monotone float->uint
    uint32_t u = __float_as_uint(f);
    return u ^ (uint32_t)(((int)u >> 31) | 0x80000000);
}
__device__ __forceinline__ float fkeyinv(uint32_t k) {
    return __uint_as_float(k ^ (((int)k >> 31) ? 0x80000000u : 0xFFFFFFFFu));
}
__device__ __forceinline__ uint32_t f2tf32(float f) {
    uint32_t r; asm("cvt.rna.tf32.f32 %0, %1;" : "=r"(r) : "f"(f)); return r;
}
__device__ __forceinline__ void mma16816(float* d, uint32_t a0, uint32_t a1, uint32_t a2,
                                         uint32_t a3, uint32_t b0, uint32_t b1) {
    asm volatile(
        "mma.sync.aligned.m16n8k16.row.col.f32.f16.f16.f32 "
        "{%0,%1,%2,%3}, {%4,%5,%6,%7}, {%8,%9}, {%0,%1,%2,%3};"
        : "+f"(d[0]), "+f"(d[1]), "+f"(d[2]), "+f"(d[3])
        : "r"(a0), "r"(a1), "r"(a2), "r"(a3), "r"(b0), "r"(b1));
}
__device__ __forceinline__ void mma_tf32(float* d, uint32_t a0, uint32_t a1, uint32_t a2,
                                         uint32_t a3, uint32_t b0, uint32_t b1) {
    asm volatile(
        "mma.sync.aligned.m16n8k8.row.col.f32.tf32.tf32.f32 "
        "{%0,%1,%2,%3}, {%4,%5,%6,%7}, {%8,%9}, {%0,%1,%2,%3};"
        : "+f"(d[0]), "+f"(d[1]), "+f"(d[2]), "+f"(d[3])
        : "r"(a0), "r"(a1), "r"(a2), "r"(a3), "r"(b0), "r"(b1));
}

// ---------------------------------------------------------------------------
// K0: pre-split A and W into tf32 hi/lo (hi = rna(x), lo = rna(x - hi))
// ---------------------------------------------------------------------------
__global__ __launch_bounds__(256) void presplit_kernel(const float4* __restrict__ A4,
                                                       const float4* __restrict__ W4) {
    int idx = blockIdx.x * 256 + threadIdx.x;
    float4 v;
    uint4* dh;
    uint4* dl;
    if (idx < 524288) {
        v = A4[idx];
        dh = reinterpret_cast<uint4*>(g_Ah) + idx;
        dl = reinterpret_cast<uint4*>(g_Al) + idx;
    } else {
        int j = idx - 524288;
        if (j >= 16384) return;
        v = W4[j];
        dh = reinterpret_cast<uint4*>(g_Wth) + j;
        dl = reinterpret_cast<uint4*>(g_Wtl) + j;
    }
    uint4 hi, lo;
    hi.x = f2tf32(v.x); lo.x = f2tf32(v.x - __uint_as_float(hi.x));
    hi.y = f2tf32(v.y); lo.y = f2tf32(v.y - __uint_as_float(hi.y));
    hi.z = f2tf32(v.z); lo.z = f2tf32(v.z - __uint_as_float(hi.z));
    hi.w = f2tf32(v.w); lo.w = f2tf32(v.w - __uint_as_float(hi.w));
    *dh = hi; *dl = lo;
}

// ---------------------------------------------------------------------------
// K_adj: adj -> bitmask, int4 loads (1 LDG.128/thread), nibble pack + shfl-OR
// grid 16384 x 256 (covers 16.78M ints)
// ---------------------------------------------------------------------------
__global__ __launch_bounds__(256) void adjbits_kernel(const int4* __restrict__ adj4) {
    unsigned idx = blockIdx.x * 256u + threadIdx.x;
    int4 v = adj4[idx];
    unsigned nib = (unsigned)(v.x > 0) | ((unsigned)(v.y > 0) << 1)
                 | ((unsigned)(v.z > 0) << 2) | ((unsigned)(v.w > 0) << 3);
    unsigned word = nib << ((threadIdx.x & 7) * 4);
    word |= __shfl_xor_sync(0xFFFFFFFFu, word, 1);
    word |= __shfl_xor_sync(0xFFFFFFFFu, word, 2);
    word |= __shfl_xor_sync(0xFFFFFFFFu, word, 4);
    if ((threadIdx.x & 7) == 0) g_adjbits[idx >> 3] = word;
}

// ---------------------------------------------------------------------------
// K1: 3x-tf32 GEMM (64x64 tile, grid (128,4)=512 blocks) + fused epilogue
// honoring the raw .view (head = row>>8 in batch, node n' = (row&255)*8 +
// col>>5, d = col&31).
// ---------------------------------------------------------------------------
__global__ __launch_bounds__(256) void gemm3x_kernel(const float* __restrict__ a_vec) {
    __shared__ uint32_t sAh[64][20], sAl[64][20];   // [m][k] stride 20: conflict-free
    __shared__ uint32_t sBh[16][72], sBl[16][72];   // [k][n] stride 72: conflict-free
    __shared__ float sa[64];

    const int tid = threadIdx.x;
    const int w = tid >> 5, lane = tid & 31;
    const int g = lane >> 2, tig = lane & 3;
    const int wr = w & 3, wc = w >> 2;
    const int mBase = blockIdx.x * 64, nBase = blockIdx.y * 64;
    if (tid < 64) sa[tid] = a_vec[tid];

    float c[4][4];
#pragma unroll
    for (int nb = 0; nb < 4; nb++)
#pragma unroll
        for (int q = 0; q < 4; q++) c[nb][q] = 0.f;

    const int rA = tid >> 2, kqA = (tid & 3) * 4;     // A tile: 64x16 u32 -> 256 uint4
    const int kkB = tid >> 4, n4B = (tid & 15) * 4;   // B tile: 16x64 u32 -> 256 uint4
    const int rw = wr * 16, cw = wc * 32;

    for (int k0 = 0; k0 < INF_; k0 += 16) {
        __syncthreads();
        *reinterpret_cast<uint4*>(&sAh[rA][kqA]) =
            *reinterpret_cast<const uint4*>(&g_Ah[(size_t)(mBase + rA) * INF_ + k0 + kqA]);
        *reinterpret_cast<uint4*>(&sAl[rA][kqA]) =
            *reinterpret_cast<const uint4*>(&g_Al[(size_t)(mBase + rA) * INF_ + k0 + kqA]);
        *reinterpret_cast<uint4*>(&sBh[kkB][n4B]) =
            *reinterpret_cast<const uint4*>(&g_Wth[(size_t)(k0 + kkB) * OUTF_ + nBase + n4B]);
        *reinterpret_cast<uint4*>(&sBl[kkB][n4B]) =
            *reinterpret_cast<const uint4*>(&g_Wtl[(size_t)(k0 + kkB) * OUTF_ + nBase + n4B]);
        __syncthreads();

#pragma unroll
        for (int kc = 0; kc < 2; kc++) {
            const int k8 = kc * 8;
            uint32_t ah0 = sAh[rw + g][k8 + tig],     ah1 = sAh[rw + g + 8][k8 + tig];
            uint32_t ah2 = sAh[rw + g][k8 + tig + 4], ah3 = sAh[rw + g + 8][k8 + tig + 4];
            uint32_t al0 = sAl[rw + g][k8 + tig],     al1 = sAl[rw + g + 8][k8 + tig];
            uint32_t al2 = sAl[rw + g][k8 + tig + 4], al3 = sAl[rw + g + 8][k8 + tig + 4];
#pragma unroll
            for (int nb = 0; nb < 4; nb++) {
                const int cn = cw + nb * 8 + g;
                uint32_t bh0 = sBh[k8 + tig][cn];
                uint32_t bh1 = sBh[k8 + tig + 4][cn];
                uint32_t bl0 = sBl[k8 + tig][cn];
                uint32_t bl1 = sBl[k8 + tig + 4][cn];
                mma_tf32(c[nb], al0, al1, al2, al3, bh0, bh1);
                mma_tf32(c[nb], ah0, ah1, ah2, ah3, bl0, bl1);
                mma_tf32(c[nb], ah0, ah1, ah2, ah3, bh0, bh1);
            }
        }
    }

    // ---- fused epilogue (raw .view mapping) ----
    const int b    = mBase >> 11;
    const int hloc = (mBase & 2047) >> 8;
    const int bh   = b * Hh + hloc;
    const int r255 = mBase & 255;
    const int cb   = (nBase >> 5) + wc;          // node sub-index 0..7
    const int m0   = r255 + wr * 16 + g;

    float mx = -1e30f;
#pragma unroll
    for (int rq = 0; rq < 2; rq++) {
        const int jn = (m0 + rq * 8) * 8 + cb;
        __half* vt = &g_Vh16[((size_t)(bh * 16 + (jn >> 7))) * 4096 + (jn & 127)];
        float t1 = 0.f, t2 = 0.f;
#pragma unroll
        for (int nb = 0; nb < 4; nb++) {
            const int d0 = nb * 8 + tig * 2;
            float cx = c[nb][rq * 2], cy = c[nb][rq * 2 + 1];
            vt[(size_t)d0 * 128]       = __float2half(cx);
            vt[(size_t)(d0 + 1) * 128] = __float2half(cy);
            t1 += cx * sa[d0]      + cy * sa[d0 + 1];
            t2 += cx * sa[32 + d0] + cy * sa[32 + d0 + 1];
        }
        t1 += __shfl_xor_sync(0xFFFFFFFFu, t1, 1);
        t1 += __shfl_xor_sync(0xFFFFFFFFu, t1, 2);
        t2 += __shfl_xor_sync(0xFFFFFFFFu, t2, 1);
        t2 += __shfl_xor_sync(0xFFFFFFFFu, t2, 2);
        t1 *= LOG2E; t2 *= LOG2E;
        if (tig == 0) {
            g_wh1s[bh * Nv + jn] = t1;
            g_wh2s[bh * Nv + jn] = t2;
        }
        mx = fmaxf(mx, t2);
    }
#pragma unroll
    for (int o = 16; o > 0; o >>= 1) mx = fmaxf(mx, __shfl_xor_sync(0xFFFFFFFFu, mx, o));
    if (lane == 0) atomicMax(&g_w2maxU[bh], fkey(mx));
}

// ---------------------------------------------------------------------------
// K2: fused scores (h2, MUFU-free) + HMMA PV + register-path l + ELU.
// grid (32 itiles, 8 h, 4 b), 128 threads (4 warps). Warp w owns 16 i-rows.
// Double-buffered smem, 1 sync/tile. No ones-MMA: l via HADD2 chunk sums.
// ---------------------------------------------------------------------------
__global__ __launch_bounds__(128) void attn_kernel(float* __restrict__ out) {
    __shared__ uint32_t sRowE[64];                          // h2 {E1, E2} per i-row
    __shared__ __align__(4) __half sF1[2][128];             // 2^(W2-wmax)
    __shared__ __align__(4) __half sF2[2][128];             // 2^(0.2*(W2-wmax))
    __shared__ uint4  sBits[2][64];
    __shared__ __align__(16) uint32_t sVt[2][32 * 68];      // V^T f16 [d][j], stride 68 u32

    const int tid  = threadIdx.x;
    const int w    = tid >> 5, lane = tid & 31;
    const int tig  = lane & 3, grp = lane >> 2;
    const int iT = blockIdx.x, hh = blockIdx.y, b = blockIdx.z;
    const int bh = b * Hh + hh;
    const int iBase = iT * 64;
    const int il0 = w * 16 + grp, il1 = il0 + 8;

    const float wmax = fkeyinv(g_w2maxU[bh]);
    if (tid < 64) {
        float C = g_wh1s[bh * Nv + iBase + tid];
        float s = C + wmax;
        float M = fmaxf(s, SLOPE * s);
        sRowE[tid] = packh2(ex2f(s - M), ex2f(SLOPE * s - M));
    }

    const unsigned* bitsBase = g_adjbits + (size_t)(b * 2048 + iBase) * 64;
    const float* wh2Base = g_wh2s + (size_t)bh * 2048;
    const uint4* vBase = reinterpret_cast<const uint4*>(g_Vh16 + (size_t)bh * 16 * 4096);
    const int s0 = tig * 2, tig2 = tig * 2;
    int vi[4];
#pragma unroll
    for (int k = 0; k < 4; k++) {
        int q = tid + k * 128;
        vi[k] = (q >> 4) * 17 + (q & 15);
    }

    // prefetch tile 0 into buffer 0
    {
        uint4* dst = reinterpret_cast<uint4*>(sVt[0]);
#pragma unroll
        for (int k = 0; k < 4; k++) dst[vi[k]] = vBase[tid + k * 128];
        float w2 = wh2Base[tid] - wmax;
        sF1[0][tid] = __float2half(ex2f(w2));
        sF2[0][tid] = __float2half(ex2f(SLOPE * w2));
        if (tid < 64)
            sBits[0][tid] = *reinterpret_cast<const uint4*>(bitsBase + (size_t)tid * 64);
    }
    __syncthreads();

    const uint32_t e0 = sRowE[il0], e1 = sRowE[il1];
    const uint32_t E0lo = prmtu(e0, e0, 0x1010u), E0hi = prmtu(e0, e0, 0x3232u);
    const uint32_t E1lo = prmtu(e1, e1, 0x1010u), E1hi = prmtu(e1, e1, 0x3232u);

    float dacc[4][4];
#pragma unroll
    for (int nb = 0; nb < 4; nb++)
#pragma unroll
        for (int q = 0; q < 4; q++) dacc[nb][q] = 0.f;
    float lsum0 = 0.f, lsum1 = 0.f;

    int buf = 0;
    for (int jt = 0; jt < 16; jt++) {
        // issue next tile's global loads (overlap with compute below)
        const int nj = (jt + 1) & 15;
        uint4 va[4];
#pragma unroll
        for (int k = 0; k < 4; k++) va[k] = vBase[nj * 512 + tid + k * 128];
        float w2n = wh2Base[nj * 128 + tid] - wmax;
        uint4 bqn = make_uint4(0, 0, 0, 0);
        if (tid < 64)
            bqn = *reinterpret_cast<const uint4*>(bitsBase + (size_t)tid * 64 + nj * 4);

        // ---- compute on current buffer ----
        const uint4 bq0 = sBits[buf][il0];
        const uint4 bq1 = sBits[buf][il1];
        const unsigned* bw0w = reinterpret_cast<const unsigned*>(&bq0);
        const unsigned* bw1w = reinterpret_cast<const unsigned*>(&bq1);
        const __half* F1p = sF1[buf];
        const __half* F2p = sF2[buf];
        const uint32_t* vtp = sVt[buf];
        uint32_t S0 = 0, S1 = 0, S2 = 0, S3 = 0;

#pragma unroll
        for (int k2 = 0; k2 < 4; k2++) {
            const unsigned u0 = bw0w[k2] >> s0;
            const unsigned u1 = bw1w[k2] >> s0;
            const unsigned v07 = u0 << 7, v06 = u0 << 6;
            const unsigned v17 = u1 << 7, v16 = u1 << 6;
#pragma unroll
            for (int kh = 0; kh < 2; kh++) {
                const int ks = k2 * 2 + kh;
                const int jb = ks * 16 + tig2;
                const uint32_t F1a = *reinterpret_cast<const uint32_t*>(F1p + jb);
                const uint32_t F1b = *reinterpret_cast<const uint32_t*>(F1p + jb + 8);
                const uint32_t F2a = *reinterpret_cast<const uint32_t*>(F2p + jb);
                const uint32_t F2b = *reinterpret_cast<const uint32_t*>(F2p + jb + 8);
                const uint32_t cA = kh ? 0xEEAAu : 0xCC88u;
                const uint32_t cB = kh ? 0xFFBBu : 0xDD99u;

                uint32_t A0 = hmax2u(hmul2u(E0lo, F1a), hmul2u(E0hi, F2a)) & prmtu(v07, v06, cA);
                uint32_t A2 = hmax2u(hmul2u(E0lo, F1b), hmul2u(E0hi, F2b)) & prmtu(v07, v06, cB);
                uint32_t A1 = hmax2u(hmul2u(E1lo, F1a), hmul2u(E1hi, F2a)) & prmtu(v17, v16, cA);
                uint32_t A3 = hmax2u(hmul2u(E1lo, F1b), hmul2u(E1hi, F2b)) & prmtu(v17, v16, cB);

                // l via f16 chunk sums (each half accumulates 8 p's <= 8)
                if (ks == 0) { S0 = A0; S1 = A1; S2 = A2; S3 = A3; }
                else {
                    S0 = hadd2u(S0, A0); S1 = hadd2u(S1, A1);
                    S2 = hadd2u(S2, A2); S3 = hadd2u(S3, A3);
                }

                const uint32_t* vcol = vtp + (jb >> 1);
#pragma unroll
                for (int nb = 0; nb < 4; nb++) {
                    int drow = nb * 8 + grp;
                    uint32_t B0 = vcol[drow * 68];
                    uint32_t B1 = vcol[drow * 68 + 4];
                    mma16816(dacc[nb], A0, A1, A2, A3, B0, B1);
                }
            }
        }
        {   // fold chunk sums into fp32 l accumulators
            float2 t;
            t = __half22float2(*reinterpret_cast<__half2*>(&S0)); lsum0 += t.x + t.y;
            t = __half22float2(*reinterpret_cast<__half2*>(&S2)); lsum0 += t.x + t.y;
            t = __half22float2(*reinterpret_cast<__half2*>(&S1)); lsum1 += t.x + t.y;
            t = __half22float2(*reinterpret_cast<__half2*>(&S3)); lsum1 += t.x + t.y;
        }

        // ---- stage next tile into the other buffer ----
        {
            uint4* dst = reinterpret_cast<uint4*>(sVt[buf ^ 1]);
#pragma unroll
            for (int k = 0; k < 4; k++) dst[vi[k]] = va[k];
            sF1[buf ^ 1][tid] = __float2half(ex2f(w2n));
            sF2[buf ^ 1][tid] = __float2half(ex2f(SLOPE * w2n));
            if (tid < 64) sBits[buf ^ 1][tid] = bqn;
        }
        __syncthreads();
        buf ^= 1;
    }

    // reduce l across the 4 lanes sharing each row
    lsum0 += __shfl_xor_sync(0xFFFFFFFFu, lsum0, 1);
    lsum0 += __shfl_xor_sync(0xFFFFFFFFu, lsum0, 2);
    lsum1 += __shfl_xor_sync(0xFFFFFFFFu, lsum1, 1);
    lsum1 += __shfl_xor_sync(0xFFFFFFFFu, lsum1, 2);
    const float rl0 = 1.f / lsum0;
    const float rl1 = 1.f / lsum1;

    const size_t o0 = ((size_t)bh * Nv + iBase + il0) * NHv + tig * 2;
    const size_t o1 = ((size_t)bh * Nv + iBase + il1) * NHv + tig * 2;
#pragma unroll
    for (int nb = 0; nb < 4; nb++) {
        float x0 = dacc[nb][0] * rl0, x1 = dacc[nb][1] * rl0;
        float y0 = dacc[nb][2] * rl1, y1 = dacc[nb][3] * rl1;
        x0 = (x0 > 0.f) ? x0 : expm1f(x0);
        x1 = (x1 > 0.f) ? x1 : expm1f(x1);
        y0 = (y0 > 0.f) ? y0 : expm1f(y0);
        y1 = (y1 > 0.f) ? y1 : expm1f(y1);
        *reinterpret_cast<float2*>(&out[o0 + nb * 8]) = make_float2(x0, x1);
        *reinterpret_cast<float2*>(&out[o1 + nb * 8]) = make_float2(y0, y1);
    }
}

// ---------------------------------------------------------------------------
extern "C" void kernel_launch(void* const* d_in, const int* in_sizes, int n_in,
                              void* d_out, int out_size) {
    const float* h   = (const float*)d_in[0];   // [4,2048,256]
    const int*   adj = (const int*)  d_in[1];   // [4,2048,2048]
    const float* W   = (const float*)d_in[2];   // [256,256]
    const float* a   = (const float*)d_in[3];   // [64,1]
    float* out = (float*)d_out;                 // [4,2048,256]

    // one-time side-stream + events (created on first, non-captured call)
    static cudaStream_t s2 = nullptr;
    static cudaEvent_t evFork = nullptr, evJoin = nullptr;
    if (s2 == nullptr) {
        cudaStreamCreateWithFlags(&s2, cudaStreamNonBlocking);
        cudaEventCreateWithFlags(&evFork, cudaEventDisableTiming);
        cudaEventCreateWithFlags(&evJoin, cudaEventDisableTiming);
    }

    // fork: adjbits (DRAM-bound) concurrent with presplit+gemm (tensor-bound)
    cudaEventRecord(evFork, 0);
    cudaStreamWaitEvent(s2, evFork, 0);
    adjbits_kernel<<<16384, 256, 0, s2>>>((const int4*)adj);
    cudaEventRecord(evJoin, s2);

    presplit_kernel<<<2112, 256>>>((const float4*)h, (const float4*)W);
    gemm3x_kernel<<<dim3(128, 4), 256>>>(a);

    // join: attn needs both branches
    cudaStreamWaitEvent(0, evJoin, 0);
    attn_kernel<<<dim3(32, 8, 4), 128>>>(out);
}

// round 10
// speedup vs baseline: 5.1903x; 1.0416x over previous
#include <cuda_runtime.h>
#include <cuda_fp16.h>
#include <cstdint>

// Problem constants
#define Bv     4
#define Nv     2048
#define INF_   256
#define OUTF_  256
#define Hh     8
#define NHv    32
#define SLOPE  0.2f
#define LOG2E  1.4426950408889634f

// ---------------------------------------------------------------------------
// Device scratch (no allocations; zero-initialized at load)
// ---------------------------------------------------------------------------
__device__ float    g_wh1s [Bv * Hh * Nv];              // wh1 * log2e   [bh][n]
__device__ float    g_wh2s [Bv * Hh * Nv];              // wh2 * log2e   [bh][n]
__device__ unsigned g_w2maxU[Bv * Hh];                  // ordered-uint max of wh2s (atomicMax)
__device__ unsigned g_adjbits[Bv * Nv * (Nv / 32)];     // 2 MB adj bitmask
__device__ __align__(16) __half g_Vh16[32 * 16 * 4096]; // 4 MB V tiles f16, [bh][jt][d 32][j 128]
__device__ __align__(16) uint32_t g_Wth[INF_ * OUTF_];  // W in tf32 bits
__device__ __align__(16) float    g_U[INF_ * 16];       // U = W @ a_blocks, [k][c(8)=a1 | 8+c=a2]

// ---------------------------------------------------------------------------
// helpers
// ---------------------------------------------------------------------------
__device__ __forceinline__ float ex2f(float x) {
    float y; asm("ex2.approx.ftz.f32 %0, %1;" : "=f"(y) : "f"(x)); return y;
}
__device__ __forceinline__ uint32_t packh2(float a, float b) {
    __half2 h = __floats2half2_rn(a, b);
    return *reinterpret_cast<uint32_t*>(&h);
}
__device__ __forceinline__ uint32_t hmul2u(uint32_t a, uint32_t b) {
    uint32_t d; asm("mul.f16x2 %0, %1, %2;" : "=r"(d) : "r"(a), "r"(b)); return d;
}
__device__ __forceinline__ uint32_t hmax2u(uint32_t a, uint32_t b) {
    uint32_t d; asm("max.f16x2 %0, %1, %2;" : "=r"(d) : "r"(a), "r"(b)); return d;
}
__device__ __forceinline__ uint32_t hadd2u(uint32_t a, uint32_t b) {
    uint32_t d; asm("add.f16x2 %0, %1, %2;" : "=r"(d) : "r"(a), "r"(b)); return d;
}
__device__ __forceinline__ uint32_t prmtu(uint32_t a, uint32_t b, uint32_t c) {
    uint32_t d; asm("prmt.b32 %0, %1, %2, %3;" : "=r"(d) : "r"(a), "r"(b), "r"(c)); return d;
}
__device__ __forceinline__ uint32_t fkey(float f) {      // monotone float->uint
    uint32_t u = __float_as_uint(f);
    return u ^ (uint32_t)(((int)u >> 31) | 0x80000000);
}
__device__ __forceinline__ float fkeyinv(uint32_t k) {
    return __uint_as_float(k ^ (((int)k >> 31) ? 0x80000000u : 0xFFFFFFFFu));
}
__device__ __forceinline__ uint32_t f2tf32(float f) {
    uint32_t r; asm("cvt.rna.tf32.f32 %0, %1;" : "=r"(r) : "f"(f)); return r;
}
__device__ __forceinline__ void mma16816(float* d, uint32_t a0, uint32_t a1, uint32_t a2,
                                         uint32_t a3, uint32_t b0, uint32_t b1) {
    asm volatile(
        "mma.sync.aligned.m16n8k16.row.col.f32.f16.f16.f32 "
        "{%0,%1,%2,%3}, {%4,%5,%6,%7}, {%8,%9}, {%0,%1,%2,%3};"
        : "+f"(d[0]), "+f"(d[1]), "+f"(d[2]), "+f"(d[3])
        : "r"(a0), "r"(a1), "r"(a2), "r"(a3), "r"(b0), "r"(b1));
}
__device__ __forceinline__ void mma_tf32(float* d, uint32_t a0, uint32_t a1, uint32_t a2,
                                         uint32_t a3, uint32_t b0, uint32_t b1) {
    asm volatile(
        "mma.sync.aligned.m16n8k8.row.col.f32.tf32.tf32.f32 "
        "{%0,%1,%2,%3}, {%4,%5,%6,%7}, {%8,%9}, {%0,%1,%2,%3};"
        : "+f"(d[0]), "+f"(d[1]), "+f"(d[2]), "+f"(d[3])
        : "r"(a0), "r"(a1), "r"(a2), "r"(a3), "r"(b0), "r"(b1));
}

// ---------------------------------------------------------------------------
// K_u: blocks 0-7: U[k][c] = sum_d W[k, c*32+d]*a[d] (c<8) / a[32+d] (c>=8)
//      blocks 8-15: convert W to tf32 bits (g_Wth)
// ---------------------------------------------------------------------------
__global__ __launch_bounds__(256) void u_kernel(const float4* __restrict__ W4,
                                                const float* __restrict__ a_vec) {
    __shared__ float sW[32][260];
    __shared__ float sa[64];
    const int bb = blockIdx.x, t = threadIdx.x;
    if (bb < 8) {
        if (t < 64) sa[t] = a_vec[t];
#pragma unroll
        for (int i = 0; i < 8; i++) {
            int idx4 = t + i * 256;                  // 2048 float4 = rows bb*32..+31
            int row = idx4 >> 6, col = (idx4 & 63) * 4;
            float4 v = W4[(size_t)(bb * 32) * 64 + idx4];
            *reinterpret_cast<float4*>(&sW[row][col]) = v;
        }
        __syncthreads();
        const int k_loc = t >> 3, c8 = t & 7;
        float u1 = 0.f, u2 = 0.f;
#pragma unroll
        for (int d = 0; d < 32; d++) {
            float wv = sW[k_loc][c8 * 32 + d];
            u1 += wv * sa[d];
            u2 += wv * sa[32 + d];
        }
        g_U[(bb * 32 + k_loc) * 16 + c8]     = u1;
        g_U[(bb * 32 + k_loc) * 16 + 8 + c8] = u2;
    } else {
        const int base = (bb - 8) * 2048 + t * 8;
        uint4* dst = reinterpret_cast<uint4*>(g_Wth);
#pragma unroll
        for (int i = 0; i < 8; i++) {
            float4 v = W4[base + i];
            uint4 u;
            u.x = f2tf32(v.x); u.y = f2tf32(v.y);
            u.z = f2tf32(v.z); u.w = f2tf32(v.w);
            dst[base + i] = u;
        }
    }
}

// ---------------------------------------------------------------------------
// K_wh12: exact fp32 wh1/wh2 = h @ U with raw-view mapping; per-head wh2 max.
// grid 512 x 256; block handles 16 GEMM rows (all one (b,h)).
// thread t: row = t>>4, out = t&15 (out<8 -> wh1 col out, else wh2 col out-8)
// ---------------------------------------------------------------------------
__global__ __launch_bounds__(256) void wh12_kernel(const float4* __restrict__ h4) {
    __shared__ float sH[16][260];
    __shared__ float sU[256][16];
    __shared__ float sred[8];
    const int t = threadIdx.x;
    const int r0 = blockIdx.x * 16;
#pragma unroll
    for (int i = 0; i < 4; i++) {
        int idx4 = t + i * 256;                      // 1024 float4 = 16 rows x 256
        int row = idx4 >> 6, col = (idx4 & 63) * 4;
        float4 v = h4[(size_t)r0 * 64 + idx4];
        *reinterpret_cast<float4*>(&sH[row][col]) = v;
    }
#pragma unroll
    for (int i = 0; i < 4; i++) {
        int idx4 = t + i * 256;                      // 1024 float4 = 4096 U floats
        *reinterpret_cast<float4*>(&sU[0][0] + idx4 * 4) =
            *reinterpret_cast<const float4*>(g_U + idx4 * 4);
    }
    __syncthreads();

    const int row = t >> 4, out = t & 15;
    const float4* hrow = reinterpret_cast<const float4*>(&sH[row][0]);
    float acc = 0.f;
#pragma unroll 8
    for (int k4 = 0; k4 < 64; k4++) {
        float4 hv = hrow[k4];
        acc += hv.x * sU[k4 * 4 + 0][out];
        acc += hv.y * sU[k4 * 4 + 1][out];
        acc += hv.z * sU[k4 * 4 + 2][out];
        acc += hv.w * sU[k4 * 4 + 3][out];
    }
    acc *= LOG2E;

    const int r = r0 + row;
    const int b = r >> 11, hloc = (r & 2047) >> 8, bh = b * Hh + hloc;
    const int np = (r & 255) * 8 + (out & 7);
    if (out < 8) g_wh1s[bh * Nv + np] = acc;
    else         g_wh2s[bh * Nv + np] = acc;

    // per-head wh2 max (block covers exactly one (b,h))
    float mx = (out >= 8) ? acc : -1e30f;
#pragma unroll
    for (int o = 16; o > 0; o >>= 1) mx = fmaxf(mx, __shfl_xor_sync(0xFFFFFFFFu, mx, o));
    if ((t & 31) == 0) sred[t >> 5] = mx;
    __syncthreads();
    if (t == 0) {
        float m = sred[0];
#pragma unroll
        for (int q = 1; q < 8; q++) m = fmaxf(m, sred[q]);
        atomicMax(&g_w2maxU[bh], fkey(m));
    }
}

// ---------------------------------------------------------------------------
// K_adj: adj -> bitmask, int4 loads, nibble pack + shfl-OR. grid 16384 x 256.
// ---------------------------------------------------------------------------
__global__ __launch_bounds__(256) void adjbits_kernel(const int4* __restrict__ adj4) {
    unsigned idx = blockIdx.x * 256u + threadIdx.x;
    int4 v = adj4[idx];
    unsigned nib = (unsigned)(v.x > 0) | ((unsigned)(v.y > 0) << 1)
                 | ((unsigned)(v.z > 0) << 2) | ((unsigned)(v.w > 0) << 3);
    unsigned word = nib << ((threadIdx.x & 7) * 4);
    word |= __shfl_xor_sync(0xFFFFFFFFu, word, 1);
    word |= __shfl_xor_sync(0xFFFFFFFFu, word, 2);
    word |= __shfl_xor_sync(0xFFFFFFFFu, word, 4);
    if ((threadIdx.x & 7) == 0) g_adjbits[idx >> 3] = word;
}

// ---------------------------------------------------------------------------
// K1: single-pass tf32 GEMM (64x64 tile, grid (128,4)) emitting only V f16
// tiles via the raw .view (head = row>>8 in batch, n' = (row&255)*8 + col>>5,
// d = col&31). A converted in-loop; W pre-converted (g_Wth).
// ---------------------------------------------------------------------------
__global__ __launch_bounds__(256) void gemm_tf32_kernel(const float4* __restrict__ A4) {
    __shared__ uint32_t sAh[64][20];   // [m][k] stride 20: conflict-free
    __shared__ uint32_t sBh[16][72];   // [k][n] stride 72: conflict-free

    const int tid = threadIdx.x;
    const int w = tid >> 5, lane = tid & 31;
    const int g = lane >> 2, tig = lane & 3;
    const int wr = w & 3, wc = w >> 2;
    const int mBase = blockIdx.x * 64, nBase = blockIdx.y * 64;

    float c[4][4];
#pragma unroll
    for (int nb = 0; nb < 4; nb++)
#pragma unroll
        for (int q = 0; q < 4; q++) c[nb][q] = 0.f;

    const int rA = tid >> 2, kqA = (tid & 3) * 4;
    const int kkB = tid >> 4, n4B = (tid & 15) * 4;
    const int rw = wr * 16, cw = wc * 32;

    for (int k0 = 0; k0 < INF_; k0 += 16) {
        __syncthreads();
        {
            float4 v = A4[(size_t)(mBase + rA) * 64 + ((k0 + kqA) >> 2)];
            sAh[rA][kqA + 0] = f2tf32(v.x);
            sAh[rA][kqA + 1] = f2tf32(v.y);
            sAh[rA][kqA + 2] = f2tf32(v.z);
            sAh[rA][kqA + 3] = f2tf32(v.w);
        }
        *reinterpret_cast<uint4*>(&sBh[kkB][n4B]) =
            *reinterpret_cast<const uint4*>(&g_Wth[(size_t)(k0 + kkB) * OUTF_ + nBase + n4B]);
        __syncthreads();

#pragma unroll
        for (int kc = 0; kc < 2; kc++) {
            const int k8 = kc * 8;
            uint32_t a0 = sAh[rw + g][k8 + tig],     a1 = sAh[rw + g + 8][k8 + tig];
            uint32_t a2 = sAh[rw + g][k8 + tig + 4], a3 = sAh[rw + g + 8][k8 + tig + 4];
#pragma unroll
            for (int nb = 0; nb < 4; nb++) {
                const int cn = cw + nb * 8 + g;
                mma_tf32(c[nb], a0, a1, a2, a3, sBh[k8 + tig][cn], sBh[k8 + tig + 4][cn]);
            }
        }
    }

    // ---- V f16 epilogue (raw .view mapping) ----
    const int b    = mBase >> 11;
    const int hloc = (mBase & 2047) >> 8;
    const int bh   = b * Hh + hloc;
    const int r255 = mBase & 255;
    const int cb   = (nBase >> 5) + wc;
    const int m0   = r255 + wr * 16 + g;

#pragma unroll
    for (int rq = 0; rq < 2; rq++) {
        const int jn = (m0 + rq * 8) * 8 + cb;
        __half* vt = &g_Vh16[((size_t)(bh * 16 + (jn >> 7))) * 4096 + (jn & 127)];
#pragma unroll
        for (int nb = 0; nb < 4; nb++) {
            const int d0 = nb * 8 + tig * 2;
            vt[(size_t)d0 * 128]       = __float2half(c[nb][rq * 2]);
            vt[(size_t)(d0 + 1) * 128] = __float2half(c[nb][rq * 2 + 1]);
        }
    }
}

// ---------------------------------------------------------------------------
// K2: fused scores (h2, MUFU-free) + HMMA PV + register-path l + ELU.
// grid (32 itiles, 8 h, 4 b), 128 threads. Double-buffered, 1 sync/tile.
// ---------------------------------------------------------------------------
__global__ __launch_bounds__(128) void attn_kernel(float* __restrict__ out) {
    __shared__ uint32_t sRowE[64];
    __shared__ __align__(4) __half sF1[2][128];
    __shared__ __align__(4) __half sF2[2][128];
    __shared__ uint4  sBits[2][64];
    __shared__ __align__(16) uint32_t sVt[2][32 * 68];

    const int tid  = threadIdx.x;
    const int w    = tid >> 5, lane = tid & 31;
    const int tig  = lane & 3, grp = lane >> 2;
    const int iT = blockIdx.x, hh = blockIdx.y, b = blockIdx.z;
    const int bh = b * Hh + hh;
    const int iBase = iT * 64;
    const int il0 = w * 16 + grp, il1 = il0 + 8;

    const float wmax = fkeyinv(g_w2maxU[bh]);
    if (tid < 64) {
        float C = g_wh1s[bh * Nv + iBase + tid];
        float s = C + wmax;
        float M = fmaxf(s, SLOPE * s);
        sRowE[tid] = packh2(ex2f(s - M), ex2f(SLOPE * s - M));
    }

    const unsigned* bitsBase = g_adjbits + (size_t)(b * 2048 + iBase) * 64;
    const float* wh2Base = g_wh2s + (size_t)bh * 2048;
    const uint4* vBase = reinterpret_cast<const uint4*>(g_Vh16 + (size_t)bh * 16 * 4096);
    const int s0 = tig * 2, tig2 = tig * 2;
    int vi[4];
#pragma unroll
    for (int k = 0; k < 4; k++) {
        int q = tid + k * 128;
        vi[k] = (q >> 4) * 17 + (q & 15);
    }

    {
        uint4* dst = reinterpret_cast<uint4*>(sVt[0]);
#pragma unroll
        for (int k = 0; k < 4; k++) dst[vi[k]] = vBase[tid + k * 128];
        float w2 = wh2Base[tid] - wmax;
        sF1[0][tid] = __float2half(ex2f(w2));
        sF2[0][tid] = __float2half(ex2f(SLOPE * w2));
        if (tid < 64)
            sBits[0][tid] = *reinterpret_cast<const uint4*>(bitsBase + (size_t)tid * 64);
    }
    __syncthreads();

    const uint32_t e0 = sRowE[il0], e1 = sRowE[il1];
    const uint32_t E0lo = prmtu(e0, e0, 0x1010u), E0hi = prmtu(e0, e0, 0x3232u);
    const uint32_t E1lo = prmtu(e1, e1, 0x1010u), E1hi = prmtu(e1, e1, 0x3232u);

    float dacc[4][4];
#pragma unroll
    for (int nb = 0; nb < 4; nb++)
#pragma unroll
        for (int q = 0; q < 4; q++) dacc[nb][q] = 0.f;
    float lsum0 = 0.f, lsum1 = 0.f;

    int buf = 0;
    for (int jt = 0; jt < 16; jt++) {
        const int nj = (jt + 1) & 15;
        uint4 va[4];
#pragma unroll
        for (int k = 0; k < 4; k++) va[k] = vBase[nj * 512 + tid + k * 128];
        float w2n = wh2Base[nj * 128 + tid] - wmax;
        uint4 bqn = make_uint4(0, 0, 0, 0);
        if (tid < 64)
            bqn = *reinterpret_cast<const uint4*>(bitsBase + (size_t)tid * 64 + nj * 4);

        const uint4 bq0 = sBits[buf][il0];
        const uint4 bq1 = sBits[buf][il1];
        const unsigned* bw0w = reinterpret_cast<const unsigned*>(&bq0);
        const unsigned* bw1w = reinterpret_cast<const unsigned*>(&bq1);
        const __half* F1p = sF1[buf];
        const __half* F2p = sF2[buf];
        const uint32_t* vtp = sVt[buf];
        uint32_t S0 = 0, S1 = 0, S2 = 0, S3 = 0;

#pragma unroll
        for (int k2 = 0; k2 < 4; k2++) {
            const unsigned u0 = bw0w[k2] >> s0;
            const unsigned u1 = bw1w[k2] >> s0;
            const unsigned v07 = u0 << 7, v06 = u0 << 6;
            const unsigned v17 = u1 << 7, v16 = u1 << 6;
#pragma unroll
            for (int kh = 0; kh < 2; kh++) {
                const int ks = k2 * 2 + kh;
                const int jb = ks * 16 + tig2;
                const uint32_t F1a = *reinterpret_cast<const uint32_t*>(F1p + jb);
                const uint32_t F1b = *reinterpret_cast<const uint32_t*>(F1p + jb + 8);
                const uint32_t F2a = *reinterpret_cast<const uint32_t*>(F2p + jb);
                const uint32_t F2b = *reinterpret_cast<const uint32_t*>(F2p + jb + 8);
                const uint32_t cA = kh ? 0xEEAAu : 0xCC88u;
                const uint32_t cB = kh ? 0xFFBBu : 0xDD99u;

                uint32_t A0 = hmax2u(hmul2u(E0lo, F1a), hmul2u(E0hi, F2a)) & prmtu(v07, v06, cA);
                uint32_t A2 = hmax2u(hmul2u(E0lo, F1b), hmul2u(E0hi, F2b)) & prmtu(v07, v06, cB);
                uint32_t A1 = hmax2u(hmul2u(E1lo, F1a), hmul2u(E1hi, F2a)) & prmtu(v17, v16, cA);
                uint32_t A3 = hmax2u(hmul2u(E1lo, F1b), hmul2u(E1hi, F2b)) & prmtu(v17, v16, cB);

                if (ks == 0) { S0 = A0; S1 = A1; S2 = A2; S3 = A3; }
                else {
                    S0 = hadd2u(S0, A0); S1 = hadd2u(S1, A1);
                    S2 = hadd2u(S2, A2); S3 = hadd2u(S3, A3);
                }

                const uint32_t* vcol = vtp + (jb >> 1);
#pragma unroll
                for (int nb = 0; nb < 4; nb++) {
                    int drow = nb * 8 + grp;
                    mma16816(dacc[nb], A0, A1, A2, A3, vcol[drow * 68], vcol[drow * 68 + 4]);
                }
            }
        }
        {
            float2 t;
            t = __half22float2(*reinterpret_cast<__half2*>(&S0)); lsum0 += t.x + t.y;
            t = __half22float2(*reinterpret_cast<__half2*>(&S2)); lsum0 += t.x + t.y;
            t = __half22float2(*reinterpret_cast<__half2*>(&S1)); lsum1 += t.x + t.y;
            t = __half22float2(*reinterpret_cast<__half2*>(&S3)); lsum1 += t.x + t.y;
        }

        {
            uint4* dst = reinterpret_cast<uint4*>(sVt[buf ^ 1]);
#pragma unroll
            for (int k = 0; k < 4; k++) dst[vi[k]] = va[k];
            sF1[buf ^ 1][tid] = __float2half(ex2f(w2n));
            sF2[buf ^ 1][tid] = __float2half(ex2f(SLOPE * w2n));
            if (tid < 64) sBits[buf ^ 1][tid] = bqn;
        }
        __syncthreads();
        buf ^= 1;
    }

    lsum0 += __shfl_xor_sync(0xFFFFFFFFu, lsum0, 1);
    lsum0 += __shfl_xor_sync(0xFFFFFFFFu, lsum0, 2);
    lsum1 += __shfl_xor_sync(0xFFFFFFFFu, lsum1, 1);
    lsum1 += __shfl_xor_sync(0xFFFFFFFFu, lsum1, 2);
    const float rl0 = 1.f / lsum0;
    const float rl1 = 1.f / lsum1;

    const size_t o0 = ((size_t)bh * Nv + iBase + il0) * NHv + tig * 2;
    const size_t o1 = ((size_t)bh * Nv + iBase + il1) * NHv + tig * 2;
#pragma unroll
    for (int nb = 0; nb < 4; nb++) {
        float x0 = dacc[nb][0] * rl0, x1 = dacc[nb][1] * rl0;
        float y0 = dacc[nb][2] * rl1, y1 = dacc[nb][3] * rl1;
        x0 = (x0 > 0.f) ? x0 : expm1f(x0);
        x1 = (x1 > 0.f) ? x1 : expm1f(x1);
        y0 = (y0 > 0.f) ? y0 : expm1f(y0);
        y1 = (y1 > 0.f) ? y1 : expm1f(y1);
        *reinterpret_cast<float2*>(&out[o0 + nb * 8]) = make_float2(x0, x1);
        *reinterpret_cast<float2*>(&out[o1 + nb * 8]) = make_float2(y0, y1);
    }
}

// ---------------------------------------------------------------------------
extern "C" void kernel_launch(void* const* d_in, const int* in_sizes, int n_in,
                              void* d_out, int out_size) {
    const float* h   = (const float*)d_in[0];   // [4,2048,256]
    const int*   adj = (const int*)  d_in[1];   // [4,2048,2048]
    const float* W   = (const float*)d_in[2];   // [256,256]
    const float* a   = (const float*)d_in[3];   // [64,1]
    float* out = (float*)d_out;                 // [4,2048,256]

    static cudaStream_t s2 = nullptr;
    static cudaEvent_t evFork = nullptr, evJoin = nullptr;
    if (s2 == nullptr) {
        cudaStreamCreateWithFlags(&s2, cudaStreamNonBlocking);
        cudaEventCreateWithFlags(&evFork, cudaEventDisableTiming);
        cudaEventCreateWithFlags(&evJoin, cudaEventDisableTiming);
    }

    // fork: adjbits (DRAM-bound) concurrent with U/wh12/gemm (compute-bound)
    cudaEventRecord(evFork, 0);
    cudaStreamWaitEvent(s2, evFork, 0);
    adjbits_kernel<<<16384, 256, 0, s2>>>((const int4*)adj);
    cudaEventRecord(evJoin, s2);

    u_kernel<<<16, 256>>>((const float4*)W, a);
    wh12_kernel<<<512, 256>>>((const float4*)h);
    gemm_tf32_kernel<<<dim3(128, 4), 256>>>((const float4*)h);

    cudaStreamWaitEvent(0, evJoin, 0);
    attn_kernel<<<dim3(32, 8, 4), 128>>>(out);
}

// round 12
// speedup vs baseline: 5.3291x; 1.0268x over previous
#include <cuda_runtime.h>
#include <cuda_fp16.h>
#include <cstdint>

// Problem constants
#define Bv     4
#define Nv     2048
#define INF_   256
#define OUTF_  256
#define Hh     8
#define NHv    32
#define SLOPE  0.2f
#define LOG2E  1.4426950408889634f

// ---------------------------------------------------------------------------
// Device scratch (no allocations; zero-initialized at load)
// ---------------------------------------------------------------------------
__device__ float    g_wh1s [Bv * Hh * Nv];              // wh1 * log2e   [bh][n]
__device__ float    g_wh2s [Bv * Hh * Nv];              // wh2 * log2e   [bh][n]
__device__ unsigned g_w2maxU[Bv * Hh];                  // ordered-uint max of wh2s (atomicMax)
__device__ unsigned g_adjbits[Bv * Nv * (Nv / 32)];     // 2 MB adj bitmask
__device__ __align__(16) __half g_Vh16[32 * 16 * 4096]; // 4 MB V tiles f16, [bh][jt][d 32][j 128]
__device__ __align__(16) uint32_t g_Wth[INF_ * OUTF_];  // W in tf32 bits
__device__ __align__(16) float    g_U[INF_ * 16];       // U = W @ a_blocks

// ---------------------------------------------------------------------------
// helpers
// ---------------------------------------------------------------------------
__device__ __forceinline__ float ex2f(float x) {
    float y; asm("ex2.approx.ftz.f32 %0, %1;" : "=f"(y) : "f"(x)); return y;
}
__device__ __forceinline__ uint32_t packh2(float a, float b) {
    __half2 h = __floats2half2_rn(a, b);
    return *reinterpret_cast<uint32_t*>(&h);
}
__device__ __forceinline__ uint32_t hmul2u(uint32_t a, uint32_t b) {
    uint32_t d; asm("mul.f16x2 %0, %1, %2;" : "=r"(d) : "r"(a), "r"(b)); return d;
}
__device__ __forceinline__ uint32_t hmax2u(uint32_t a, uint32_t b) {
    uint32_t d; asm("max.f16x2 %0, %1, %2;" : "=r"(d) : "r"(a), "r"(b)); return d;
}
__device__ __forceinline__ uint32_t hadd2u(uint32_t a, uint32_t b) {
    uint32_t d; asm("add.f16x2 %0, %1, %2;" : "=r"(d) : "r"(a), "r"(b)); return d;
}
__device__ __forceinline__ uint32_t prmtu(uint32_t a, uint32_t b, uint32_t c) {
    uint32_t d; asm("prmt.b32 %0, %1, %2, %3;" : "=r"(d) : "r"(a), "r"(b), "r"(c)); return d;
}
__device__ __forceinline__ uint32_t fkey(float f) {
    uint32_t u = __float_as_uint(f);
    return u ^ (uint32_t)(((int)u >> 31) | 0x80000000);
}
__device__ __forceinline__ float fkeyinv(uint32_t k) {
    return __uint_as_float(k ^ (((int)k >> 31) ? 0x80000000u : 0xFFFFFFFFu));
}
__device__ __forceinline__ uint32_t f2tf32(float f) {
    uint32_t r; asm("cvt.rna.tf32.f32 %0, %1;" : "=r"(r) : "f"(f)); return r;
}
__device__ __forceinline__ void mma16816(float* d, uint32_t a0, uint32_t a1, uint32_t a2,
                                         uint32_t a3, uint32_t b0, uint32_t b1) {
    asm volatile(
        "mma.sync.aligned.m16n8k16.row.col.f32.f16.f16.f32 "
        "{%0,%1,%2,%3}, {%4,%5,%6,%7}, {%8,%9}, {%0,%1,%2,%3};"
        : "+f"(d[0]), "+f"(d[1]), "+f"(d[2]), "+f"(d[3])
        : "r"(a0), "r"(a1), "r"(a2), "r"(a3), "r"(b0), "r"(b1));
}
__device__ __forceinline__ void mma_tf32(float* d, uint32_t a0, uint32_t a1, uint32_t a2,
                                         uint32_t a3, uint32_t b0, uint32_t b1) {
    asm volatile(
        "mma.sync.aligned.m16n8k8.row.col.f32.tf32.tf32.f32 "
        "{%0,%1,%2,%3}, {%4,%5,%6,%7}, {%8,%9}, {%0,%1,%2,%3};"
        : "+f"(d[0]), "+f"(d[1]), "+f"(d[2]), "+f"(d[3])
        : "r"(a0), "r"(a1), "r"(a2), "r"(a3), "r"(b0), "r"(b1));
}

// ---------------------------------------------------------------------------
// K_u: blocks 0-7: U[k][c] from W and a; blocks 8-15: W -> tf32 bits
// ---------------------------------------------------------------------------
__global__ __launch_bounds__(256) void u_kernel(const float4* __restrict__ W4,
                                                const float* __restrict__ a_vec) {
    __shared__ float sW[32][260];
    __shared__ float sa[64];
    const int bb = blockIdx.x, t = threadIdx.x;
    if (bb < 8) {
        if (t < 64) sa[t] = a_vec[t];
#pragma unroll
        for (int i = 0; i < 8; i++) {
            int idx4 = t + i * 256;
            int row = idx4 >> 6, col = (idx4 & 63) * 4;
            float4 v = W4[(size_t)(bb * 32) * 64 + idx4];
            *reinterpret_cast<float4*>(&sW[row][col]) = v;
        }
        __syncthreads();
        const int k_loc = t >> 3, c8 = t & 7;
        float u1 = 0.f, u2 = 0.f;
#pragma unroll
        for (int d = 0; d < 32; d++) {
            float wv = sW[k_loc][c8 * 32 + d];
            u1 += wv * sa[d];
            u2 += wv * sa[32 + d];
        }
        g_U[(bb * 32 + k_loc) * 16 + c8]     = u1;
        g_U[(bb * 32 + k_loc) * 16 + 8 + c8] = u2;
    } else {
        const int base = (bb - 8) * 2048 + t * 8;
        uint4* dst = reinterpret_cast<uint4*>(g_Wth);
#pragma unroll
        for (int i = 0; i < 8; i++) {
            float4 v = W4[base + i];
            uint4 u;
            u.x = f2tf32(v.x); u.y = f2tf32(v.y);
            u.z = f2tf32(v.z); u.w = f2tf32(v.w);
            dst[base + i] = u;
        }
    }
}

// ---------------------------------------------------------------------------
// K_wh12: exact fp32 wh1/wh2 = h @ U (raw-view mapping); per-head wh2 max.
// ---------------------------------------------------------------------------
__global__ __launch_bounds__(256) void wh12_kernel(const float4* __restrict__ h4) {
    __shared__ float sH[16][260];
    __shared__ float sU[256][16];
    __shared__ float sred[8];
    const int t = threadIdx.x;
    const int r0 = blockIdx.x * 16;
#pragma unroll
    for (int i = 0; i < 4; i++) {
        int idx4 = t + i * 256;
        int row = idx4 >> 6, col = (idx4 & 63) * 4;
        float4 v = h4[(size_t)r0 * 64 + idx4];
        *reinterpret_cast<float4*>(&sH[row][col]) = v;
    }
#pragma unroll
    for (int i = 0; i < 4; i++) {
        int idx4 = t + i * 256;
        *reinterpret_cast<float4*>(&sU[0][0] + idx4 * 4) =
            *reinterpret_cast<const float4*>(g_U + idx4 * 4);
    }
    __syncthreads();

    const int row = t >> 4, out = t & 15;
    const float4* hrow = reinterpret_cast<const float4*>(&sH[row][0]);
    float acc = 0.f;
#pragma unroll 8
    for (int k4 = 0; k4 < 64; k4++) {
        float4 hv = hrow[k4];
        acc += hv.x * sU[k4 * 4 + 0][out];
        acc += hv.y * sU[k4 * 4 + 1][out];
        acc += hv.z * sU[k4 * 4 + 2][out];
        acc += hv.w * sU[k4 * 4 + 3][out];
    }
    acc *= LOG2E;

    const int r = r0 + row;
    const int b = r >> 11, hloc = (r & 2047) >> 8, bh = b * Hh + hloc;
    const int np = (r & 255) * 8 + (out & 7);
    if (out < 8) g_wh1s[bh * Nv + np] = acc;
    else         g_wh2s[bh * Nv + np] = acc;

    float mx = (out >= 8) ? acc : -1e30f;
#pragma unroll
    for (int o = 16; o > 0; o >>= 1) mx = fmaxf(mx, __shfl_xor_sync(0xFFFFFFFFu, mx, o));
    if ((t & 31) == 0) sred[t >> 5] = mx;
    __syncthreads();
    if (t == 0) {
        float m = sred[0];
#pragma unroll
        for (int q = 1; q < 8; q++) m = fmaxf(m, sred[q]);
        atomicMax(&g_w2maxU[bh], fkey(m));
    }
}

// ---------------------------------------------------------------------------
// K_adj: adj -> bitmask, int4 loads, nibble pack + shfl-OR. grid 16384 x 256.
// ---------------------------------------------------------------------------
__global__ __launch_bounds__(256) void adjbits_kernel(const int4* __restrict__ adj4) {
    unsigned idx = blockIdx.x * 256u + threadIdx.x;
    int4 v = adj4[idx];
    unsigned nib = (unsigned)(v.x > 0) | ((unsigned)(v.y > 0) << 1)
                 | ((unsigned)(v.z > 0) << 2) | ((unsigned)(v.w > 0) << 3);
    unsigned word = nib << ((threadIdx.x & 7) * 4);
    word |= __shfl_xor_sync(0xFFFFFFFFu, word, 1);
    word |= __shfl_xor_sync(0xFFFFFFFFu, word, 2);
    word |= __shfl_xor_sync(0xFFFFFFFFu, word, 4);
    if ((threadIdx.x & 7) == 0) g_adjbits[idx >> 3] = word;
}

// ---------------------------------------------------------------------------
// K1: single-pass tf32 GEMM, double-buffered smem (1 sync per 16-k chunk,
// next chunk's LDG+cvt overlapped with MMA). Emits V f16 tiles (raw .view).
// ---------------------------------------------------------------------------
__global__ __launch_bounds__(256) void gemm_tf32_kernel(const float4* __restrict__ A4) {
    __shared__ uint32_t sAh[2][64][20];
    __shared__ uint32_t sBh[2][16][72];

    const int tid = threadIdx.x;
    const int w = tid >> 5, lane = tid & 31;
    const int g = lane >> 2, tig = lane & 3;
    const int wr = w & 3, wc = w >> 2;
    const int mBase = blockIdx.x * 64, nBase = blockIdx.y * 64;

    float c[4][4];
#pragma unroll
    for (int nb = 0; nb < 4; nb++)
#pragma unroll
        for (int q = 0; q < 4; q++) c[nb][q] = 0.f;

    const int rA = tid >> 2, kqA = (tid & 3) * 4;
    const int kkB = tid >> 4, n4B = (tid & 15) * 4;
    const int rw = wr * 16, cw = wc * 32;

    // preload chunk 0
    {
        float4 v = A4[(size_t)(mBase + rA) * 64 + (kqA >> 2)];
        sAh[0][rA][kqA + 0] = f2tf32(v.x);
        sAh[0][rA][kqA + 1] = f2tf32(v.y);
        sAh[0][rA][kqA + 2] = f2tf32(v.z);
        sAh[0][rA][kqA + 3] = f2tf32(v.w);
        *reinterpret_cast<uint4*>(&sBh[0][kkB][n4B]) =
            *reinterpret_cast<const uint4*>(&g_Wth[(size_t)kkB * OUTF_ + nBase + n4B]);
    }
    __syncthreads();

    int buf = 0;
    for (int k0 = 0; k0 < INF_; k0 += 16) {
        // issue next chunk's loads into registers
        uint32_t an[4];
        uint4 bn;
        const bool more = (k0 + 16) < INF_;
        if (more) {
            float4 v = A4[(size_t)(mBase + rA) * 64 + ((k0 + 16 + kqA) >> 2)];
            an[0] = f2tf32(v.x); an[1] = f2tf32(v.y);
            an[2] = f2tf32(v.z); an[3] = f2tf32(v.w);
            bn = *reinterpret_cast<const uint4*>(&g_Wth[(size_t)(k0 + 16 + kkB) * OUTF_ + nBase + n4B]);
        }

        // compute on current buffer
#pragma unroll
        for (int kc = 0; kc < 2; kc++) {
            const int k8 = kc * 8;
            uint32_t a0 = sAh[buf][rw + g][k8 + tig],     a1 = sAh[buf][rw + g + 8][k8 + tig];
            uint32_t a2 = sAh[buf][rw + g][k8 + tig + 4], a3 = sAh[buf][rw + g + 8][k8 + tig + 4];
#pragma unroll
            for (int nb = 0; nb < 4; nb++) {
                const int cn = cw + nb * 8 + g;
                mma_tf32(c[nb], a0, a1, a2, a3,
                         sBh[buf][k8 + tig][cn], sBh[buf][k8 + tig + 4][cn]);
            }
        }

        if (more) {
            *reinterpret_cast<uint4*>(&sAh[buf ^ 1][rA][kqA]) = *reinterpret_cast<uint4*>(an);
            *reinterpret_cast<uint4*>(&sBh[buf ^ 1][kkB][n4B]) = bn;
        }
        __syncthreads();
        buf ^= 1;
    }

    // ---- V f16 epilogue (raw .view mapping) ----
    const int b    = mBase >> 11;
    const int hloc = (mBase & 2047) >> 8;
    const int bh   = b * Hh + hloc;
    const int r255 = mBase & 255;
    const int cb   = (nBase >> 5) + wc;
    const int m0   = r255 + wr * 16 + g;

#pragma unroll
    for (int rq = 0; rq < 2; rq++) {
        const int jn = (m0 + rq * 8) * 8 + cb;
        __half* vt = &g_Vh16[((size_t)(bh * 16 + (jn >> 7))) * 4096 + (jn & 127)];
#pragma unroll
        for (int nb = 0; nb < 4; nb++) {
            const int d0 = nb * 8 + tig * 2;
            vt[(size_t)d0 * 128]       = __float2half(c[nb][rq * 2]);
            vt[(size_t)(d0 + 1) * 128] = __float2half(c[nb][rq * 2 + 1]);
        }
    }
}

// ---------------------------------------------------------------------------
// K2: fused scores (h2, MUFU-free) + HMMA PV + register-path l + ELU.
// grid (32 itiles, 8 h, 4 b), 128 threads. Double-buffered, 1 sync/tile.
// ---------------------------------------------------------------------------
__global__ __launch_bounds__(128) void attn_kernel(float* __restrict__ out) {
    __shared__ uint32_t sRowE[64];
    __shared__ __align__(4) __half sF1[2][128];
    __shared__ __align__(4) __half sF2[2][128];
    __shared__ uint4  sBits[2][64];
    __shared__ __align__(16) uint32_t sVt[2][32 * 68];

    const int tid  = threadIdx.x;
    const int w    = tid >> 5, lane = tid & 31;
    const int tig  = lane & 3, grp = lane >> 2;
    const int iT = blockIdx.x, hh = blockIdx.y, b = blockIdx.z;
    const int bh = b * Hh + hh;
    const int iBase = iT * 64;
    const int il0 = w * 16 + grp, il1 = il0 + 8;

    const float wmax = fkeyinv(g_w2maxU[bh]);
    if (tid < 64) {
        float C = g_wh1s[bh * Nv + iBase + tid];
        float s = C + wmax;
        float M = fmaxf(s, SLOPE * s);
        sRowE[tid] = packh2(ex2f(s - M), ex2f(SLOPE * s - M));
    }

    const unsigned* bitsBase = g_adjbits + (size_t)(b * 2048 + iBase) * 64;
    const float* wh2Base = g_wh2s + (size_t)bh * 2048;
    const uint4* vBase = reinterpret_cast<const uint4*>(g_Vh16 + (size_t)bh * 16 * 4096);
    const int s0 = tig * 2, tig2 = tig * 2;
    int vi[4];
#pragma unroll
    for (int k = 0; k < 4; k++) {
        int q = tid + k * 128;
        vi[k] = (q >> 4) * 17 + (q & 15);
    }

    {
        uint4* dst = reinterpret_cast<uint4*>(sVt[0]);
#pragma unroll
        for (int k = 0; k < 4; k++) dst[vi[k]] = vBase[tid + k * 128];
        float w2 = wh2Base[tid] - wmax;
        sF1[0][tid] = __float2half(ex2f(w2));
        sF2[0][tid] = __float2half(ex2f(SLOPE * w2));
        if (tid < 64)
            sBits[0][tid] = *reinterpret_cast<const uint4*>(bitsBase + (size_t)tid * 64);
    }
    __syncthreads();

    const uint32_t e0 = sRowE[il0], e1 = sRowE[il1];
    const uint32_t E0lo = prmtu(e0, e0, 0x1010u), E0hi = prmtu(e0, e0, 0x3232u);
    const uint32_t E1lo = prmtu(e1, e1, 0x1010u), E1hi = prmtu(e1, e1, 0x3232u);

    float dacc[4][4];
#pragma unroll
    for (int nb = 0; nb < 4; nb++)
#pragma unroll
        for (int q = 0; q < 4; q++) dacc[nb][q] = 0.f;
    float lsum0 = 0.f, lsum1 = 0.f;

    int buf = 0;
    for (int jt = 0; jt < 16; jt++) {
        const int nj = (jt + 1) & 15;
        uint4 va[4];
#pragma unroll
        for (int k = 0; k < 4; k++) va[k] = vBase[nj * 512 + tid + k * 128];
        float w2n = wh2Base[nj * 128 + tid] - wmax;
        uint4 bqn = make_uint4(0, 0, 0, 0);
        if (tid < 64)
            bqn = *reinterpret_cast<const uint4*>(bitsBase + (size_t)tid * 64 + nj * 4);

        const uint4 bq0 = sBits[buf][il0];
        const uint4 bq1 = sBits[buf][il1];
        const unsigned* bw0w = reinterpret_cast<const unsigned*>(&bq0);
        const unsigned* bw1w = reinterpret_cast<const unsigned*>(&bq1);
        const __half* F1p = sF1[buf];
        const __half* F2p = sF2[buf];
        const uint32_t* vtp = sVt[buf];
        uint32_t S0 = 0, S1 = 0, S2 = 0, S3 = 0;

#pragma unroll
        for (int k2 = 0; k2 < 4; k2++) {
            const unsigned u0 = bw0w[k2] >> s0;
            const unsigned u1 = bw1w[k2] >> s0;
            const unsigned v07 = u0 << 7, v06 = u0 << 6;
            const unsigned v17 = u1 << 7, v16 = u1 << 6;
#pragma unroll
            for (int kh = 0; kh < 2; kh++) {
                const int ks = k2 * 2 + kh;
                const int jb = ks * 16 + tig2;
                const uint32_t F1a = *reinterpret_cast<const uint32_t*>(F1p + jb);
                const uint32_t F1b = *reinterpret_cast<const uint32_t*>(F1p + jb + 8);
                const uint32_t F2a = *reinterpret_cast<const uint32_t*>(F2p + jb);
                const uint32_t F2b = *reinterpret_cast<const uint32_t*>(F2p + jb + 8);
                const uint32_t cA = kh ? 0xEEAAu : 0xCC88u;
                const uint32_t cB = kh ? 0xFFBBu : 0xDD99u;

                uint32_t A0 = hmax2u(hmul2u(E0lo, F1a), hmul2u(E0hi, F2a)) & prmtu(v07, v06, cA);
                uint32_t A2 = hmax2u(hmul2u(E0lo, F1b), hmul2u(E0hi, F2b)) & prmtu(v07, v06, cB);
                uint32_t A1 = hmax2u(hmul2u(E1lo, F1a), hmul2u(E1hi, F2a)) & prmtu(v17, v16, cA);
                uint32_t A3 = hmax2u(hmul2u(E1lo, F1b), hmul2u(E1hi, F2b)) & prmtu(v17, v16, cB);

                if (ks == 0) { S0 = A0; S1 = A1; S2 = A2; S3 = A3; }
                else {
                    S0 = hadd2u(S0, A0); S1 = hadd2u(S1, A1);
                    S2 = hadd2u(S2, A2); S3 = hadd2u(S3, A3);
                }

                const uint32_t* vcol = vtp + (jb >> 1);
#pragma unroll
                for (int nb = 0; nb < 4; nb++) {
                    int drow = nb * 8 + grp;
                    mma16816(dacc[nb], A0, A1, A2, A3, vcol[drow * 68], vcol[drow * 68 + 4]);
                }
            }
        }
        {
            float2 t;
            t = __half22float2(*reinterpret_cast<__half2*>(&S0)); lsum0 += t.x + t.y;
            t = __half22float2(*reinterpret_cast<__half2*>(&S2)); lsum0 += t.x + t.y;
            t = __half22float2(*reinterpret_cast<__half2*>(&S1)); lsum1 += t.x + t.y;
            t = __half22float2(*reinterpret_cast<__half2*>(&S3)); lsum1 += t.x + t.y;
        }

        {
            uint4* dst = reinterpret_cast<uint4*>(sVt[buf ^ 1]);
#pragma unroll
            for (int k = 0; k < 4; k++) dst[vi[k]] = va[k];
            sF1[buf ^ 1][tid] = __float2half(ex2f(w2n));
            sF2[buf ^ 1][tid] = __float2half(ex2f(SLOPE * w2n));
            if (tid < 64) sBits[buf ^ 1][tid] = bqn;
        }
        __syncthreads();
        buf ^= 1;
    }

    lsum0 += __shfl_xor_sync(0xFFFFFFFFu, lsum0, 1);
    lsum0 += __shfl_xor_sync(0xFFFFFFFFu, lsum0, 2);
    lsum1 += __shfl_xor_sync(0xFFFFFFFFu, lsum1, 1);
    lsum1 += __shfl_xor_sync(0xFFFFFFFFu, lsum1, 2);
    const float rl0 = 1.f / lsum0;
    const float rl1 = 1.f / lsum1;

    const size_t o0 = ((size_t)bh * Nv + iBase + il0) * NHv + tig * 2;
    const size_t o1 = ((size_t)bh * Nv + iBase + il1) * NHv + tig * 2;
#pragma unroll
    for (int nb = 0; nb < 4; nb++) {
        float x0 = dacc[nb][0] * rl0, x1 = dacc[nb][1] * rl0;
        float y0 = dacc[nb][2] * rl1, y1 = dacc[nb][3] * rl1;
        x0 = (x0 > 0.f) ? x0 : expm1f(x0);
        x1 = (x1 > 0.f) ? x1 : expm1f(x1);
        y0 = (y0 > 0.f) ? y0 : expm1f(y0);
        y1 = (y1 > 0.f) ? y1 : expm1f(y1);
        *reinterpret_cast<float2*>(&out[o0 + nb * 8]) = make_float2(x0, x1);
        *reinterpret_cast<float2*>(&out[o1 + nb * 8]) = make_float2(y0, y1);
    }
}

// ---------------------------------------------------------------------------
extern "C" void kernel_launch(void* const* d_in, const int* in_sizes, int n_in,
                              void* d_out, int out_size) {
    const float* h   = (const float*)d_in[0];   // [4,2048,256]
    const int*   adj = (const int*)  d_in[1];   // [4,2048,2048]
    const float* W   = (const float*)d_in[2];   // [256,256]
    const float* a   = (const float*)d_in[3];   // [64,1]
    float* out = (float*)d_out;                 // [4,2048,256]

    static cudaStream_t s2 = nullptr, s3 = nullptr;
    static cudaEvent_t evFork = nullptr, evU = nullptr, evJ2 = nullptr, evJ3 = nullptr;
    if (s2 == nullptr) {
        cudaStreamCreateWithFlags(&s2, cudaStreamNonBlocking);
        cudaStreamCreateWithFlags(&s3, cudaStreamNonBlocking);
        cudaEventCreateWithFlags(&evFork, cudaEventDisableTiming);
        cudaEventCreateWithFlags(&evU, cudaEventDisableTiming);
        cudaEventCreateWithFlags(&evJ2, cudaEventDisableTiming);
        cudaEventCreateWithFlags(&evJ3, cudaEventDisableTiming);
    }

    // fork adjbits immediately (DRAM-bound, no dependencies)
    cudaEventRecord(evFork, 0);
    cudaStreamWaitEvent(s2, evFork, 0);
    adjbits_kernel<<<16384, 256, 0, s2>>>((const int4*)adj);
    cudaEventRecord(evJ2, s2);

    // u first (produces g_U for wh12 AND g_Wth for gemm)
    u_kernel<<<16, 256>>>((const float4*)W, a);
    cudaEventRecord(evU, 0);

    // wh12 (fma-bound) on s3, concurrent with gemm (tensor-bound) on main
    cudaStreamWaitEvent(s3, evU, 0);
    wh12_kernel<<<512, 256, 0, s3>>>((const float4*)h);
    cudaEventRecord(evJ3, s3);

    gemm_tf32_kernel<<<dim3(128, 4), 256>>>((const float4*)h);

    // join: attn needs all branches
    cudaStreamWaitEvent(0, evJ2, 0);
    cudaStreamWaitEvent(0, evJ3, 0);
    attn_kernel<<<dim3(32, 8, 4), 128>>>(out);
}

// round 13
// speedup vs baseline: 5.6501x; 1.0602x over previous
#include <cuda_runtime.h>
#include <cuda_fp16.h>
#include <cstdint>

// Problem constants
#define Bv     4
#define Nv     2048
#define INF_   256
#define OUTF_  256
#define Hh     8
#define NHv    32
#define SLOPE  0.2f
#define LOG2E  1.4426950408889634f

// ---------------------------------------------------------------------------
// Device scratch (no allocations; zero-initialized at load)
// ---------------------------------------------------------------------------
__device__ float    g_wh1s [Bv * Hh * Nv];              // wh1 * log2e   [bh][n]
__device__ float    g_wh2s [Bv * Hh * Nv];              // wh2 * log2e   [bh][n]
__device__ unsigned g_w2maxU[Bv * Hh];                  // ordered-uint max of wh2s (atomicMax)
__device__ unsigned g_adjbits[Bv * Nv * (Nv / 32)];     // 2 MB adj bitmask
__device__ __align__(16) __half g_Vh16[32 * 16 * 4096]; // 4 MB V tiles f16 (j-interleaved halves)
__device__ __align__(16) uint32_t g_Wh16t[OUTF_ * 128]; // W^T f16 h2-packed, k-interleaved [n][128 words]
__device__ __align__(16) float    g_U[INF_ * 16];       // U = W @ a_blocks

// ---------------------------------------------------------------------------
// helpers
// ---------------------------------------------------------------------------
__device__ __forceinline__ float ex2f(float x) {
    float y; asm("ex2.approx.ftz.f32 %0, %1;" : "=f"(y) : "f"(x)); return y;
}
__device__ __forceinline__ uint32_t packh2(float a, float b) {
    __half2 h = __floats2half2_rn(a, b);
    return *reinterpret_cast<uint32_t*>(&h);
}
__device__ __forceinline__ uint32_t hmul2u(uint32_t a, uint32_t b) {
    uint32_t d; asm("mul.f16x2 %0, %1, %2;" : "=r"(d) : "r"(a), "r"(b)); return d;
}
__device__ __forceinline__ uint32_t hmax2u(uint32_t a, uint32_t b) {
    uint32_t d; asm("max.f16x2 %0, %1, %2;" : "=r"(d) : "r"(a), "r"(b)); return d;
}
__device__ __forceinline__ uint32_t hadd2u(uint32_t a, uint32_t b) {
    uint32_t d; asm("add.f16x2 %0, %1, %2;" : "=r"(d) : "r"(a), "r"(b)); return d;
}
__device__ __forceinline__ uint32_t prmtu(uint32_t a, uint32_t b, uint32_t c) {
    uint32_t d; asm("prmt.b32 %0, %1, %2, %3;" : "=r"(d) : "r"(a), "r"(b), "r"(c)); return d;
}
__device__ __forceinline__ uint32_t fkey(float f) {
    uint32_t u = __float_as_uint(f);
    return u ^ (uint32_t)(((int)u >> 31) | 0x80000000);
}
__device__ __forceinline__ float fkeyinv(uint32_t k) {
    return __uint_as_float(k ^ (((int)k >> 31) ? 0x80000000u : 0xFFFFFFFFu));
}
// interleaved half-position within a 128-wide row: groups of 16, pair p -> slot (p&3)*2|(p>>2)
__device__ __forceinline__ int ipos(int j) {
    int p = (j >> 1) & 7;
    int slot = ((p & 3) << 1) | (p >> 2);
    return (((j >> 4) << 3) + slot) * 2 + (j & 1);
}
__device__ __forceinline__ void mma16816(float* d, uint32_t a0, uint32_t a1, uint32_t a2,
                                         uint32_t a3, uint32_t b0, uint32_t b1) {
    asm volatile(
        "mma.sync.aligned.m16n8k16.row.col.f32.f16.f16.f32 "
        "{%0,%1,%2,%3}, {%4,%5,%6,%7}, {%8,%9}, {%0,%1,%2,%3};"
        : "+f"(d[0]), "+f"(d[1]), "+f"(d[2]), "+f"(d[3])
        : "r"(a0), "r"(a1), "r"(a2), "r"(a3), "r"(b0), "r"(b1));
}

// ---------------------------------------------------------------------------
// K_u: blocks 0-7: U[k][c] from W and a.
//      blocks 8-15: W -> W^T f16 h2-packed, k-interleaved (g_Wh16t).
// ---------------------------------------------------------------------------
__global__ __launch_bounds__(256) void u_kernel(const float4* __restrict__ W4,
                                                const float* __restrict__ a_vec) {
    __shared__ float sW[32][260];
    __shared__ float sa[64];
    const int bb = blockIdx.x, t = threadIdx.x;
    if (t < 64 && bb < 8) sa[t] = a_vec[t];
    // both halves load a 32-row k-slice of W into smem
    const int k0 = (bb & 7) * 32;
#pragma unroll
    for (int i = 0; i < 8; i++) {
        int idx4 = t + i * 256;
        int row = idx4 >> 6, col = (idx4 & 63) * 4;
        float4 v = W4[(size_t)k0 * 64 + idx4];
        *reinterpret_cast<float4*>(&sW[row][col]) = v;
    }
    __syncthreads();

    if (bb < 8) {
        const int k_loc = t >> 3, c8 = t & 7;
        float u1 = 0.f, u2 = 0.f;
#pragma unroll
        for (int d = 0; d < 32; d++) {
            float wv = sW[k_loc][c8 * 32 + d];
            u1 += wv * sa[d];
            u2 += wv * sa[32 + d];
        }
        g_U[(k0 + k_loc) * 16 + c8]     = u1;
        g_U[(k0 + k_loc) * 16 + 8 + c8] = u2;
    } else {
        // transpose + pack: thread t owns column n = t
        const int n = t;
#pragma unroll
        for (int kp = 0; kp < 16; kp++) {
            uint32_t w = packh2(sW[2 * kp][n], sW[2 * kp + 1][n]);
            int kg = (k0 >> 4) + (kp >> 3);
            int p = kp & 7;
            int slot = ((p & 3) << 1) | (p >> 2);
            g_Wh16t[n * 128 + kg * 8 + slot] = w;
        }
    }
}

// ---------------------------------------------------------------------------
// K_wh12: exact fp32 wh1/wh2 = h @ U (raw-view mapping); per-head wh2 max.
// ---------------------------------------------------------------------------
__global__ __launch_bounds__(256) void wh12_kernel(const float4* __restrict__ h4) {
    __shared__ float sH[16][260];
    __shared__ float sU[256][16];
    __shared__ float sred[8];
    const int t = threadIdx.x;
    const int r0 = blockIdx.x * 16;
#pragma unroll
    for (int i = 0; i < 4; i++) {
        int idx4 = t + i * 256;
        int row = idx4 >> 6, col = (idx4 & 63) * 4;
        float4 v = h4[(size_t)r0 * 64 + idx4];
        *reinterpret_cast<float4*>(&sH[row][col]) = v;
    }
#pragma unroll
    for (int i = 0; i < 4; i++) {
        int idx4 = t + i * 256;
        *reinterpret_cast<float4*>(&sU[0][0] + idx4 * 4) =
            *reinterpret_cast<const float4*>(g_U + idx4 * 4);
    }
    __syncthreads();

    const int row = t >> 4, out = t & 15;
    const float4* hrow = reinterpret_cast<const float4*>(&sH[row][0]);
    float acc = 0.f;
#pragma unroll 8
    for (int k4 = 0; k4 < 64; k4++) {
        float4 hv = hrow[k4];
        acc += hv.x * sU[k4 * 4 + 0][out];
        acc += hv.y * sU[k4 * 4 + 1][out];
        acc += hv.z * sU[k4 * 4 + 2][out];
        acc += hv.w * sU[k4 * 4 + 3][out];
    }
    acc *= LOG2E;

    const int r = r0 + row;
    const int b = r >> 11, hloc = (r & 2047) >> 8, bh = b * Hh + hloc;
    const int np = (r & 255) * 8 + (out & 7);
    if (out < 8) g_wh1s[bh * Nv + np] = acc;
    else         g_wh2s[bh * Nv + np] = acc;

    float mx = (out >= 8) ? acc : -1e30f;
#pragma unroll
    for (int o = 16; o > 0; o >>= 1) mx = fmaxf(mx, __shfl_xor_sync(0xFFFFFFFFu, mx, o));
    if ((t & 31) == 0) sred[t >> 5] = mx;
    __syncthreads();
    if (t == 0) {
        float m = sred[0];
#pragma unroll
        for (int q = 1; q < 8; q++) m = fmaxf(m, sred[q]);
        atomicMax(&g_w2maxU[bh], fkey(m));
    }
}

// ---------------------------------------------------------------------------
// K_adj: adj -> bitmask, int4 loads, nibble pack + shfl-OR. grid 16384 x 256.
// ---------------------------------------------------------------------------
__global__ __launch_bounds__(256) void adjbits_kernel(const int4* __restrict__ adj4) {
    unsigned idx = blockIdx.x * 256u + threadIdx.x;
    int4 v = adj4[idx];
    unsigned nib = (unsigned)(v.x > 0) | ((unsigned)(v.y > 0) << 1)
                 | ((unsigned)(v.z > 0) << 2) | ((unsigned)(v.w > 0) << 3);
    unsigned word = nib << ((threadIdx.x & 7) * 4);
    word |= __shfl_xor_sync(0xFFFFFFFFu, word, 1);
    word |= __shfl_xor_sync(0xFFFFFFFFu, word, 2);
    word |= __shfl_xor_sync(0xFFFFFFFFu, word, 4);
    if ((threadIdx.x & 7) == 0) g_adjbits[idx >> 3] = word;
}

// ---------------------------------------------------------------------------
// K1: f16 HMMA GEMM (tile 64x64, BK=16, double-buffered, all frags via LDS.64
// from k-interleaved layouts). Emits V f16 tiles (raw .view, j-interleaved).
// ---------------------------------------------------------------------------
__global__ __launch_bounds__(256) void gemm_f16_kernel(const float4* __restrict__ A4) {
    __shared__ uint32_t sA[2][64][8];   // [m][k-words interleaved], stride 8 conflict-free
    __shared__ uint32_t sB[2][64][8];   // [n][k-words interleaved]

    const int tid = threadIdx.x;
    const int w = tid >> 5, lane = tid & 31;
    const int g = lane >> 2, tig = lane & 3;
    const int wr = w & 3, wc = w >> 2;
    const int mBase = blockIdx.x * 64, nBase = blockIdx.y * 64;

    float c[4][4];
#pragma unroll
    for (int nb = 0; nb < 4; nb++)
#pragma unroll
        for (int q = 0; q < 4; q++) c[nb][q] = 0.f;

    const int rA = tid >> 2;
    const int p0 = (tid & 3) * 2;                       // this thread's two k-halfpairs
    const int slotA0 = ((p0 & 3) << 1) | (p0 >> 2);
    const int p1 = p0 + 1;
    const int slotA1 = ((p1 & 3) << 1) | (p1 >> 2);
    const int nB = tid >> 1, qB = tid & 1;              // B staging (tid < 128)
    const int rw = wr * 16, cw = wc * 32;
    const int tig2 = tig * 2;

    // staging lambda-ish via macro-less inline
    {   // preload chunk 0
        float4 v = A4[(size_t)(mBase + rA) * 64 + (p0 >> 1)];
        sA[0][rA][slotA0] = packh2(v.x, v.y);
        sA[0][rA][slotA1] = packh2(v.z, v.w);
        if (tid < 128) {
            reinterpret_cast<uint4*>(&sB[0][0][0])[nB * 2 + qB] =
                reinterpret_cast<const uint4*>(g_Wh16t)[(nBase + nB) * 32 + qB];
        }
    }
    __syncthreads();

    int buf = 0;
    for (int kc = 0; kc < 16; kc++) {
        // prefetch next chunk into registers
        uint32_t a0n = 0, a1n = 0;
        uint4 bn = make_uint4(0, 0, 0, 0);
        const bool more = kc < 15;
        if (more) {
            float4 v = A4[(size_t)(mBase + rA) * 64 + (kc + 1) * 4 + (p0 >> 1)];
            a0n = packh2(v.x, v.y);
            a1n = packh2(v.z, v.w);
            if (tid < 128)
                bn = reinterpret_cast<const uint4*>(g_Wh16t)[(nBase + nB) * 32 + (kc + 1) * 2 + qB];
        }

        // compute: 1 k-step of 16 per chunk
        uint2 a02 = *reinterpret_cast<const uint2*>(&sA[buf][rw + g][tig2]);
        uint2 a13 = *reinterpret_cast<const uint2*>(&sA[buf][rw + g + 8][tig2]);
#pragma unroll
        for (int nb = 0; nb < 4; nb++) {
            const int cn = cw + nb * 8 + g;
            uint2 bb = *reinterpret_cast<const uint2*>(&sB[buf][cn][tig2]);
            mma16816(c[nb], a02.x, a13.x, a02.y, a13.y, bb.x, bb.y);
        }

        if (more) {
            sA[buf ^ 1][rA][slotA0] = a0n;
            sA[buf ^ 1][rA][slotA1] = a1n;
            if (tid < 128)
                reinterpret_cast<uint4*>(&sB[buf ^ 1][0][0])[nB * 2 + qB] = bn;
        }
        __syncthreads();
        buf ^= 1;
    }

    // ---- V f16 epilogue (raw .view mapping, j-interleaved positions) ----
    const int b    = mBase >> 11;
    const int hloc = (mBase & 2047) >> 8;
    const int bh   = b * Hh + hloc;
    const int r255 = mBase & 255;
    const int cb   = (nBase >> 5) + wc;
    const int m0   = r255 + wr * 16 + g;

#pragma unroll
    for (int rq = 0; rq < 2; rq++) {
        const int jn = (m0 + rq * 8) * 8 + cb;
        const int ipj = ipos(jn & 127);
        __half* vt = &g_Vh16[((size_t)(bh * 16 + (jn >> 7))) * 4096 + ipj];
#pragma unroll
        for (int nb = 0; nb < 4; nb++) {
            const int d0 = nb * 8 + tig * 2;
            vt[(size_t)d0 * 128]       = __float2half(c[nb][rq * 2]);
            vt[(size_t)(d0 + 1) * 128] = __float2half(c[nb][rq * 2 + 1]);
        }
    }
}

// ---------------------------------------------------------------------------
// K2: fused scores (h2, MUFU-free) + HMMA PV + register-path l + ELU.
// All hot-loop smem reads are LDS.64 (interleaved V/F layouts).
// grid (32 itiles, 8 h, 4 b), 128 threads. Double-buffered, 1 sync/tile.
// ---------------------------------------------------------------------------
__global__ __launch_bounds__(128) void attn_kernel(float* __restrict__ out) {
    __shared__ uint32_t sRowE[64];
    __shared__ __align__(8) uint32_t sF1[2][64];            // 2^(W2-wmax), interleaved
    __shared__ __align__(8) uint32_t sF2[2][64];            // 2^(0.2*(W2-wmax)), interleaved
    __shared__ uint4  sBits[2][64];
    __shared__ __align__(16) uint32_t sVt[2][32 * 72];      // V^T f16 interleaved, stride 72

    const int tid  = threadIdx.x;
    const int w    = tid >> 5, lane = tid & 31;
    const int tig  = lane & 3, grp = lane >> 2;
    const int iT = blockIdx.x, hh = blockIdx.y, b = blockIdx.z;
    const int bh = b * Hh + hh;
    const int iBase = iT * 64;
    const int il0 = w * 16 + grp, il1 = il0 + 8;
    const int ipt = ipos(tid);

    const float wmax = fkeyinv(g_w2maxU[bh]);
    if (tid < 64) {
        float C = g_wh1s[bh * Nv + iBase + tid];
        float s = C + wmax;
        float M = fmaxf(s, SLOPE * s);
        sRowE[tid] = packh2(ex2f(s - M), ex2f(SLOPE * s - M));
    }

    const unsigned* bitsBase = g_adjbits + (size_t)(b * 2048 + iBase) * 64;
    const float* wh2Base = g_wh2s + (size_t)bh * 2048;
    const uint4* vBase = reinterpret_cast<const uint4*>(g_Vh16 + (size_t)bh * 16 * 4096);
    const int s0 = tig * 2, tig2 = tig * 2;
    int vi[4];
#pragma unroll
    for (int k = 0; k < 4; k++) {
        int q = tid + k * 128;
        vi[k] = (q >> 4) * 18 + (q & 15);   // row stride 18 uint4 = 72 words
    }

    {
        uint4* dst = reinterpret_cast<uint4*>(sVt[0]);
#pragma unroll
        for (int k = 0; k < 4; k++) dst[vi[k]] = vBase[tid + k * 128];
        float w2 = wh2Base[tid] - wmax;
        reinterpret_cast<__half*>(sF1[0])[ipt] = __float2half(ex2f(w2));
        reinterpret_cast<__half*>(sF2[0])[ipt] = __float2half(ex2f(SLOPE * w2));
        if (tid < 64)
            sBits[0][tid] = *reinterpret_cast<const uint4*>(bitsBase + (size_t)tid * 64);
    }
    __syncthreads();

    const uint32_t e0 = sRowE[il0], e1 = sRowE[il1];
    const uint32_t E0lo = prmtu(e0, e0, 0x1010u), E0hi = prmtu(e0, e0, 0x3232u);
    const uint32_t E1lo = prmtu(e1, e1, 0x1010u), E1hi = prmtu(e1, e1, 0x3232u);

    float dacc[4][4];
#pragma unroll
    for (int nb = 0; nb < 4; nb++)
#pragma unroll
        for (int q = 0; q < 4; q++) dacc[nb][q] = 0.f;
    float lsum0 = 0.f, lsum1 = 0.f;

    int buf = 0;
    for (int jt = 0; jt < 16; jt++) {
        const int nj = (jt + 1) & 15;
        uint4 va[4];
#pragma unroll
        for (int k = 0; k < 4; k++) va[k] = vBase[nj * 512 + tid + k * 128];
        float w2n = wh2Base[nj * 128 + tid] - wmax;
        uint4 bqn = make_uint4(0, 0, 0, 0);
        if (tid < 64)
            bqn = *reinterpret_cast<const uint4*>(bitsBase + (size_t)tid * 64 + nj * 4);

        const uint4 bq0 = sBits[buf][il0];
        const uint4 bq1 = sBits[buf][il1];
        const unsigned* bw0w = reinterpret_cast<const unsigned*>(&bq0);
        const unsigned* bw1w = reinterpret_cast<const unsigned*>(&bq1);
        const uint32_t* F1p = sF1[buf];
        const uint32_t* F2p = sF2[buf];
        const uint32_t* vtp = sVt[buf];
        uint32_t S0 = 0, S1 = 0, S2 = 0, S3 = 0;

#pragma unroll
        for (int k2 = 0; k2 < 4; k2++) {
            const unsigned u0 = bw0w[k2] >> s0;
            const unsigned u1 = bw1w[k2] >> s0;
            const unsigned v07 = u0 << 7, v06 = u0 << 6;
            const unsigned v17 = u1 << 7, v16 = u1 << 6;
#pragma unroll
            for (int kh = 0; kh < 2; kh++) {
                const int ks = k2 * 2 + kh;
                const int wofs = ks * 8 + tig2;
                const uint2 f1 = *reinterpret_cast<const uint2*>(F1p + wofs);
                const uint2 f2 = *reinterpret_cast<const uint2*>(F2p + wofs);
                const uint32_t cA = kh ? 0xEEAAu : 0xCC88u;
                const uint32_t cB = kh ? 0xFFBBu : 0xDD99u;

                uint32_t A0 = hmax2u(hmul2u(E0lo, f1.x), hmul2u(E0hi, f2.x)) & prmtu(v07, v06, cA);
                uint32_t A2 = hmax2u(hmul2u(E0lo, f1.y), hmul2u(E0hi, f2.y)) & prmtu(v07, v06, cB);
                uint32_t A1 = hmax2u(hmul2u(E1lo, f1.x), hmul2u(E1hi, f2.x)) & prmtu(v17, v16, cA);
                uint32_t A3 = hmax2u(hmul2u(E1lo, f1.y), hmul2u(E1hi, f2.y)) & prmtu(v17, v16, cB);

                if (ks == 0) { S0 = A0; S1 = A1; S2 = A2; S3 = A3; }
                else {
                    S0 = hadd2u(S0, A0); S1 = hadd2u(S1, A1);
                    S2 = hadd2u(S2, A2); S3 = hadd2u(S3, A3);
                }

#pragma unroll
                for (int nb = 0; nb < 4; nb++) {
                    int drow = nb * 8 + grp;
                    uint2 vv = *reinterpret_cast<const uint2*>(vtp + drow * 72 + wofs);
                    mma16816(dacc[nb], A0, A1, A2, A3, vv.x, vv.y);
                }
            }
        }
        {
            float2 t;
            t = __half22float2(*reinterpret_cast<__half2*>(&S0)); lsum0 += t.x + t.y;
            t = __half22float2(*reinterpret_cast<__half2*>(&S2)); lsum0 += t.x + t.y;
            t = __half22float2(*reinterpret_cast<__half2*>(&S1)); lsum1 += t.x + t.y;
            t = __half22float2(*reinterpret_cast<__half2*>(&S3)); lsum1 += t.x + t.y;
        }

        {
            uint4* dst = reinterpret_cast<uint4*>(sVt[buf ^ 1]);
#pragma unroll
            for (int k = 0; k < 4; k++) dst[vi[k]] = va[k];
            reinterpret_cast<__half*>(sF1[buf ^ 1])[ipt] = __float2half(ex2f(w2n));
            reinterpret_cast<__half*>(sF2[buf ^ 1])[ipt] = __float2half(ex2f(SLOPE * w2n));
            if (tid < 64) sBits[buf ^ 1][tid] = bqn;
        }
        __syncthreads();
        buf ^= 1;
    }

    lsum0 += __shfl_xor_sync(0xFFFFFFFFu, lsum0, 1);
    lsum0 += __shfl_xor_sync(0xFFFFFFFFu, lsum0, 2);
    lsum1 += __shfl_xor_sync(0xFFFFFFFFu, lsum1, 1);
    lsum1 += __shfl_xor_sync(0xFFFFFFFFu, lsum1, 2);
    const float rl0 = 1.f / lsum0;
    const float rl1 = 1.f / lsum1;

    const size_t o0 = ((size_t)bh * Nv + iBase + il0) * NHv + tig * 2;
    const size_t o1 = ((size_t)bh * Nv + iBase + il1) * NHv + tig * 2;
#pragma unroll
    for (int nb = 0; nb < 4; nb++) {
        float x0 = dacc[nb][0] * rl0, x1 = dacc[nb][1] * rl0;
        float y0 = dacc[nb][2] * rl1, y1 = dacc[nb][3] * rl1;
        x0 = (x0 > 0.f) ? x0 : expm1f(x0);
        x1 = (x1 > 0.f) ? x1 : expm1f(x1);
        y0 = (y0 > 0.f) ? y0 : expm1f(y0);
        y1 = (y1 > 0.f) ? y1 : expm1f(y1);
        *reinterpret_cast<float2*>(&out[o0 + nb * 8]) = make_float2(x0, x1);
        *reinterpret_cast<float2*>(&out[o1 + nb * 8]) = make_float2(y0, y1);
    }
}

// ---------------------------------------------------------------------------
extern "C" void kernel_launch(void* const* d_in, const int* in_sizes, int n_in,
                              void* d_out, int out_size) {
    const float* h   = (const float*)d_in[0];   // [4,2048,256]
    const int*   adj = (const int*)  d_in[1];   // [4,2048,2048]
    const float* W   = (const float*)d_in[2];   // [256,256]
    const float* a   = (const float*)d_in[3];   // [64,1]
    float* out = (float*)d_out;                 // [4,2048,256]

    static cudaStream_t s2 = nullptr, s3 = nullptr;
    static cudaEvent_t evFork = nullptr, evU = nullptr, evJ2 = nullptr, evJ3 = nullptr;
    if (s2 == nullptr) {
        cudaStreamCreateWithFlags(&s2, cudaStreamNonBlocking);
        cudaStreamCreateWithFlags(&s3, cudaStreamNonBlocking);
        cudaEventCreateWithFlags(&evFork, cudaEventDisableTiming);
        cudaEventCreateWithFlags(&evU, cudaEventDisableTiming);
        cudaEventCreateWithFlags(&evJ2, cudaEventDisableTiming);
        cudaEventCreateWithFlags(&evJ3, cudaEventDisableTiming);
    }

    // fork adjbits immediately (DRAM-bound, no dependencies)
    cudaEventRecord(evFork, 0);
    cudaStreamWaitEvent(s2, evFork, 0);
    adjbits_kernel<<<16384, 256, 0, s2>>>((const int4*)adj);
    cudaEventRecord(evJ2, s2);

    // u first (produces g_U for wh12 AND g_Wh16t for gemm)
    u_kernel<<<16, 256>>>((const float4*)W, a);
    cudaEventRecord(evU, 0);

    // wh12 (fma-bound) on s3, concurrent with gemm (tensor-bound) on main
    cudaStreamWaitEvent(s3, evU, 0);
    wh12_kernel<<<512, 256, 0, s3>>>((const float4*)h);
    cudaEventRecord(evJ3, s3);

    gemm_f16_kernel<<<dim3(128, 4), 256>>>((const float4*)h);

    // join: attn needs all branches
    cudaStreamWaitEvent(0, evJ2, 0);
    cudaStreamWaitEvent(0, evJ3, 0);
    attn_kernel<<<dim3(32, 8, 4), 128>>>(out);
}

// round 14
// speedup vs baseline: 5.7659x; 1.0205x over previous
#include <cuda_runtime.h>
#include <cuda_fp16.h>
#include <cstdint>

// Problem constants
#define Bv     4
#define Nv     2048
#define INF_   256
#define OUTF_  256
#define Hh     8
#define NHv    32
#define SLOPE  0.2f
#define LOG2E  1.4426950408889634f

// ---------------------------------------------------------------------------
// Device scratch (no allocations; zero-initialized at load)
// ---------------------------------------------------------------------------
__device__ float    g_wh1s [Bv * Hh * Nv];              // wh1 * log2e   [bh][n]
__device__ float    g_wh2s [Bv * Hh * Nv];              // wh2 * log2e   [bh][n]
__device__ unsigned g_w2maxU[Bv * Hh];                  // ordered-uint max of wh2s (atomicMax)
__device__ unsigned g_adjbits[Bv * Nv * (Nv / 32)];     // 2 MB adj bitmask
__device__ __align__(16) __half g_Vh16[32 * 16 * 4096]; // 4 MB V tiles f16 (j-interleaved halves)
__device__ __align__(16) uint32_t g_Wh16t[OUTF_ * 128]; // W^T f16 h2-packed, k-interleaved [n][128 words]
__device__ __align__(16) float    g_U[INF_ * 16];       // U = W @ a_blocks

#define ONESH2 0x3C003C00u

// ---------------------------------------------------------------------------
// helpers
// ---------------------------------------------------------------------------
__device__ __forceinline__ float ex2f(float x) {
    float y; asm("ex2.approx.ftz.f32 %0, %1;" : "=f"(y) : "f"(x)); return y;
}
__device__ __forceinline__ uint32_t packh2(float a, float b) {
    __half2 h = __floats2half2_rn(a, b);
    return *reinterpret_cast<uint32_t*>(&h);
}
__device__ __forceinline__ uint32_t hmul2u(uint32_t a, uint32_t b) {
    uint32_t d; asm("mul.f16x2 %0, %1, %2;" : "=r"(d) : "r"(a), "r"(b)); return d;
}
__device__ __forceinline__ uint32_t hmax2u(uint32_t a, uint32_t b) {
    uint32_t d; asm("max.f16x2 %0, %1, %2;" : "=r"(d) : "r"(a), "r"(b)); return d;
}
__device__ __forceinline__ uint32_t prmtu(uint32_t a, uint32_t b, uint32_t c) {
    uint32_t d; asm("prmt.b32 %0, %1, %2, %3;" : "=r"(d) : "r"(a), "r"(b), "r"(c)); return d;
}
__device__ __forceinline__ uint32_t fkey(float f) {
    uint32_t u = __float_as_uint(f);
    return u ^ (uint32_t)(((int)u >> 31) | 0x80000000);
}
__device__ __forceinline__ float fkeyinv(uint32_t k) {
    return __uint_as_float(k ^ (((int)k >> 31) ? 0x80000000u : 0xFFFFFFFFu));
}
// interleaved half-position within a 128-wide row: groups of 16, pair p -> slot (p&3)*2|(p>>2)
__device__ __forceinline__ int ipos(int j) {
    int p = (j >> 1) & 7;
    int slot = ((p & 3) << 1) | (p >> 2);
    return (((j >> 4) << 3) + slot) * 2 + (j & 1);
}
__device__ __forceinline__ void mma16816(float* d, uint32_t a0, uint32_t a1, uint32_t a2,
                                         uint32_t a3, uint32_t b0, uint32_t b1) {
    asm volatile(
        "mma.sync.aligned.m16n8k16.row.col.f32.f16.f16.f32 "
        "{%0,%1,%2,%3}, {%4,%5,%6,%7}, {%8,%9}, {%0,%1,%2,%3};"
        : "+f"(d[0]), "+f"(d[1]), "+f"(d[2]), "+f"(d[3])
        : "r"(a0), "r"(a1), "r"(a2), "r"(a3), "r"(b0), "r"(b1));
}

// ---------------------------------------------------------------------------
// K_u: blocks 0-7: U[k][c] from W and a.
//      blocks 8-15: W -> W^T f16 h2-packed, k-interleaved (g_Wh16t).
// ---------------------------------------------------------------------------
__global__ __launch_bounds__(256) void u_kernel(const float4* __restrict__ W4,
                                                const float* __restrict__ a_vec) {
    __shared__ float sW[32][260];
    __shared__ float sa[64];
    const int bb = blockIdx.x, t = threadIdx.x;
    if (t < 64 && bb < 8) sa[t] = a_vec[t];
    const int k0 = (bb & 7) * 32;
#pragma unroll
    for (int i = 0; i < 8; i++) {
        int idx4 = t + i * 256;
        int row = idx4 >> 6, col = (idx4 & 63) * 4;
        float4 v = W4[(size_t)k0 * 64 + idx4];
        *reinterpret_cast<float4*>(&sW[row][col]) = v;
    }
    __syncthreads();

    if (bb < 8) {
        const int k_loc = t >> 3, c8 = t & 7;
        float u1 = 0.f, u2 = 0.f;
#pragma unroll
        for (int d = 0; d < 32; d++) {
            float wv = sW[k_loc][c8 * 32 + d];
            u1 += wv * sa[d];
            u2 += wv * sa[32 + d];
        }
        g_U[(k0 + k_loc) * 16 + c8]     = u1;
        g_U[(k0 + k_loc) * 16 + 8 + c8] = u2;
    } else {
        const int n = t;
#pragma unroll
        for (int kp = 0; kp < 16; kp++) {
            uint32_t w = packh2(sW[2 * kp][n], sW[2 * kp + 1][n]);
            int kg = (k0 >> 4) + (kp >> 3);
            int p = kp & 7;
            int slot = ((p & 3) << 1) | (p >> 2);
            g_Wh16t[n * 128 + kg * 8 + slot] = w;
        }
    }
}

// ---------------------------------------------------------------------------
// K_wh12: exact fp32 wh1/wh2 = h @ U (raw-view mapping); per-head wh2 max.
// ---------------------------------------------------------------------------
__global__ __launch_bounds__(256) void wh12_kernel(const float4* __restrict__ h4) {
    __shared__ float sH[16][260];
    __shared__ float sU[256][16];
    __shared__ float sred[8];
    const int t = threadIdx.x;
    const int r0 = blockIdx.x * 16;
#pragma unroll
    for (int i = 0; i < 4; i++) {
        int idx4 = t + i * 256;
        int row = idx4 >> 6, col = (idx4 & 63) * 4;
        float4 v = h4[(size_t)r0 * 64 + idx4];
        *reinterpret_cast<float4*>(&sH[row][col]) = v;
    }
#pragma unroll
    for (int i = 0; i < 4; i++) {
        int idx4 = t + i * 256;
        *reinterpret_cast<float4*>(&sU[0][0] + idx4 * 4) =
            *reinterpret_cast<const float4*>(g_U + idx4 * 4);
    }
    __syncthreads();

    const int row = t >> 4, out = t & 15;
    const float4* hrow = reinterpret_cast<const float4*>(&sH[row][0]);
    float acc = 0.f;
#pragma unroll 8
    for (int k4 = 0; k4 < 64; k4++) {
        float4 hv = hrow[k4];
        acc += hv.x * sU[k4 * 4 + 0][out];
        acc += hv.y * sU[k4 * 4 + 1][out];
        acc += hv.z * sU[k4 * 4 + 2][out];
        acc += hv.w * sU[k4 * 4 + 3][out];
    }
    acc *= LOG2E;

    const int r = r0 + row;
    const int b = r >> 11, hloc = (r & 2047) >> 8, bh = b * Hh + hloc;
    const int np = (r & 255) * 8 + (out & 7);
    if (out < 8) g_wh1s[bh * Nv + np] = acc;
    else         g_wh2s[bh * Nv + np] = acc;

    float mx = (out >= 8) ? acc : -1e30f;
#pragma unroll
    for (int o = 16; o > 0; o >>= 1) mx = fmaxf(mx, __shfl_xor_sync(0xFFFFFFFFu, mx, o));
    if ((t & 31) == 0) sred[t >> 5] = mx;
    __syncthreads();
    if (t == 0) {
        float m = sred[0];
#pragma unroll
        for (int q = 1; q < 8; q++) m = fmaxf(m, sred[q]);
        atomicMax(&g_w2maxU[bh], fkey(m));
    }
}

// ---------------------------------------------------------------------------
// K_adj: adj -> bitmask, int4 loads, nibble pack + shfl-OR. grid 16384 x 256.
// ---------------------------------------------------------------------------
__global__ __launch_bounds__(256) void adjbits_kernel(const int4* __restrict__ adj4) {
    unsigned idx = blockIdx.x * 256u + threadIdx.x;
    int4 v = adj4[idx];
    unsigned nib = (unsigned)(v.x > 0) | ((unsigned)(v.y > 0) << 1)
                 | ((unsigned)(v.z > 0) << 2) | ((unsigned)(v.w > 0) << 3);
    unsigned word = nib << ((threadIdx.x & 7) * 4);
    word |= __shfl_xor_sync(0xFFFFFFFFu, word, 1);
    word |= __shfl_xor_sync(0xFFFFFFFFu, word, 2);
    word |= __shfl_xor_sync(0xFFFFFFFFu, word, 4);
    if ((threadIdx.x & 7) == 0) g_adjbits[idx >> 3] = word;
}

// ---------------------------------------------------------------------------
// K1: f16 HMMA GEMM, BK=32 double-buffered (8 barriers; 8 MMAs per stage).
// sA/sB split into per-ksub 8-word planes -> all fragments conflict-free LDS.64.
// Emits V f16 tiles (raw .view, j-interleaved).
// ---------------------------------------------------------------------------
__global__ __launch_bounds__(256) void gemm_f16_kernel(const float4* __restrict__ A4) {
    __shared__ uint32_t sA[2][2][64][8];   // [buf][ksub][m][8 words]
    __shared__ uint32_t sB[2][2][64][8];   // [buf][ksub][n][8 words]

    const int tid = threadIdx.x;
    const int w = tid >> 5, lane = tid & 31;
    const int g = lane >> 2, tig = lane & 3;
    const int wr = w & 3, wc = w >> 2;
    const int mBase = blockIdx.x * 64, nBase = blockIdx.y * 64;

    float c[4][4];
#pragma unroll
    for (int nb = 0; nb < 4; nb++)
#pragma unroll
        for (int q = 0; q < 4; q++) c[nb][q] = 0.f;

    const int rA = tid >> 2, qA = tid & 3;              // 4 threads per A row
    const int p0 = qA * 2;                              // pair indices p0, p0+1
    const int slot0 = ((p0 & 3) << 1) | (p0 >> 2);
    const int slot1 = (((p0 + 1) & 3) << 1) | ((p0 + 1) >> 2);
    const int nB = tid >> 2, qB = tid & 3;              // 4 uint4 per B row per chunk
    const int ksubB = qB >> 1, u4B = qB & 1;
    const int rw = wr * 16, cw = wc * 32;
    const int tig2 = tig * 2;

    // preload chunk 0 (k 0..31)
    {
        float4 v0 = A4[(size_t)(mBase + rA) * 64 + qA];        // ksub0: floats qA*4..+3
        float4 v1 = A4[(size_t)(mBase + rA) * 64 + 4 + qA];    // ksub1
        sA[0][0][rA][slot0] = packh2(v0.x, v0.y);
        sA[0][0][rA][slot1] = packh2(v0.z, v0.w);
        sA[0][1][rA][slot0] = packh2(v1.x, v1.y);
        sA[0][1][rA][slot1] = packh2(v1.z, v1.w);
        reinterpret_cast<uint4*>(&sB[0][ksubB][nB][0])[u4B] =
            reinterpret_cast<const uint4*>(g_Wh16t)[(nBase + nB) * 32 + qB];
    }
    __syncthreads();

    int buf = 0;
    for (int kc = 0; kc < 8; kc++) {          // 8 chunks of BK=32
        // prefetch next chunk into registers
        uint32_t an[4];
        uint4 bn = make_uint4(0, 0, 0, 0);
        const bool more = kc < 7;
        if (more) {
            float4 v0 = A4[(size_t)(mBase + rA) * 64 + (kc + 1) * 8 + qA];
            float4 v1 = A4[(size_t)(mBase + rA) * 64 + (kc + 1) * 8 + 4 + qA];
            an[0] = packh2(v0.x, v0.y); an[1] = packh2(v0.z, v0.w);
            an[2] = packh2(v1.x, v1.y); an[3] = packh2(v1.z, v1.w);
            bn = reinterpret_cast<const uint4*>(g_Wh16t)[(nBase + nB) * 32 + (kc + 1) * 4 + qB];
        }

        // compute: 2 k-steps of 16
#pragma unroll
        for (int ks = 0; ks < 2; ks++) {
            uint2 a02 = *reinterpret_cast<const uint2*>(&sA[buf][ks][rw + g][tig2]);
            uint2 a13 = *reinterpret_cast<const uint2*>(&sA[buf][ks][rw + g + 8][tig2]);
#pragma unroll
            for (int nb = 0; nb < 4; nb++) {
                const int cn = cw + nb * 8 + g;
                uint2 bb = *reinterpret_cast<const uint2*>(&sB[buf][ks][cn][tig2]);
                mma16816(c[nb], a02.x, a13.x, a02.y, a13.y, bb.x, bb.y);
            }
        }

        if (more) {
            sA[buf ^ 1][0][rA][slot0] = an[0];
            sA[buf ^ 1][0][rA][slot1] = an[1];
            sA[buf ^ 1][1][rA][slot0] = an[2];
            sA[buf ^ 1][1][rA][slot1] = an[3];
            reinterpret_cast<uint4*>(&sB[buf ^ 1][ksubB][nB][0])[u4B] = bn;
        }
        __syncthreads();
        buf ^= 1;
    }

    // ---- V f16 epilogue (raw .view mapping, j-interleaved positions) ----
    const int b    = mBase >> 11;
    const int hloc = (mBase & 2047) >> 8;
    const int bh   = b * Hh + hloc;
    const int r255 = mBase & 255;
    const int cb   = (nBase >> 5) + wc;
    const int m0   = r255 + wr * 16 + g;

#pragma unroll
    for (int rq = 0; rq < 2; rq++) {
        const int jn = (m0 + rq * 8) * 8 + cb;
        const int ipj = ipos(jn & 127);
        __half* vt = &g_Vh16[((size_t)(bh * 16 + (jn >> 7))) * 4096 + ipj];
#pragma unroll
        for (int nb = 0; nb < 4; nb++) {
            const int d0 = nb * 8 + tig * 2;
            vt[(size_t)d0 * 128]       = __float2half(c[nb][rq * 2]);
            vt[(size_t)(d0 + 1) * 128] = __float2half(c[nb][rq * 2 + 1]);
        }
    }
}

// ---------------------------------------------------------------------------
// K2: fused scores (h2, MUFU-free) + HMMA PV + ones-MMA l + ELU.
// All hot-loop smem reads LDS.64. l via per-kh ones-MMA (issue-cheap; tensor
// has headroom). grid (32, 8, 4), 128 threads, double-buffered, 1 sync/tile.
// ---------------------------------------------------------------------------
__global__ __launch_bounds__(128) void attn_kernel(float* __restrict__ out) {
    __shared__ uint32_t sRowE[64];
    __shared__ __align__(8) uint32_t sF1[2][64];
    __shared__ __align__(8) uint32_t sF2[2][64];
    __shared__ uint4  sBits[2][64];
    __shared__ __align__(16) uint32_t sVt[2][32 * 72];

    const int tid  = threadIdx.x;
    const int w    = tid >> 5, lane = tid & 31;
    const int tig  = lane & 3, grp = lane >> 2;
    const int iT = blockIdx.x, hh = blockIdx.y, b = blockIdx.z;
    const int bh = b * Hh + hh;
    const int iBase = iT * 64;
    const int il0 = w * 16 + grp, il1 = il0 + 8;
    const int ipt = ipos(tid);

    const float wmax = fkeyinv(g_w2maxU[bh]);
    if (tid < 64) {
        float C = g_wh1s[bh * Nv + iBase + tid];
        float s = C + wmax;
        float M = fmaxf(s, SLOPE * s);
        sRowE[tid] = packh2(ex2f(s - M), ex2f(SLOPE * s - M));
    }

    const unsigned* bitsBase = g_adjbits + (size_t)(b * 2048 + iBase) * 64;
    const float* wh2Base = g_wh2s + (size_t)bh * 2048;
    const uint4* vBase = reinterpret_cast<const uint4*>(g_Vh16 + (size_t)bh * 16 * 4096);
    const int s0 = tig * 2, tig2 = tig * 2;
    int vi[4];
#pragma unroll
    for (int k = 0; k < 4; k++) {
        int q = tid + k * 128;
        vi[k] = (q >> 4) * 18 + (q & 15);
    }

    {
        uint4* dst = reinterpret_cast<uint4*>(sVt[0]);
#pragma unroll
        for (int k = 0; k < 4; k++) dst[vi[k]] = vBase[tid + k * 128];
        float w2 = wh2Base[tid] - wmax;
        reinterpret_cast<__half*>(sF1[0])[ipt] = __float2half(ex2f(w2));
        reinterpret_cast<__half*>(sF2[0])[ipt] = __float2half(ex2f(SLOPE * w2));
        if (tid < 64)
            sBits[0][tid] = *reinterpret_cast<const uint4*>(bitsBase + (size_t)tid * 64);
    }
    __syncthreads();

    const uint32_t e0 = sRowE[il0], e1 = sRowE[il1];
    const uint32_t E0lo = prmtu(e0, e0, 0x1010u), E0hi = prmtu(e0, e0, 0x3232u);
    const uint32_t E1lo = prmtu(e1, e1, 0x1010u), E1hi = prmtu(e1, e1, 0x3232u);

    float dacc[4][4];
#pragma unroll
    for (int nb = 0; nb < 4; nb++)
#pragma unroll
        for (int q = 0; q < 4; q++) dacc[nb][q] = 0.f;
    float lacc[4] = {0.f, 0.f, 0.f, 0.f};

    int buf = 0;
    for (int jt = 0; jt < 16; jt++) {
        const int nj = (jt + 1) & 15;
        uint4 va[4];
#pragma unroll
        for (int k = 0; k < 4; k++) va[k] = vBase[nj * 512 + tid + k * 128];
        float w2n = wh2Base[nj * 128 + tid] - wmax;
        uint4 bqn = make_uint4(0, 0, 0, 0);
        if (tid < 64)
            bqn = *reinterpret_cast<const uint4*>(bitsBase + (size_t)tid * 64 + nj * 4);

        const uint4 bq0 = sBits[buf][il0];
        const uint4 bq1 = sBits[buf][il1];
        const unsigned* bw0w = reinterpret_cast<const unsigned*>(&bq0);
        const unsigned* bw1w = reinterpret_cast<const unsigned*>(&bq1);
        const uint32_t* F1p = sF1[buf];
        const uint32_t* F2p = sF2[buf];
        const uint32_t* vtp = sVt[buf];

#pragma unroll
        for (int k2 = 0; k2 < 4; k2++) {
            const unsigned u0 = bw0w[k2] >> s0;
            const unsigned u1 = bw1w[k2] >> s0;
            const unsigned v07 = u0 << 7, v06 = u0 << 6;
            const unsigned v17 = u1 << 7, v16 = u1 << 6;
#pragma unroll
            for (int kh = 0; kh < 2; kh++) {
                const int wofs = (k2 * 2 + kh) * 8 + tig2;
                const uint2 f1 = *reinterpret_cast<const uint2*>(F1p + wofs);
                const uint2 f2 = *reinterpret_cast<const uint2*>(F2p + wofs);
                const uint32_t cA = kh ? 0xEEAAu : 0xCC88u;
                const uint32_t cB = kh ? 0xFFBBu : 0xDD99u;

                uint32_t A0 = hmax2u(hmul2u(E0lo, f1.x), hmul2u(E0hi, f2.x)) & prmtu(v07, v06, cA);
                uint32_t A2 = hmax2u(hmul2u(E0lo, f1.y), hmul2u(E0hi, f2.y)) & prmtu(v07, v06, cB);
                uint32_t A1 = hmax2u(hmul2u(E1lo, f1.x), hmul2u(E1hi, f2.x)) & prmtu(v17, v16, cA);
                uint32_t A3 = hmax2u(hmul2u(E1lo, f1.y), hmul2u(E1hi, f2.y)) & prmtu(v17, v16, cB);

#pragma unroll
                for (int nb = 0; nb < 4; nb++) {
                    int drow = nb * 8 + grp;
                    uint2 vv = *reinterpret_cast<const uint2*>(vtp + drow * 72 + wofs);
                    mma16816(dacc[nb], A0, A1, A2, A3, vv.x, vv.y);
                }
                mma16816(lacc, A0, A1, A2, A3, ONESH2, ONESH2);
            }
        }

        {
            uint4* dst = reinterpret_cast<uint4*>(sVt[buf ^ 1]);
#pragma unroll
            for (int k = 0; k < 4; k++) dst[vi[k]] = va[k];
            reinterpret_cast<__half*>(sF1[buf ^ 1])[ipt] = __float2half(ex2f(w2n));
            reinterpret_cast<__half*>(sF2[buf ^ 1])[ipt] = __float2half(ex2f(SLOPE * w2n));
            if (tid < 64) sBits[buf ^ 1][tid] = bqn;
        }
        __syncthreads();
        buf ^= 1;
    }

    const float rl0 = 1.f / lacc[0];
    const float rl1 = 1.f / lacc[2];

    const size_t o0 = ((size_t)bh * Nv + iBase + il0) * NHv + tig * 2;
    const size_t o1 = ((size_t)bh * Nv + iBase + il1) * NHv + tig * 2;
#pragma unroll
    for (int nb = 0; nb < 4; nb++) {
        float x0 = dacc[nb][0] * rl0, x1 = dacc[nb][1] * rl0;
        float y0 = dacc[nb][2] * rl1, y1 = dacc[nb][3] * rl1;
        x0 = (x0 > 0.f) ? x0 : expm1f(x0);
        x1 = (x1 > 0.f) ? x1 : expm1f(x1);
        y0 = (y0 > 0.f) ? y0 : expm1f(y0);
        y1 = (y1 > 0.f) ? y1 : expm1f(y1);
        *reinterpret_cast<float2*>(&out[o0 + nb * 8]) = make_float2(x0, x1);
        *reinterpret_cast<float2*>(&out[o1 + nb * 8]) = make_float2(y0, y1);
    }
}

// ---------------------------------------------------------------------------
extern "C" void kernel_launch(void* const* d_in, const int* in_sizes, int n_in,
                              void* d_out, int out_size) {
    const float* h   = (const float*)d_in[0];   // [4,2048,256]
    const int*   adj = (const int*)  d_in[1];   // [4,2048,2048]
    const float* W   = (const float*)d_in[2];   // [256,256]
    const float* a   = (const float*)d_in[3];   // [64,1]
    float* out = (float*)d_out;                 // [4,2048,256]

    static cudaStream_t s2 = nullptr, s3 = nullptr;
    static cudaEvent_t evFork = nullptr, evU = nullptr, evJ2 = nullptr, evJ3 = nullptr;
    if (s2 == nullptr) {
        cudaStreamCreateWithFlags(&s2, cudaStreamNonBlocking);
        cudaStreamCreateWithFlags(&s3, cudaStreamNonBlocking);
        cudaEventCreateWithFlags(&evFork, cudaEventDisableTiming);
        cudaEventCreateWithFlags(&evU, cudaEventDisableTiming);
        cudaEventCreateWithFlags(&evJ2, cudaEventDisableTiming);
        cudaEventCreateWithFlags(&evJ3, cudaEventDisableTiming);
    }

    // fork adjbits immediately (DRAM-bound, no dependencies)
    cudaEventRecord(evFork, 0);
    cudaStreamWaitEvent(s2, evFork, 0);
    adjbits_kernel<<<16384, 256, 0, s2>>>((const int4*)adj);
    cudaEventRecord(evJ2, s2);

    // u first (produces g_U for wh12 AND g_Wh16t for gemm)
    u_kernel<<<16, 256>>>((const float4*)W, a);
    cudaEventRecord(evU, 0);

    // wh12 (fma-bound) on s3, concurrent with gemm (tensor-bound) on main
    cudaStreamWaitEvent(s3, evU, 0);
    wh12_kernel<<<512, 256, 0, s3>>>((const float4*)h);
    cudaEventRecord(evJ3, s3);

    gemm_f16_kernel<<<dim3(128, 4), 256>>>((const float4*)h);

    // join: attn needs all branches
    cudaStreamWaitEvent(0, evJ2, 0);
    cudaStreamWaitEvent(0, evJ3, 0);
    attn_kernel<<<dim3(32, 8, 4), 128>>>(out);
}

// round 15
// speedup vs baseline: 6.1498x; 1.0666x over previous
#include <cuda_runtime.h>
#include <cuda_fp16.h>
#include <cstdint>

// Problem constants
#define Bv     4
#define Nv     2048
#define INF_   256
#define OUTF_  256
#define Hh     8
#define NHv    32
#define SLOPE  0.2f
#define LOG2E  1.4426950408889634f

// ---------------------------------------------------------------------------
// Device scratch (no allocations; zero-initialized at load)
// ---------------------------------------------------------------------------
__device__ float    g_wh1s [Bv * Hh * Nv];              // wh1 * log2e   [bh][n]
__device__ float    g_wh2s [Bv * Hh * Nv];              // wh2 * log2e   [bh][n]
__device__ unsigned g_w2maxU[Bv * Hh];                  // ordered-uint max (atomicMax)
__device__ unsigned g_adjbits[Bv * Nv * (Nv / 32)];     // 2 MB adj bitmask
__device__ __align__(16) __half g_Vh16[32 * 16 * 4096]; // 4 MB V tiles f16 (j-interleaved)
__device__ __align__(16) uint32_t g_Wh16t[OUTF_ * 128]; // W^T f16 h2, k-interleaved [n][128w]
__device__ __align__(16) uint32_t g_Ah16[Bv * Nv * 128];// 4 MB h f16 h2, k-interleaved [m][128w]
__device__ __align__(16) float    g_U[INF_ * 16];       // U = W @ a_blocks

#define ONESH2 0x3C003C00u

// ---------------------------------------------------------------------------
// helpers
// ---------------------------------------------------------------------------
__device__ __forceinline__ float ex2f(float x) {
    float y; asm("ex2.approx.ftz.f32 %0, %1;" : "=f"(y) : "f"(x)); return y;
}
__device__ __forceinline__ uint32_t packh2(float a, float b) {
    __half2 h = __floats2half2_rn(a, b);
    return *reinterpret_cast<uint32_t*>(&h);
}
__device__ __forceinline__ uint32_t hmul2u(uint32_t a, uint32_t b) {
    uint32_t d; asm("mul.f16x2 %0, %1, %2;" : "=r"(d) : "r"(a), "r"(b)); return d;
}
__device__ __forceinline__ uint32_t hmax2u(uint32_t a, uint32_t b) {
    uint32_t d; asm("max.f16x2 %0, %1, %2;" : "=r"(d) : "r"(a), "r"(b)); return d;
}
__device__ __forceinline__ uint32_t prmtu(uint32_t a, uint32_t b, uint32_t c) {
    uint32_t d; asm("prmt.b32 %0, %1, %2, %3;" : "=r"(d) : "r"(a), "r"(b), "r"(c)); return d;
}
__device__ __forceinline__ uint32_t fkey(float f) {
    uint32_t u = __float_as_uint(f);
    return u ^ (uint32_t)(((int)u >> 31) | 0x80000000);
}
__device__ __forceinline__ float fkeyinv(uint32_t k) {
    return __uint_as_float(k ^ (((int)k >> 31) ? 0x80000000u : 0xFFFFFFFFu));
}
// interleaved word index for k-pair p within a 128-word row
__device__ __forceinline__ int wordpos(int p) {
    int q = p & 7;
    int slot = ((q & 3) << 1) | (q >> 2);
    return ((p >> 3) << 3) + slot;
}
// interleaved half-position within a 128-wide row (for V j index)
__device__ __forceinline__ int ipos(int j) {
    return wordpos(j >> 1) * 2 + (j & 1);
}
__device__ __forceinline__ uint32_t smem_u32(const void* p) {
    uint32_t a;
    asm("{ .reg .u64 t; cvta.to.shared.u64 t, %1; cvt.u32.u64 %0, t; }" : "=r"(a) : "l"(p));
    return a;
}
#define CP_ASYNC16(dst, src) \
    asm volatile("cp.async.cg.shared.global [%0], [%1], 16;" :: "r"(dst), "l"(src))
#define CP_COMMIT() asm volatile("cp.async.commit_group;" ::: "memory")
#define CP_WAIT2()  asm volatile("cp.async.wait_group 2;" ::: "memory")

__device__ __forceinline__ void mma16816(float* d, uint32_t a0, uint32_t a1, uint32_t a2,
                                         uint32_t a3, uint32_t b0, uint32_t b1) {
    asm volatile(
        "mma.sync.aligned.m16n8k16.row.col.f32.f16.f16.f32 "
        "{%0,%1,%2,%3}, {%4,%5,%6,%7}, {%8,%9}, {%0,%1,%2,%3};"
        : "+f"(d[0]), "+f"(d[1]), "+f"(d[2]), "+f"(d[3])
        : "r"(a0), "r"(a1), "r"(a2), "r"(a3), "r"(b0), "r"(b1));
}

// ---------------------------------------------------------------------------
// K_u: blocks 0-7: U[k][c] from W and a.
//      blocks 8-15: W -> W^T f16 h2-packed, k-interleaved (g_Wh16t).
//      blocks 16-527: h -> f16 h2-packed, k-interleaved (g_Ah16), 16 rows/blk.
// ---------------------------------------------------------------------------
__global__ __launch_bounds__(256) void u_kernel(const float4* __restrict__ W4,
                                                const float* __restrict__ a_vec,
                                                const float4* __restrict__ h4) {
    __shared__ float sW[32][260];
    __shared__ float sa[64];
    const int bb = blockIdx.x, t = threadIdx.x;

    if (bb >= 16) {   // ---- hconv: 16 rows of h per block ----
        const int rb = (bb - 16) * 16;
#pragma unroll
        for (int i = 0; i < 4; i++) {
            int idx = t + i * 256;
            int row = rb + (idx >> 6), k4 = idx & 63;
            float4 v = h4[(size_t)row * 64 + k4];
            int p0 = k4 * 2;
            g_Ah16[(size_t)row * 128 + wordpos(p0)]     = packh2(v.x, v.y);
            g_Ah16[(size_t)row * 128 + wordpos(p0 + 1)] = packh2(v.z, v.w);
        }
        return;
    }

    if (t < 64 && bb < 8) sa[t] = a_vec[t];
    const int k0 = (bb & 7) * 32;
#pragma unroll
    for (int i = 0; i < 8; i++) {
        int idx4 = t + i * 256;
        int row = idx4 >> 6, col = (idx4 & 63) * 4;
        float4 v = W4[(size_t)k0 * 64 + idx4];
        *reinterpret_cast<float4*>(&sW[row][col]) = v;
    }
    __syncthreads();

    if (bb < 8) {
        const int k_loc = t >> 3, c8 = t & 7;
        float u1 = 0.f, u2 = 0.f;
#pragma unroll
        for (int d = 0; d < 32; d++) {
            float wv = sW[k_loc][c8 * 32 + d];
            u1 += wv * sa[d];
            u2 += wv * sa[32 + d];
        }
        g_U[(k0 + k_loc) * 16 + c8]     = u1;
        g_U[(k0 + k_loc) * 16 + 8 + c8] = u2;
    } else {
        const int n = t;
#pragma unroll
        for (int kp = 0; kp < 16; kp++) {
            uint32_t w = packh2(sW[2 * kp][n], sW[2 * kp + 1][n]);
            g_Wh16t[n * 128 + (k0 >> 4) * 8 + wordpos(kp) - ((kp >> 3) << 3) +
                    ((kp >> 3) << 3)] = w;   // == n*128 + wordpos((k0>>4)*8 + kp)
        }
    }
}

// ---------------------------------------------------------------------------
// K_wh12: exact fp32 wh1/wh2 = h @ U (raw-view mapping); per-head wh2 max.
// ---------------------------------------------------------------------------
__global__ __launch_bounds__(256) void wh12_kernel(const float4* __restrict__ h4) {
    __shared__ float sH[16][260];
    __shared__ float sU[256][16];
    __shared__ float sred[8];
    const int t = threadIdx.x;
    const int r0 = blockIdx.x * 16;
#pragma unroll
    for (int i = 0; i < 4; i++) {
        int idx4 = t + i * 256;
        int row = idx4 >> 6, col = (idx4 & 63) * 4;
        float4 v = h4[(size_t)r0 * 64 + idx4];
        *reinterpret_cast<float4*>(&sH[row][col]) = v;
    }
#pragma unroll
    for (int i = 0; i < 4; i++) {
        int idx4 = t + i * 256;
        *reinterpret_cast<float4*>(&sU[0][0] + idx4 * 4) =
            *reinterpret_cast<const float4*>(g_U + idx4 * 4);
    }
    __syncthreads();

    const int row = t >> 4, out = t & 15;
    const float4* hrow = reinterpret_cast<const float4*>(&sH[row][0]);
    float acc = 0.f;
#pragma unroll 8
    for (int k4 = 0; k4 < 64; k4++) {
        float4 hv = hrow[k4];
        acc += hv.x * sU[k4 * 4 + 0][out];
        acc += hv.y * sU[k4 * 4 + 1][out];
        acc += hv.z * sU[k4 * 4 + 2][out];
        acc += hv.w * sU[k4 * 4 + 3][out];
    }
    acc *= LOG2E;

    const int r = r0 + row;
    const int b = r >> 11, hloc = (r & 2047) >> 8, bh = b * Hh + hloc;
    const int np = (r & 255) * 8 + (out & 7);
    if (out < 8) g_wh1s[bh * Nv + np] = acc;
    else         g_wh2s[bh * Nv + np] = acc;

    float mx = (out >= 8) ? acc : -1e30f;
#pragma unroll
    for (int o = 16; o > 0; o >>= 1) mx = fmaxf(mx, __shfl_xor_sync(0xFFFFFFFFu, mx, o));
    if ((t & 31) == 0) sred[t >> 5] = mx;
    __syncthreads();
    if (t == 0) {
        float m = sred[0];
#pragma unroll
        for (int q = 1; q < 8; q++) m = fmaxf(m, sred[q]);
        atomicMax(&g_w2maxU[bh], fkey(m));
    }
}

// ---------------------------------------------------------------------------
// K_adj: adj -> bitmask, int4 loads, nibble pack + shfl-OR. grid 16384 x 256.
// ---------------------------------------------------------------------------
__global__ __launch_bounds__(256) void adjbits_kernel(const int4* __restrict__ adj4) {
    unsigned idx = blockIdx.x * 256u + threadIdx.x;
    int4 v = adj4[idx];
    unsigned nib = (unsigned)(v.x > 0) | ((unsigned)(v.y > 0) << 1)
                 | ((unsigned)(v.z > 0) << 2) | ((unsigned)(v.w > 0) << 3);
    unsigned word = nib << ((threadIdx.x & 7) * 4);
    word |= __shfl_xor_sync(0xFFFFFFFFu, word, 1);
    word |= __shfl_xor_sync(0xFFFFFFFFu, word, 2);
    word |= __shfl_xor_sync(0xFFFFFFFFu, word, 4);
    if ((threadIdx.x & 7) == 0) g_adjbits[idx >> 3] = word;
}

// ---------------------------------------------------------------------------
// K1: f16 HMMA GEMM, 4-stage cp.async pipeline (BK=32/stage, 8 stages).
// A/B both pre-converted f16 h2 k-interleaved; rows padded to 20 words ->
// conflict-free LDS.64 fragments. Emits V f16 tiles (raw .view, j-interleaved).
// ---------------------------------------------------------------------------
__global__ __launch_bounds__(256) void gemm_f16_kernel() {
    __shared__ uint32_t sA[4][64][20];
    __shared__ uint32_t sB[4][64][20];

    const int tid = threadIdx.x;
    const int w = tid >> 5, lane = tid & 31;
    const int g = lane >> 2, tig = lane & 3;
    const int wr = w & 3, wc = w >> 2;
    const int mBase = blockIdx.x * 64, nBase = blockIdx.y * 64;

    float c[4][4];
#pragma unroll
    for (int nb = 0; nb < 4; nb++)
#pragma unroll
        for (int q = 0; q < 4; q++) c[nb][q] = 0.f;

    // staging: thread -> (row, 4-word chunk) for both A and B
    const int rowC = tid >> 2, qw = (tid & 3) * 4;
    const uint32_t dA0 = smem_u32(&sA[0][rowC][qw]);
    const uint32_t dB0 = smem_u32(&sB[0][rowC][qw]);
    const uint32_t* srcA = g_Ah16 + (size_t)(mBase + rowC) * 128 + qw;
    const uint32_t* srcB = g_Wh16t + (size_t)(nBase + rowC) * 128 + qw;
    const int STAGE_B = 64 * 20 * 4;   // bytes per stage

    const int rw = wr * 16, cw = wc * 32;
    const int tig2 = tig * 2;

    // prologue: issue stages 0..2
#pragma unroll
    for (int s = 0; s < 3; s++) {
        CP_ASYNC16(dA0 + s * STAGE_B, srcA + s * 16);
        CP_ASYNC16(dB0 + s * STAGE_B, srcB + s * 16);
        CP_COMMIT();
    }

    for (int kc = 0; kc < 8; kc++) {
        CP_WAIT2();
        __syncthreads();
        const int st = kc & 3;

#pragma unroll
        for (int ks = 0; ks < 2; ks++) {
            uint2 a02 = *reinterpret_cast<const uint2*>(&sA[st][rw + g][ks * 8 + tig2]);
            uint2 a13 = *reinterpret_cast<const uint2*>(&sA[st][rw + g + 8][ks * 8 + tig2]);
#pragma unroll
            for (int nb = 0; nb < 4; nb++) {
                const int cn = cw + nb * 8 + g;
                uint2 bb = *reinterpret_cast<const uint2*>(&sB[st][cn][ks * 8 + tig2]);
                mma16816(c[nb], a02.x, a13.x, a02.y, a13.y, bb.x, bb.y);
            }
        }

        if (kc + 3 < 8) {
            const int s = kc + 3, sl = s & 3;
            CP_ASYNC16(dA0 + sl * STAGE_B, srcA + s * 16);
            CP_ASYNC16(dB0 + sl * STAGE_B, srcB + s * 16);
        }
        CP_COMMIT();   // always commit to keep wait-group arithmetic constant
    }

    // ---- V f16 epilogue (raw .view mapping, j-interleaved positions) ----
    const int b    = mBase >> 11;
    const int hloc = (mBase & 2047) >> 8;
    const int bh   = b * Hh + hloc;
    const int r255 = mBase & 255;
    const int cb   = (nBase >> 5) + wc;
    const int m0   = r255 + wr * 16 + g;

#pragma unroll
    for (int rq = 0; rq < 2; rq++) {
        const int jn = (m0 + rq * 8) * 8 + cb;
        const int ipj = ipos(jn & 127);
        __half* vt = &g_Vh16[((size_t)(bh * 16 + (jn >> 7))) * 4096 + ipj];
#pragma unroll
        for (int nb = 0; nb < 4; nb++) {
            const int d0 = nb * 8 + tig * 2;
            vt[(size_t)d0 * 128]       = __float2half(c[nb][rq * 2]);
            vt[(size_t)(d0 + 1) * 128] = __float2half(c[nb][rq * 2 + 1]);
        }
    }
}

// ---------------------------------------------------------------------------
// K2: fused scores (h2, MUFU-free) + HMMA PV + ones-MMA l + ELU.
// grid (32, 8, 4), 128 threads, double-buffered, 1 sync/tile.
// ---------------------------------------------------------------------------
__global__ __launch_bounds__(128) void attn_kernel(float* __restrict__ out) {
    __shared__ uint32_t sRowE[64];
    __shared__ __align__(8) uint32_t sF1[2][64];
    __shared__ __align__(8) uint32_t sF2[2][64];
    __shared__ uint4  sBits[2][64];
    __shared__ __align__(16) uint32_t sVt[2][32 * 72];

    const int tid  = threadIdx.x;
    const int w    = tid >> 5, lane = tid & 31;
    const int tig  = lane & 3, grp = lane >> 2;
    const int iT = blockIdx.x, hh = blockIdx.y, b = blockIdx.z;
    const int bh = b * Hh + hh;
    const int iBase = iT * 64;
    const int il0 = w * 16 + grp, il1 = il0 + 8;
    const int ipt = ipos(tid);

    const float wmax = fkeyinv(g_w2maxU[bh]);
    if (tid < 64) {
        float C = g_wh1s[bh * Nv + iBase + tid];
        float s = C + wmax;
        float M = fmaxf(s, SLOPE * s);
        sRowE[tid] = packh2(ex2f(s - M), ex2f(SLOPE * s - M));
    }

    const unsigned* bitsBase = g_adjbits + (size_t)(b * 2048 + iBase) * 64;
    const float* wh2Base = g_wh2s + (size_t)bh * 2048;
    const uint4* vBase = reinterpret_cast<const uint4*>(g_Vh16 + (size_t)bh * 16 * 4096);
    const int s0 = tig * 2, tig2 = tig * 2;
    int vi[4];
#pragma unroll
    for (int k = 0; k < 4; k++) {
        int q = tid + k * 128;
        vi[k] = (q >> 4) * 18 + (q & 15);
    }

    {
        uint4* dst = reinterpret_cast<uint4*>(sVt[0]);
#pragma unroll
        for (int k = 0; k < 4; k++) dst[vi[k]] = vBase[tid + k * 128];
        float w2 = wh2Base[tid] - wmax;
        reinterpret_cast<__half*>(sF1[0])[ipt] = __float2half(ex2f(w2));
        reinterpret_cast<__half*>(sF2[0])[ipt] = __float2half(ex2f(SLOPE * w2));
        if (tid < 64)
            sBits[0][tid] = *reinterpret_cast<const uint4*>(bitsBase + (size_t)tid * 64);
    }
    __syncthreads();

    const uint32_t e0 = sRowE[il0], e1 = sRowE[il1];
    const uint32_t E0lo = prmtu(e0, e0, 0x1010u), E0hi = prmtu(e0, e0, 0x3232u);
    const uint32_t E1lo = prmtu(e1, e1, 0x1010u), E1hi = prmtu(e1, e1, 0x3232u);

    float dacc[4][4];
#pragma unroll
    for (int nb = 0; nb < 4; nb++)
#pragma unroll
        for (int q = 0; q < 4; q++) dacc[nb][q] = 0.f;
    float lacc[4] = {0.f, 0.f, 0.f, 0.f};

    int buf = 0;
    for (int jt = 0; jt < 16; jt++) {
        const int nj = (jt + 1) & 15;
        uint4 va[4];
#pragma unroll
        for (int k = 0; k < 4; k++) va[k] = vBase[nj * 512 + tid + k * 128];
        float w2n = wh2Base[nj * 128 + tid] - wmax;
        uint4 bqn = make_uint4(0, 0, 0, 0);
        if (tid < 64)
            bqn = *reinterpret_cast<const uint4*>(bitsBase + (size_t)tid * 64 + nj * 4);

        const uint4 bq0 = sBits[buf][il0];
        const uint4 bq1 = sBits[buf][il1];
        const unsigned* bw0w = reinterpret_cast<const unsigned*>(&bq0);
        const unsigned* bw1w = reinterpret_cast<const unsigned*>(&bq1);
        const uint32_t* F1p = sF1[buf];
        const uint32_t* F2p = sF2[buf];
        const uint32_t* vtp = sVt[buf];

#pragma unroll
        for (int k2 = 0; k2 < 4; k2++) {
            const unsigned u0 = bw0w[k2] >> s0;
            const unsigned u1 = bw1w[k2] >> s0;
            const unsigned v07 = u0 << 7, v06 = u0 << 6;
            const unsigned v17 = u1 << 7, v16 = u1 << 6;
#pragma unroll
            for (int kh = 0; kh < 2; kh++) {
                const int wofs = (k2 * 2 + kh) * 8 + tig2;
                const uint2 f1 = *reinterpret_cast<const uint2*>(F1p + wofs);
                const uint2 f2 = *reinterpret_cast<const uint2*>(F2p + wofs);
                const uint32_t cA = kh ? 0xEEAAu : 0xCC88u;
                const uint32_t cB = kh ? 0xFFBBu : 0xDD99u;

                uint32_t A0 = hmax2u(hmul2u(E0lo, f1.x), hmul2u(E0hi, f2.x)) & prmtu(v07, v06, cA);
                uint32_t A2 = hmax2u(hmul2u(E0lo, f1.y), hmul2u(E0hi, f2.y)) & prmtu(v07, v06, cB);
                uint32_t A1 = hmax2u(hmul2u(E1lo, f1.x), hmul2u(E1hi, f2.x)) & prmtu(v17, v16, cA);
                uint32_t A3 = hmax2u(hmul2u(E1lo, f1.y), hmul2u(E1hi, f2.y)) & prmtu(v17, v16, cB);

#pragma unroll
                for (int nb = 0; nb < 4; nb++) {
                    int drow = nb * 8 + grp;
                    uint2 vv = *reinterpret_cast<const uint2*>(vtp + drow * 72 + wofs);
                    mma16816(dacc[nb], A0, A1, A2, A3, vv.x, vv.y);
                }
                mma16816(lacc, A0, A1, A2, A3, ONESH2, ONESH2);
            }
        }

        {
            uint4* dst = reinterpret_cast<uint4*>(sVt[buf ^ 1]);
#pragma unroll
            for (int k = 0; k < 4; k++) dst[vi[k]] = va[k];
            reinterpret_cast<__half*>(sF1[buf ^ 1])[ipt] = __float2half(ex2f(w2n));
            reinterpret_cast<__half*>(sF2[buf ^ 1])[ipt] = __float2half(ex2f(SLOPE * w2n));
            if (tid < 64) sBits[buf ^ 1][tid] = bqn;
        }
        __syncthreads();
        buf ^= 1;
    }

    const float rl0 = 1.f / lacc[0];
    const float rl1 = 1.f / lacc[2];

    const size_t o0 = ((size_t)bh * Nv + iBase + il0) * NHv + tig * 2;
    const size_t o1 = ((size_t)bh * Nv + iBase + il1) * NHv + tig * 2;
#pragma unroll
    for (int nb = 0; nb < 4; nb++) {
        float x0 = dacc[nb][0] * rl0, x1 = dacc[nb][1] * rl0;
        float y0 = dacc[nb][2] * rl1, y1 = dacc[nb][3] * rl1;
        x0 = (x0 > 0.f) ? x0 : expm1f(x0);
        x1 = (x1 > 0.f) ? x1 : expm1f(x1);
        y0 = (y0 > 0.f) ? y0 : expm1f(y0);
        y1 = (y1 > 0.f) ? y1 : expm1f(y1);
        *reinterpret_cast<float2*>(&out[o0 + nb * 8]) = make_float2(x0, x1);
        *reinterpret_cast<float2*>(&out[o1 + nb * 8]) = make_float2(y0, y1);
    }
}

// ---------------------------------------------------------------------------
extern "C" void kernel_launch(void* const* d_in, const int* in_sizes, int n_in,
                              void* d_out, int out_size) {
    const float* h   = (const float*)d_in[0];   // [4,2048,256]
    const int*   adj = (const int*)  d_in[1];   // [4,2048,2048]
    const float* W   = (const float*)d_in[2];   // [256,256]
    const float* a   = (const float*)d_in[3];   // [64,1]
    float* out = (float*)d_out;                 // [4,2048,256]

    static cudaStream_t s2 = nullptr, s3 = nullptr;
    static cudaEvent_t evFork = nullptr, evU = nullptr, evJ2 = nullptr, evJ3 = nullptr;
    if (s2 == nullptr) {
        cudaStreamCreateWithFlags(&s2, cudaStreamNonBlocking);
        cudaStreamCreateWithFlags(&s3, cudaStreamNonBlocking);
        cudaEventCreateWithFlags(&evFork, cudaEventDisableTiming);
        cudaEventCreateWithFlags(&evU, cudaEventDisableTiming);
        cudaEventCreateWithFlags(&evJ2, cudaEventDisableTiming);
        cudaEventCreateWithFlags(&evJ3, cudaEventDisableTiming);
    }

    // fork adjbits immediately (DRAM-bound, no dependencies)
    cudaEventRecord(evFork, 0);
    cudaStreamWaitEvent(s2, evFork, 0);
    adjbits_kernel<<<16384, 256, 0, s2>>>((const int4*)adj);
    cudaEventRecord(evJ2, s2);

    // u (+hconv) first: produces g_U, g_Wh16t, g_Ah16
    u_kernel<<<528, 256>>>((const float4*)W, a, (const float4*)h);
    cudaEventRecord(evU, 0);

    // wh12 (fma-bound) on s3, concurrent with gemm (tensor-bound) on main
    cudaStreamWaitEvent(s3, evU, 0);
    wh12_kernel<<<512, 256, 0, s3>>>((const float4*)h);
    cudaEventRecord(evJ3, s3);

    gemm_f16_kernel<<<dim3(128, 4), 256>>>();

    // join: attn needs all branches
    cudaStreamWaitEvent(0, evJ2, 0);
    cudaStreamWaitEvent(0, evJ3, 0);
    attn_kernel<<<dim3(32, 8, 4), 128>>>(out);
}

// round 16
// speedup vs baseline: 6.2962x; 1.0238x over previous
#include <cuda_runtime.h>
#include <cuda_fp16.h>
#include <cstdint>

// Problem constants
#define Bv     4
#define Nv     2048
#define INF_   256
#define OUTF_  256
#define Hh     8
#define NHv    32
#define SLOPE  0.2f
#define LOG2E  1.4426950408889634f

// ---------------------------------------------------------------------------
// Device scratch (no allocations; zero-initialized at load)
// ---------------------------------------------------------------------------
__device__ float    g_wh1s [Bv * Hh * Nv];              // wh1 * log2e   [bh][n]
__device__ float    g_wh2s [Bv * Hh * Nv];              // wh2 * log2e   [bh][n]
__device__ unsigned g_w2maxU[Bv * Hh];                  // ordered-uint max (atomicMax)
__device__ unsigned g_adjbits[Bv * Nv * (Nv / 32)];     // 2 MB adj bitmask
__device__ __align__(16) __half g_Vh16[32 * 2048 * 32]; // 4 MB V f16, plain [bh][j][d]
__device__ __align__(16) uint32_t g_Wh16t[OUTF_ * 128]; // W^T f16 h2, k-interleaved [n][128w]
__device__ __align__(16) uint32_t g_Ah16[Bv * Nv * 128];// 4 MB h f16 h2, k-interleaved [m][128w]
__device__ __align__(16) float    g_U[INF_ * 16];       // U = W @ a_blocks

#define ONESH2 0x3C003C00u

// ---------------------------------------------------------------------------
// helpers
// ---------------------------------------------------------------------------
__device__ __forceinline__ float ex2f(float x) {
    float y; asm("ex2.approx.ftz.f32 %0, %1;" : "=f"(y) : "f"(x)); return y;
}
__device__ __forceinline__ uint32_t packh2(float a, float b) {
    __half2 h = __floats2half2_rn(a, b);
    return *reinterpret_cast<uint32_t*>(&h);
}
__device__ __forceinline__ uint32_t hmul2u(uint32_t a, uint32_t b) {
    uint32_t d; asm("mul.f16x2 %0, %1, %2;" : "=r"(d) : "r"(a), "r"(b)); return d;
}
__device__ __forceinline__ uint32_t hmax2u(uint32_t a, uint32_t b) {
    uint32_t d; asm("max.f16x2 %0, %1, %2;" : "=r"(d) : "r"(a), "r"(b)); return d;
}
__device__ __forceinline__ uint32_t prmtu(uint32_t a, uint32_t b, uint32_t c) {
    uint32_t d; asm("prmt.b32 %0, %1, %2, %3;" : "=r"(d) : "r"(a), "r"(b), "r"(c)); return d;
}
__device__ __forceinline__ uint32_t fkey(float f) {
    uint32_t u = __float_as_uint(f);
    return u ^ (uint32_t)(((int)u >> 31) | 0x80000000);
}
__device__ __forceinline__ float fkeyinv(uint32_t k) {
    return __uint_as_float(k ^ (((int)k >> 31) ? 0x80000000u : 0xFFFFFFFFu));
}
// interleaved word index for k-pair p within a 128-word row (A/W frag layout)
__device__ __forceinline__ int wordpos(int p) {
    int q = p & 7;
    int slot = ((q & 3) << 1) | (q >> 2);
    return ((p >> 3) << 3) + slot;
}
__device__ __forceinline__ int ipos(int j) {     // half index (F1/F2 rows)
    return wordpos(j >> 1) * 2 + (j & 1);
}
__device__ __forceinline__ uint32_t smem_u32(const void* p) {
    uint32_t a;
    asm("{ .reg .u64 t; cvta.to.shared.u64 t, %1; cvt.u32.u64 %0, t; }" : "=r"(a) : "l"(p));
    return a;
}
#define CP_ASYNC16(dst, src) \
    asm volatile("cp.async.cg.shared.global [%0], [%1], 16;" :: "r"(dst), "l"(src))
#define CP_COMMIT() asm volatile("cp.async.commit_group;" ::: "memory")
#define CP_WAIT2()  asm volatile("cp.async.wait_group 2;" ::: "memory")
#define LDSM4T(r0, r1, r2, r3, addr) \
    asm volatile("ldmatrix.sync.aligned.m8n8.x4.trans.shared.b16 {%0,%1,%2,%3}, [%4];" \
                 : "=r"(r0), "=r"(r1), "=r"(r2), "=r"(r3) : "r"(addr))

__device__ __forceinline__ void mma16816(float* d, uint32_t a0, uint32_t a1, uint32_t a2,
                                         uint32_t a3, uint32_t b0, uint32_t b1) {
    asm volatile(
        "mma.sync.aligned.m16n8k16.row.col.f32.f16.f16.f32 "
        "{%0,%1,%2,%3}, {%4,%5,%6,%7}, {%8,%9}, {%0,%1,%2,%3};"
        : "+f"(d[0]), "+f"(d[1]), "+f"(d[2]), "+f"(d[3])
        : "r"(a0), "r"(a1), "r"(a2), "r"(a3), "r"(b0), "r"(b1));
}

// ---------------------------------------------------------------------------
// K_u: blocks 0-7: U[k][c] from W and a.
//      blocks 8-15: W -> W^T f16 h2-packed, k-interleaved (g_Wh16t).
//      blocks 16-527: h -> f16 h2-packed, k-interleaved (g_Ah16), 16 rows/blk.
// ---------------------------------------------------------------------------
__global__ __launch_bounds__(256) void u_kernel(const float4* __restrict__ W4,
                                                const float* __restrict__ a_vec,
                                                const float4* __restrict__ h4) {
    __shared__ float sW[32][260];
    __shared__ float sa[64];
    const int bb = blockIdx.x, t = threadIdx.x;

    if (bb >= 16) {   // ---- hconv: 16 rows of h per block ----
        const int rb = (bb - 16) * 16;
#pragma unroll
        for (int i = 0; i < 4; i++) {
            int idx = t + i * 256;
            int row = rb + (idx >> 6), k4 = idx & 63;
            float4 v = h4[(size_t)row * 64 + k4];
            int p0 = k4 * 2;
            g_Ah16[(size_t)row * 128 + wordpos(p0)]     = packh2(v.x, v.y);
            g_Ah16[(size_t)row * 128 + wordpos(p0 + 1)] = packh2(v.z, v.w);
        }
        return;
    }

    if (t < 64 && bb < 8) sa[t] = a_vec[t];
    const int k0 = (bb & 7) * 32;
#pragma unroll
    for (int i = 0; i < 8; i++) {
        int idx4 = t + i * 256;
        int row = idx4 >> 6, col = (idx4 & 63) * 4;
        float4 v = W4[(size_t)k0 * 64 + idx4];
        *reinterpret_cast<float4*>(&sW[row][col]) = v;
    }
    __syncthreads();

    if (bb < 8) {
        const int k_loc = t >> 3, c8 = t & 7;
        float u1 = 0.f, u2 = 0.f;
#pragma unroll
        for (int d = 0; d < 32; d++) {
            float wv = sW[k_loc][c8 * 32 + d];
            u1 += wv * sa[d];
            u2 += wv * sa[32 + d];
        }
        g_U[(k0 + k_loc) * 16 + c8]     = u1;
        g_U[(k0 + k_loc) * 16 + 8 + c8] = u2;
    } else {
        const int n = t;
#pragma unroll
        for (int kp = 0; kp < 16; kp++) {
            uint32_t w = packh2(sW[2 * kp][n], sW[2 * kp + 1][n]);
            g_Wh16t[n * 128 + (k0 >> 4) * 8 + wordpos(kp)] = w;
        }
    }
}

// ---------------------------------------------------------------------------
// K_wh12: exact fp32 wh1/wh2 = h @ U (raw-view mapping); per-head wh2 max.
// ---------------------------------------------------------------------------
__global__ __launch_bounds__(256) void wh12_kernel(const float4* __restrict__ h4) {
    __shared__ float sH[16][260];
    __shared__ float sU[256][16];
    __shared__ float sred[8];
    const int t = threadIdx.x;
    const int r0 = blockIdx.x * 16;
#pragma unroll
    for (int i = 0; i < 4; i++) {
        int idx4 = t + i * 256;
        int row = idx4 >> 6, col = (idx4 & 63) * 4;
        float4 v = h4[(size_t)r0 * 64 + idx4];
        *reinterpret_cast<float4*>(&sH[row][col]) = v;
    }
#pragma unroll
    for (int i = 0; i < 4; i++) {
        int idx4 = t + i * 256;
        *reinterpret_cast<float4*>(&sU[0][0] + idx4 * 4) =
            *reinterpret_cast<const float4*>(g_U + idx4 * 4);
    }
    __syncthreads();

    const int row = t >> 4, out = t & 15;
    const float4* hrow = reinterpret_cast<const float4*>(&sH[row][0]);
    float acc = 0.f;
#pragma unroll 8
    for (int k4 = 0; k4 < 64; k4++) {
        float4 hv = hrow[k4];
        acc += hv.x * sU[k4 * 4 + 0][out];
        acc += hv.y * sU[k4 * 4 + 1][out];
        acc += hv.z * sU[k4 * 4 + 2][out];
        acc += hv.w * sU[k4 * 4 + 3][out];
    }
    acc *= LOG2E;

    const int r = r0 + row;
    const int b = r >> 11, hloc = (r & 2047) >> 8, bh = b * Hh + hloc;
    const int np = (r & 255) * 8 + (out & 7);
    if (out < 8) g_wh1s[bh * Nv + np] = acc;
    else         g_wh2s[bh * Nv + np] = acc;

    float mx = (out >= 8) ? acc : -1e30f;
#pragma unroll
    for (int o = 16; o > 0; o >>= 1) mx = fmaxf(mx, __shfl_xor_sync(0xFFFFFFFFu, mx, o));
    if ((t & 31) == 0) sred[t >> 5] = mx;
    __syncthreads();
    if (t == 0) {
        float m = sred[0];
#pragma unroll
        for (int q = 1; q < 8; q++) m = fmaxf(m, sred[q]);
        atomicMax(&g_w2maxU[bh], fkey(m));
    }
}

// ---------------------------------------------------------------------------
// K_adj: adj -> bitmask, int4 loads, nibble pack + shfl-OR. grid 16384 x 256.
// ---------------------------------------------------------------------------
__global__ __launch_bounds__(256) void adjbits_kernel(const int4* __restrict__ adj4) {
    unsigned idx = blockIdx.x * 256u + threadIdx.x;
    int4 v = adj4[idx];
    unsigned nib = (unsigned)(v.x > 0) | ((unsigned)(v.y > 0) << 1)
                 | ((unsigned)(v.z > 0) << 2) | ((unsigned)(v.w > 0) << 3);
    unsigned word = nib << ((threadIdx.x & 7) * 4);
    word |= __shfl_xor_sync(0xFFFFFFFFu, word, 1);
    word |= __shfl_xor_sync(0xFFFFFFFFu, word, 2);
    word |= __shfl_xor_sync(0xFFFFFFFFu, word, 4);
    if ((threadIdx.x & 7) == 0) g_adjbits[idx >> 3] = word;
}

// ---------------------------------------------------------------------------
// K1: f16 HMMA GEMM, 4-stage cp.async pipeline (BK=32/stage, 8 stages).
// Emits V f16 in plain [bh][j][d] layout (coalesced half2 stores).
// ---------------------------------------------------------------------------
__global__ __launch_bounds__(256) void gemm_f16_kernel() {
    __shared__ uint32_t sA[4][64][20];
    __shared__ uint32_t sB[4][64][20];

    const int tid = threadIdx.x;
    const int w = tid >> 5, lane = tid & 31;
    const int g = lane >> 2, tig = lane & 3;
    const int wr = w & 3, wc = w >> 2;
    const int mBase = blockIdx.x * 64, nBase = blockIdx.y * 64;

    float c[4][4];
#pragma unroll
    for (int nb = 0; nb < 4; nb++)
#pragma unroll
        for (int q = 0; q < 4; q++) c[nb][q] = 0.f;

    const int rowC = tid >> 2, qw = (tid & 3) * 4;
    const uint32_t dA0 = smem_u32(&sA[0][rowC][qw]);
    const uint32_t dB0 = smem_u32(&sB[0][rowC][qw]);
    const uint32_t* srcA = g_Ah16 + (size_t)(mBase + rowC) * 128 + qw;
    const uint32_t* srcB = g_Wh16t + (size_t)(nBase + rowC) * 128 + qw;
    const int STAGE_B = 64 * 20 * 4;

    const int rw = wr * 16, cw = wc * 32;
    const int tig2 = tig * 2;

#pragma unroll
    for (int s = 0; s < 3; s++) {
        CP_ASYNC16(dA0 + s * STAGE_B, srcA + s * 16);
        CP_ASYNC16(dB0 + s * STAGE_B, srcB + s * 16);
        CP_COMMIT();
    }

    for (int kc = 0; kc < 8; kc++) {
        CP_WAIT2();
        __syncthreads();
        const int st = kc & 3;

#pragma unroll
        for (int ks = 0; ks < 2; ks++) {
            uint2 a02 = *reinterpret_cast<const uint2*>(&sA[st][rw + g][ks * 8 + tig2]);
            uint2 a13 = *reinterpret_cast<const uint2*>(&sA[st][rw + g + 8][ks * 8 + tig2]);
#pragma unroll
            for (int nb = 0; nb < 4; nb++) {
                const int cn = cw + nb * 8 + g;
                uint2 bb = *reinterpret_cast<const uint2*>(&sB[st][cn][ks * 8 + tig2]);
                mma16816(c[nb], a02.x, a13.x, a02.y, a13.y, bb.x, bb.y);
            }
        }

        if (kc + 3 < 8) {
            const int s = kc + 3, sl = s & 3;
            CP_ASYNC16(dA0 + sl * STAGE_B, srcA + s * 16);
            CP_ASYNC16(dB0 + sl * STAGE_B, srcB + s * 16);
        }
        CP_COMMIT();
    }

    // ---- V epilogue: plain [bh][j][d], coalesced half2 stores ----
    const int b    = mBase >> 11;
    const int hloc = (mBase & 2047) >> 8;
    const int bh   = b * Hh + hloc;
    const int r255 = mBase & 255;
    const int cb   = (nBase >> 5) + wc;
    const int m0   = r255 + wr * 16 + g;

#pragma unroll
    for (int rq = 0; rq < 2; rq++) {
        const int jn = (m0 + rq * 8) * 8 + cb;
        __half* vrow = g_Vh16 + ((size_t)bh * 2048 + jn) * 32 + tig2;
#pragma unroll
        for (int nb = 0; nb < 4; nb++) {
            *reinterpret_cast<__half2*>(vrow + nb * 8) =
                __floats2half2_rn(c[nb][rq * 2], c[nb][rq * 2 + 1]);
        }
    }
}

// ---------------------------------------------------------------------------
// K2: fused scores (h2, MUFU-free) + HMMA PV (B-frags via ldmatrix.trans)
// + ones-MMA l + ELU. grid (32, 8, 4), 128 threads, double-buffered.
// V smem: [j][d] rows padded to 80 B (20 words) -> conflict-free LDSM.
// ---------------------------------------------------------------------------
__global__ __launch_bounds__(128) void attn_kernel(float* __restrict__ out) {
    __shared__ uint32_t sRowE[64];
    __shared__ __align__(8) uint32_t sF1[2][64];
    __shared__ __align__(8) uint32_t sF2[2][64];
    __shared__ uint4  sBits[2][64];
    __shared__ __align__(16) uint32_t sVt[2][128 * 20];

    const int tid  = threadIdx.x;
    const int w    = tid >> 5, lane = tid & 31;
    const int tig  = lane & 3, grp = lane >> 2;
    const int iT = blockIdx.x, hh = blockIdx.y, b = blockIdx.z;
    const int bh = b * Hh + hh;
    const int iBase = iT * 64;
    const int il0 = w * 16 + grp, il1 = il0 + 8;
    const int ipt = ipos(tid);

    const float wmax = fkeyinv(g_w2maxU[bh]);
    if (tid < 64) {
        float C = g_wh1s[bh * Nv + iBase + tid];
        float s = C + wmax;
        float M = fmaxf(s, SLOPE * s);
        sRowE[tid] = packh2(ex2f(s - M), ex2f(SLOPE * s - M));
    }

    const unsigned* bitsBase = g_adjbits + (size_t)(b * 2048 + iBase) * 64;
    const float* wh2Base = g_wh2s + (size_t)bh * 2048;
    const uint4* vBase = reinterpret_cast<const uint4*>(g_Vh16 + (size_t)bh * 2048 * 32);
    const int s0 = tig * 2, tig2 = tig * 2;

    // ldmatrix per-lane offset (bytes): row = jb + (lane&7) + ((lane>>3)&1)*8,
    // col-block = (lane>>4)*16B
    const int laneRow = (lane & 7) + ((lane >> 3) & 1) * 8;
    const uint32_t laneOff = (uint32_t)(laneRow * 80 + (lane >> 4) * 16);
    const uint32_t vAddr[2] = { smem_u32(&sVt[0][0]) + laneOff,
                                smem_u32(&sVt[1][0]) + laneOff };

    {   // prefetch tile 0
        uint32_t* dst = sVt[0];
#pragma unroll
        for (int k = 0; k < 4; k++) {
            int idx = tid + k * 128;
            reinterpret_cast<uint4*>(dst)[(idx >> 2) * 5 + (idx & 3)] = vBase[idx];
        }
        float w2 = wh2Base[tid] - wmax;
        reinterpret_cast<__half*>(sF1[0])[ipt] = __float2half(ex2f(w2));
        reinterpret_cast<__half*>(sF2[0])[ipt] = __float2half(ex2f(SLOPE * w2));
        if (tid < 64)
            sBits[0][tid] = *reinterpret_cast<const uint4*>(bitsBase + (size_t)tid * 64);
    }
    __syncthreads();

    const uint32_t e0 = sRowE[il0], e1 = sRowE[il1];
    const uint32_t E0lo = prmtu(e0, e0, 0x1010u), E0hi = prmtu(e0, e0, 0x3232u);
    const uint32_t E1lo = prmtu(e1, e1, 0x1010u), E1hi = prmtu(e1, e1, 0x3232u);

    float dacc[4][4];
#pragma unroll
    for (int nb = 0; nb < 4; nb++)
#pragma unroll
        for (int q = 0; q < 4; q++) dacc[nb][q] = 0.f;
    float lacc[4] = {0.f, 0.f, 0.f, 0.f};

    int buf = 0;
    for (int jt = 0; jt < 16; jt++) {
        const int nj = (jt + 1) & 15;
        uint4 va[4];
#pragma unroll
        for (int k = 0; k < 4; k++) va[k] = vBase[nj * 512 + tid + k * 128];
        float w2n = wh2Base[nj * 128 + tid] - wmax;
        uint4 bqn = make_uint4(0, 0, 0, 0);
        if (tid < 64)
            bqn = *reinterpret_cast<const uint4*>(bitsBase + (size_t)tid * 64 + nj * 4);

        const uint4 bq0 = sBits[buf][il0];
        const uint4 bq1 = sBits[buf][il1];
        const unsigned* bw0w = reinterpret_cast<const unsigned*>(&bq0);
        const unsigned* bw1w = reinterpret_cast<const unsigned*>(&bq1);
        const uint32_t* F1p = sF1[buf];
        const uint32_t* F2p = sF2[buf];
        const uint32_t vA = vAddr[buf];

#pragma unroll
        for (int k2 = 0; k2 < 4; k2++) {
            const unsigned u0 = bw0w[k2] >> s0;
            const unsigned u1 = bw1w[k2] >> s0;
            const unsigned v07 = u0 << 7, v06 = u0 << 6;
            const unsigned v17 = u1 << 7, v16 = u1 << 6;
#pragma unroll
            for (int kh = 0; kh < 2; kh++) {
                const int ks = k2 * 2 + kh;
                const int wofs = ks * 8 + tig2;
                const uint2 f1 = *reinterpret_cast<const uint2*>(F1p + wofs);
                const uint2 f2 = *reinterpret_cast<const uint2*>(F2p + wofs);
                const uint32_t cA = kh ? 0xEEAAu : 0xCC88u;
                const uint32_t cB = kh ? 0xFFBBu : 0xDD99u;

                uint32_t A0 = hmax2u(hmul2u(E0lo, f1.x), hmul2u(E0hi, f2.x)) & prmtu(v07, v06, cA);
                uint32_t A2 = hmax2u(hmul2u(E0lo, f1.y), hmul2u(E0hi, f2.y)) & prmtu(v07, v06, cB);
                uint32_t A1 = hmax2u(hmul2u(E1lo, f1.x), hmul2u(E1hi, f2.x)) & prmtu(v17, v16, cA);
                uint32_t A3 = hmax2u(hmul2u(E1lo, f1.y), hmul2u(E1hi, f2.y)) & prmtu(v17, v16, cB);

                const uint32_t rowAddr = vA + (uint32_t)(ks * 16 * 80);
                uint32_t b0, b1, b2, b3;
                LDSM4T(b0, b1, b2, b3, rowAddr);
                mma16816(dacc[0], A0, A1, A2, A3, b0, b1);
                mma16816(dacc[1], A0, A1, A2, A3, b2, b3);
                LDSM4T(b0, b1, b2, b3, rowAddr + 32);
                mma16816(dacc[2], A0, A1, A2, A3, b0, b1);
                mma16816(dacc[3], A0, A1, A2, A3, b2, b3);
                mma16816(lacc, A0, A1, A2, A3, ONESH2, ONESH2);
            }
        }

        {   // stage next tile
            uint32_t* dst = sVt[buf ^ 1];
#pragma unroll
            for (int k = 0; k < 4; k++) {
                int idx = tid + k * 128;
                reinterpret_cast<uint4*>(dst)[(idx >> 2) * 5 + (idx & 3)] = va[k];
            }
            reinterpret_cast<__half*>(sF1[buf ^ 1])[ipt] = __float2half(ex2f(w2n));
            reinterpret_cast<__half*>(sF2[buf ^ 1])[ipt] = __float2half(ex2f(SLOPE * w2n));
            if (tid < 64) sBits[buf ^ 1][tid] = bqn;
        }
        __syncthreads();
        buf ^= 1;
    }

    const float rl0 = 1.f / lacc[0];
    const float rl1 = 1.f / lacc[2];

    const size_t o0 = ((size_t)bh * Nv + iBase + il0) * NHv + tig * 2;
    const size_t o1 = ((size_t)bh * Nv + iBase + il1) * NHv + tig * 2;
#pragma unroll
    for (int nb = 0; nb < 4; nb++) {
        float x0 = dacc[nb][0] * rl0, x1 = dacc[nb][1] * rl0;
        float y0 = dacc[nb][2] * rl1, y1 = dacc[nb][3] * rl1;
        x0 = (x0 > 0.f) ? x0 : expm1f(x0);
        x1 = (x1 > 0.f) ? x1 : expm1f(x1);
        y0 = (y0 > 0.f) ? y0 : expm1f(y0);
        y1 = (y1 > 0.f) ? y1 : expm1f(y1);
        *reinterpret_cast<float2*>(&out[o0 + nb * 8]) = make_float2(x0, x1);
        *reinterpret_cast<float2*>(&out[o1 + nb * 8]) = make_float2(y0, y1);
    }
}

// ---------------------------------------------------------------------------
extern "C" void kernel_launch(void* const* d_in, const int* in_sizes, int n_in,
                              void* d_out, int out_size) {
    const float* h   = (const float*)d_in[0];   // [4,2048,256]
    const int*   adj = (const int*)  d_in[1];   // [4,2048,2048]
    const float* W   = (const float*)d_in[2];   // [256,256]
    const float* a   = (const float*)d_in[3];   // [64,1]
    float* out = (float*)d_out;                 // [4,2048,256]

    static cudaStream_t s2 = nullptr, s3 = nullptr;
    static cudaEvent_t evFork = nullptr, evU = nullptr, evJ2 = nullptr, evJ3 = nullptr;
    if (s2 == nullptr) {
        cudaStreamCreateWithFlags(&s2, cudaStreamNonBlocking);
        cudaStreamCreateWithFlags(&s3, cudaStreamNonBlocking);
        cudaEventCreateWithFlags(&evFork, cudaEventDisableTiming);
        cudaEventCreateWithFlags(&evU, cudaEventDisableTiming);
        cudaEventCreateWithFlags(&evJ2, cudaEventDisableTiming);
        cudaEventCreateWithFlags(&evJ3, cudaEventDisableTiming);
    }

    // fork adjbits immediately (DRAM-bound, no dependencies)
    cudaEventRecord(evFork, 0);
    cudaStreamWaitEvent(s2, evFork, 0);
    adjbits_kernel<<<16384, 256, 0, s2>>>((const int4*)adj);
    cudaEventRecord(evJ2, s2);

    // u (+hconv) first: produces g_U, g_Wh16t, g_Ah16
    u_kernel<<<528, 256>>>((const float4*)W, a, (const float4*)h);
    cudaEventRecord(evU, 0);

    // wh12 (fma-bound) on s3, concurrent with gemm (tensor-bound) on main
    cudaStreamWaitEvent(s3, evU, 0);
    wh12_kernel<<<512, 256, 0, s3>>>((const float4*)h);
    cudaEventRecord(evJ3, s3);

    gemm_f16_kernel<<<dim3(128, 4), 256>>>();

    // join: attn needs all branches
    cudaStreamWaitEvent(0, evJ2, 0);
    cudaStreamWaitEvent(0, evJ3, 0);
    attn_kernel<<<dim3(32, 8, 4), 128>>>(out);
}